// round 11
// baseline (speedup 1.0000x reference)
#include <cuda_runtime.h>
#include <cuda_bf16.h>
#include <math.h>
#include <stdint.h>

// Problem constants
#define LAYERS 2
#define DMODEL 2048
#define NHEAD  16
#define HDIM   128
#define FFDIM  5632
#define RLORA  16
#define BATCH  4
#define SEQ    512
#define BB     8
#define MTOK   (BB*SEQ)
#define LORA_SCALE 1.4f
#define SCALE_QK 0.08838834764831845f

#define DD ((size_t)DMODEL * DMODEL)
#define DF ((size_t)DMODEL * FFDIM)
#define LSTR (4 * DD + 3 * DF)
#define WSL 21504   // per-layer scale rows: 4*2048 + 2*5632 + 2048

// ---------------- scratch ----------------
__device__ float g_h   [MTOK * DMODEL];
__device__ float g_x   [MTOK * DMODEL];
__device__ float g_q   [MTOK * DMODEL];
__device__ float g_k   [MTOK * DMODEL];
__device__ float g_v   [MTOK * DMODEL];
__device__ float g_o   [MTOK * DMODEL];
__device__ float g_sc  [BB * NHEAD * SEQ * SEQ];
__device__ float g_gate[MTOK * FFDIM];
__device__ float g_up  [MTOK * FFDIM];
__device__ float g_t   [3 * MTOK * RLORA];
__device__ float g_reps[BB * DMODEL];
// int8 digit buffers
__device__ int8_t g_aa1[MTOK * FFDIM];
__device__ int8_t g_aa2[MTOK * FFDIM];
__device__ float  g_asc[MTOK];
__device__ int8_t g_w1[2 * LSTR];
__device__ int8_t g_w2[2 * LSTR];
__device__ float  g_wsc[2 * WSL];
// attention bf16 split buffers
__device__ __nv_bfloat16 g_qh[MTOK * DMODEL];
__device__ __nv_bfloat16 g_ql[MTOK * DMODEL];
__device__ __nv_bfloat16 g_kh[MTOK * DMODEL];
__device__ __nv_bfloat16 g_kl[MTOK * DMODEL];
__device__ __nv_bfloat16 g_ph[BB * NHEAD * SEQ * SEQ];
__device__ __nv_bfloat16 g_pl[BB * NHEAD * SEQ * SEQ];
__device__ __nv_bfloat16 g_vth[MTOK * DMODEL];
__device__ __nv_bfloat16 g_vtl[MTOK * DMODEL];

// =================== helpers ===================
__device__ __forceinline__ uint32_t smem_u32(const void* p) {
    uint32_t a;
    asm("{ .reg .u64 t; cvta.to.shared.u64 t, %1; cvt.u32.u64 %0, t; }" : "=r"(a) : "l"(p));
    return a;
}
__device__ __forceinline__ void cp_async16(uint32_t saddr, const void* gptr) {
    asm volatile("cp.async.cg.shared.global [%0], [%1], 16;" :: "r"(saddr), "l"(gptr));
}
__device__ __forceinline__ void cp_commit() { asm volatile("cp.async.commit_group;"); }
template <int NWAIT>
__device__ __forceinline__ void cp_wait() {
    asm volatile("cp.async.wait_group %0;" :: "n"(NWAIT));
}
__device__ __forceinline__ void mma16(float* d, const uint32_t* a, uint32_t b0, uint32_t b1) {
    asm volatile(
        "mma.sync.aligned.m16n8k16.row.col.f32.bf16.bf16.f32 "
        "{%0,%1,%2,%3}, {%4,%5,%6,%7}, {%8,%9}, {%0,%1,%2,%3};"
        : "+f"(d[0]), "+f"(d[1]), "+f"(d[2]), "+f"(d[3])
        : "r"(a[0]), "r"(a[1]), "r"(a[2]), "r"(a[3]), "r"(b0), "r"(b1));
}
__device__ __forceinline__ void mma_i8(int* d, const uint32_t* a, uint32_t b0, uint32_t b1) {
    asm volatile(
        "mma.sync.aligned.m16n8k32.row.col.s32.s8.s8.s32 "
        "{%0,%1,%2,%3}, {%4,%5,%6,%7}, {%8,%9}, {%0,%1,%2,%3};"
        : "+r"(d[0]), "+r"(d[1]), "+r"(d[2]), "+r"(d[3])
        : "r"(a[0]), "r"(a[1]), "r"(a[2]), "r"(a[3]), "r"(b0), "r"(b1));
}
__device__ __forceinline__ void ldm_x4(uint32_t* r, uint32_t addr) {
    asm volatile("ldmatrix.sync.aligned.m8n8.x4.shared.b16 {%0,%1,%2,%3}, [%4];"
                 : "=r"(r[0]), "=r"(r[1]), "=r"(r[2]), "=r"(r[3]) : "r"(addr));
}
__device__ __forceinline__ void split_bf16(float v, __nv_bfloat16& h, __nv_bfloat16& l) {
    h = __float2bfloat16(v);
    l = __float2bfloat16(v - __bfloat162float(h));
}

// stage layout: 4 arrays of 128 rows, 48B row stride
#define ARRB16  6144
#define STGB16  24576
#define NSTAGE  4
#define LA_OFF  98304
#define LB_OFF  104448
#define GSMEM   110592
#define SCSM    98816
#define AVSM    98304

// ---- bf16 stage compute (attention kernels; unchanged) ----
#define COMPUTE16(stbase)                                                         \
    {                                                                             \
        uint32_t ahf[2][4], alf[2][4];                                            \
        int grp = lane >> 3, r8 = lane & 7;                                       \
        int mm = (grp & 1) * 8 + r8;                                              \
        int koff = (grp >> 1) * 8;                                                \
        _Pragma("unroll")                                                         \
        for (int mt = 0; mt < 2; mt++) {                                          \
            uint32_t ad = (stbase) + (wm * 32 + mt * 16 + mm) * 48 + koff * 2;    \
            ldm_x4(ahf[mt], ad);                                                  \
            ldm_x4(alf[mt], ad + ARRB16);                                         \
        }                                                                         \
        _Pragma("unroll")                                                         \
        for (int np = 0; np < 4; np++) {                                          \
            int nn = (grp >> 1) * 8 + r8;                                         \
            int koffb = (grp & 1) * 8;                                            \
            uint32_t bd = (stbase) + 2 * ARRB16 + (wn * 64 + np * 16 + nn) * 48 + koffb * 2; \
            uint32_t bh[4], bl[4];                                                \
            ldm_x4(bh, bd);                                                       \
            ldm_x4(bl, bd + ARRB16);                                              \
            mma16(d[0][np * 2],     ahf[0], bh[0], bh[1]);                        \
            mma16(d[0][np * 2 + 1], ahf[0], bh[2], bh[3]);                        \
            mma16(d[1][np * 2],     ahf[1], bh[0], bh[1]);                        \
            mma16(d[1][np * 2 + 1], ahf[1], bh[2], bh[3]);                        \
            mma16(d[0][np * 2],     ahf[0], bl[0], bl[1]);                        \
            mma16(d[0][np * 2 + 1], ahf[0], bl[2], bl[3]);                        \
            mma16(d[1][np * 2],     ahf[1], bl[0], bl[1]);                        \
            mma16(d[1][np * 2 + 1], ahf[1], bl[2], bl[3]);                        \
            mma16(d[0][np * 2],     alf[0], bh[0], bh[1]);                        \
            mma16(d[0][np * 2 + 1], alf[0], bh[2], bh[3]);                        \
            mma16(d[1][np * 2],     alf[1], bh[0], bh[1]);                        \
            mma16(d[1][np * 2 + 1], alf[1], bh[2], bh[3]);                        \
        }                                                                         \
    }

#define ISSUE16(kt, aH, aL, bH, bL, LDA, LDB)                                     \
    {                                                                             \
        const int k0_ = (kt) << 4;                                                \
        const int buf_ = (kt) & (NSTAGE - 1);                                     \
        _Pragma("unroll")                                                         \
        for (int j = 0; j < 4; j++) {                                             \
            int e = tid + j * 256;                                                \
            int arr = e >> 8;                                                     \
            int i = e & 255;                                                      \
            int row = i >> 1;                                                     \
            int cg = (i & 1) << 3;                                                \
            const __nv_bfloat16* gp;                                              \
            if (arr == 0)      gp = (aH) + (size_t)row * (LDA) + k0_ + cg;        \
            else if (arr == 1) gp = (aL) + (size_t)row * (LDA) + k0_ + cg;        \
            else if (arr == 2) gp = (bH) + (size_t)row * (LDB) + k0_ + cg;        \
            else               gp = (bL) + (size_t)row * (LDB) + k0_ + cg;        \
            cp_async16(sb + buf_ * STGB16 + arr * ARRB16 + row * 48 + cg * 2, gp);\
        }                                                                         \
        cp_commit();                                                              \
    }

#define MAINLOOP(nk, aH, aL, bH, bL, LDA, LDB)                                    \
    {                                                                             \
        ISSUE16(0, aH, aL, bH, bL, LDA, LDB);                                     \
        ISSUE16(1, aH, aL, bH, bL, LDA, LDB);                                     \
        ISSUE16(2, aH, aL, bH, bL, LDA, LDB);                                     \
        for (int kt = 0; kt < (nk); kt++) {                                       \
            cp_wait<2>();                                                         \
            __syncthreads();                                                      \
            const uint32_t st_ = sb + (kt & (NSTAGE - 1)) * STGB16;               \
            COMPUTE16(st_)                                                        \
            if (kt + 3 < (nk)) { ISSUE16(kt + 3, aH, aL, bH, bL, LDA, LDB); }     \
            else               { cp_commit(); }                                   \
        }                                                                         \
        cp_wait<0>();                                                             \
        __syncthreads();                                                          \
    }

// =================== INT8 GEMM: C = A@W + 1.4*T@lB (+= C) ===================
// A digits Aa1/Aa2 [M,K] int8 + sA[m]; W^T digits Bw1/Bw2 [N,K] int8 + sB[n].
// 512 threads, CTA 128x128, warptile 32x32, BK=32, 4-stage cp.async.
#define ISSUE_I8(kt)                                                              \
    {                                                                             \
        const int k0_ = (kt) << 5;                                                \
        const int buf_ = (kt) & 3;                                                \
        _Pragma("unroll")                                                         \
        for (int j = 0; j < 2; j++) {                                             \
            int e = tid + j * 512;                                                \
            int arr = e >> 8;                                                     \
            int i = e & 255;                                                      \
            int row = i >> 1;                                                     \
            int cb = (i & 1) << 4;                                                \
            const int8_t* gp;                                                     \
            if (arr == 0)      gp = pa1 + (size_t)row * K + k0_ + cb;             \
            else if (arr == 1) gp = pa2 + (size_t)row * K + k0_ + cb;             \
            else if (arr == 2) gp = pb1 + (size_t)row * K + k0_ + cb;             \
            else               gp = pb2 + (size_t)row * K + k0_ + cb;             \
            cp_async16(sb + buf_ * STGB16 + arr * ARRB16 + row * 48 + cb, gp);    \
        }                                                                         \
        cp_commit();                                                              \
    }

__global__ __launch_bounds__(512, 1)
void gemm_i8(const int8_t* __restrict__ Aa1, const int8_t* __restrict__ Aa2,
             const float* __restrict__ sA,
             const int8_t* __restrict__ Bw1, const int8_t* __restrict__ Bw2,
             const float* __restrict__ sB,
             float* __restrict__ C, int M, int N, int K,
             const float* __restrict__ lT, const float* __restrict__ lB, int accum)
{
    extern __shared__ char smc[];
    const int tid  = threadIdx.x;
    const int wid  = tid >> 5;
    const int lane = tid & 31;
    const int t4   = lane & 3;
    const int g    = lane >> 2;
    const int wm   = wid >> 2;    // 0..3
    const int wn   = wid & 3;     // 0..3
    const int bm   = blockIdx.y * 128;
    const int bn   = blockIdx.x * 128;
    const uint32_t sb = smem_u32(smc);

    __nv_bfloat16* la = (__nv_bfloat16*)(smc + LA_OFF);
    __nv_bfloat16* lb = (__nv_bfloat16*)(smc + LB_OFF);
    for (int i = tid; i < 2048; i += 512) {
        int row = i >> 4, r = i & 15;
        la[row * 24 + r] = __float2bfloat16(LORA_SCALE * lT[(size_t)(bm + row) * RLORA + r]);
        lb[row * 24 + r] = __float2bfloat16(lB[(size_t)r * N + bn + row]);
    }

    int hi[2][4][4], mid[2][4][4];
    #pragma unroll
    for (int mt = 0; mt < 2; mt++)
        #pragma unroll
        for (int nt = 0; nt < 4; nt++)
            #pragma unroll
            for (int j = 0; j < 4; j++) { hi[mt][nt][j] = 0; mid[mt][nt][j] = 0; }

    const int8_t* pa1 = Aa1 + (size_t)bm * K;
    const int8_t* pa2 = Aa2 + (size_t)bm * K;
    const int8_t* pb1 = Bw1 + (size_t)bn * K;
    const int8_t* pb2 = Bw2 + (size_t)bn * K;

    const int nk = K >> 5;
    ISSUE_I8(0); ISSUE_I8(1); ISSUE_I8(2);
    for (int kt = 0; kt < nk; kt++) {
        cp_wait<2>();
        __syncthreads();
        const uint32_t st = sb + (kt & 3) * STGB16;
        {
            uint32_t af[2][2][4];   // [digit][mt]
            #pragma unroll
            for (int mt = 0; mt < 2; mt++) {
                uint32_t ad = st + (wm * 32 + mt * 16 + (lane & 15)) * 48 + ((lane >> 4) << 4);
                ldm_x4(af[0][mt], ad);
                ldm_x4(af[1][mt], ad + ARRB16);
            }
            #pragma unroll
            for (int npair = 0; npair < 2; npair++) {
                uint32_t bd = st + 2 * ARRB16 + (wn * 32 + npair * 16 + (lane & 15)) * 48 + ((lane >> 4) << 4);
                uint32_t bh[4], bl[4];
                ldm_x4(bh, bd);
                ldm_x4(bl, bd + ARRB16);
                #pragma unroll
                for (int tt = 0; tt < 2; tt++) {
                    const int nt = npair * 2 + tt;
                    mma_i8(hi[0][nt],  af[0][0], bh[tt], bh[tt + 2]);
                    mma_i8(hi[1][nt],  af[0][1], bh[tt], bh[tt + 2]);
                    mma_i8(mid[0][nt], af[0][0], bl[tt], bl[tt + 2]);
                    mma_i8(mid[1][nt], af[0][1], bl[tt], bl[tt + 2]);
                    mma_i8(mid[0][nt], af[1][0], bh[tt], bh[tt + 2]);
                    mma_i8(mid[1][nt], af[1][1], bh[tt], bh[tt + 2]);
                }
            }
        }
        if (kt + 3 < nk) { ISSUE_I8(kt + 3); }
        else             { cp_commit(); }
    }
    cp_wait<0>();
    __syncthreads();

    // ---- dequant epilogue + LoRA tail + residual ----
    float d[2][4][4];
    #pragma unroll
    for (int mt = 0; mt < 2; mt++) {
        const int r0 = bm + wm * 32 + mt * 16 + g;
        float sa0 = sA[r0] * 128.f;
        float sa1 = sA[r0 + 8] * 128.f;
        #pragma unroll
        for (int nt = 0; nt < 4; nt++) {
            const int c0 = bn + wn * 32 + nt * 8 + 2 * t4;
            float s0 = sB[c0], s1 = sB[c0 + 1];
            d[mt][nt][0] = fmaf(128.f, (float)hi[mt][nt][0], (float)mid[mt][nt][0]) * sa0 * s0;
            d[mt][nt][1] = fmaf(128.f, (float)hi[mt][nt][1], (float)mid[mt][nt][1]) * sa0 * s1;
            d[mt][nt][2] = fmaf(128.f, (float)hi[mt][nt][2], (float)mid[mt][nt][2]) * sa1 * s0;
            d[mt][nt][3] = fmaf(128.f, (float)hi[mt][nt][3], (float)mid[mt][nt][3]) * sa1 * s1;
        }
    }

    {   // LoRA tail (bf16, K=16)
        uint32_t a[2][4];
        #pragma unroll
        for (int mt = 0; mt < 2; mt++) {
            const char* pa = (const char*)la + (wm * 32 + mt * 16 + g) * 48 + t4 * 4;
            a[mt][0] = *(const uint32_t*)(pa);
            a[mt][1] = *(const uint32_t*)(pa + 8 * 48);
            a[mt][2] = *(const uint32_t*)(pa + 16);
            a[mt][3] = *(const uint32_t*)(pa + 8 * 48 + 16);
        }
        #pragma unroll
        for (int nt = 0; nt < 4; nt++) {
            const char* pb = (const char*)lb + (wn * 32 + nt * 8 + g) * 48 + t4 * 4;
            uint32_t b0 = *(const uint32_t*)(pb);
            uint32_t b1 = *(const uint32_t*)(pb + 16);
            #pragma unroll
            for (int mt = 0; mt < 2; mt++) mma16(d[mt][nt], a[mt], b0, b1);
        }
    }

    #pragma unroll
    for (int mt = 0; mt < 2; mt++) {
        const int r0 = bm + wm * 32 + mt * 16 + g;
        #pragma unroll
        for (int nt = 0; nt < 4; nt++) {
            const int c0 = bn + wn * 32 + nt * 8 + 2 * t4;
            float2 v0 = make_float2(d[mt][nt][0], d[mt][nt][1]);
            float2 v1 = make_float2(d[mt][nt][2], d[mt][nt][3]);
            float* p0 = C + (size_t)r0 * N + c0;
            float* p1 = C + (size_t)(r0 + 8) * N + c0;
            if (accum) {
                float2 o0 = *(const float2*)p0;
                float2 o1 = *(const float2*)p1;
                v0.x += o0.x; v0.y += o0.y;
                v1.x += o1.x; v1.y += o1.y;
            }
            *(float2*)p0 = v0;
            *(float2*)p1 = v1;
        }
    }
}

// =================== scores (bf16x3, unchanged) ===================
__global__ __launch_bounds__(256, 2)
void scores_mma(const __nv_bfloat16* __restrict__ Qh, const __nv_bfloat16* __restrict__ Ql,
                const __nv_bfloat16* __restrict__ Kh, const __nv_bfloat16* __restrict__ Kl,
                const int* __restrict__ mT, const int* __restrict__ mM,
                float* __restrict__ S_)
{
    extern __shared__ char smc[];
    const int tid  = threadIdx.x;
    const int wid  = tid >> 5;
    const int lane = tid & 31;
    const int t4   = lane & 3;
    const int g    = lane >> 2;
    const int wm   = wid >> 1;
    const int wn   = wid & 1;
    const int z    = blockIdx.z;
    const int bb   = z >> 4;
    const int hh   = z & 15;
    const int bm   = blockIdx.y * 128;
    const int bn   = blockIdx.x * 128;
    const uint32_t sb = smem_u32(smc);
    int* msk = (int*)(smc + NSTAGE * STGB16);

    const int* mask = (bb < 4) ? (mT + bb * SEQ) : (mM + (bb - 4) * SEQ);
    if (tid < 128) msk[tid] = mask[bn + tid];

    float* Sbase = S_ + (size_t)z * SEQ * SEQ;

    if (bn > bm) {
        __syncthreads();
        for (int i = tid; i < 128 * 128; i += 256) {
            int r = i >> 7, c = i & 127;
            Sbase[(size_t)(bm + r) * SEQ + bn + c] = -1e9f;
        }
        return;
    }

    float d[2][8][4];
    #pragma unroll
    for (int mt = 0; mt < 2; mt++)
        #pragma unroll
        for (int nt = 0; nt < 8; nt++)
            #pragma unroll
            for (int j = 0; j < 4; j++) d[mt][nt][j] = 0.f;

    const __nv_bfloat16* aH = Qh + (size_t)(bb * SEQ + bm) * DMODEL + hh * HDIM;
    const __nv_bfloat16* aL = Ql + (size_t)(bb * SEQ + bm) * DMODEL + hh * HDIM;
    const __nv_bfloat16* bH = Kh + (size_t)(bb * SEQ + bn) * DMODEL + hh * HDIM;
    const __nv_bfloat16* bL = Kl + (size_t)(bb * SEQ + bn) * DMODEL + hh * HDIM;

    const int nk = HDIM >> 4;
    MAINLOOP(nk, aH, aL, bH, bL, DMODEL, DMODEL)

    #pragma unroll
    for (int mt = 0; mt < 2; mt++) {
        const int r0 = wm * 32 + mt * 16 + g;
        #pragma unroll
        for (int nt = 0; nt < 8; nt++) {
            const int c0 = wn * 64 + nt * 8 + 2 * t4;
            #pragma unroll
            for (int half = 0; half < 2; half++) {
                int r = r0 + half * 8;
                int sq = bm + r, sk0 = bn + c0;
                float va = d[mt][nt][half * 2], vb = d[mt][nt][half * 2 + 1];
                bool ok0 = (sk0 <= sq) && (msk[c0] > 0);
                bool ok1 = (sk0 + 1 <= sq) && (msk[c0 + 1] > 0);
                float2 out;
                out.x = va * SCALE_QK + (ok0 ? 0.f : -1e9f);
                out.y = vb * SCALE_QK + (ok1 ? 0.f : -1e9f);
                *(float2*)(Sbase + (size_t)sq * SEQ + sk0) = out;
            }
        }
    }
}

// =================== attnv (bf16x3, causal-truncated) ===================
__global__ __launch_bounds__(256, 2)
void attnv_mma(const __nv_bfloat16* __restrict__ Ph, const __nv_bfloat16* __restrict__ Pl,
               const __nv_bfloat16* __restrict__ Vth, const __nv_bfloat16* __restrict__ Vtl,
               float* __restrict__ O)
{
    extern __shared__ char smc[];
    const int tid  = threadIdx.x;
    const int wid  = tid >> 5;
    const int lane = tid & 31;
    const int t4   = lane & 3;
    const int g    = lane >> 2;
    const int wm   = wid >> 1;
    const int wn   = wid & 1;
    const int z    = blockIdx.z;
    const int bb   = z >> 4;
    const int hh   = z & 15;
    const int bm   = blockIdx.y * 128;
    const uint32_t sb = smem_u32(smc);

    float d[2][8][4];
    #pragma unroll
    for (int mt = 0; mt < 2; mt++)
        #pragma unroll
        for (int nt = 0; nt < 8; nt++)
            #pragma unroll
            for (int j = 0; j < 4; j++) d[mt][nt][j] = 0.f;

    const __nv_bfloat16* aH = Ph + ((size_t)z * SEQ + bm) * SEQ;
    const __nv_bfloat16* aL = Pl + ((size_t)z * SEQ + bm) * SEQ;
    const __nv_bfloat16* bH = Vth + (size_t)z * HDIM * SEQ;
    const __nv_bfloat16* bL = Vtl + (size_t)z * HDIM * SEQ;

    const int nk = (bm >> 4) + 8;
    MAINLOOP(nk, aH, aL, bH, bL, SEQ, SEQ)

    #pragma unroll
    for (int mt = 0; mt < 2; mt++) {
        const int r0 = bm + wm * 32 + mt * 16 + g;
        #pragma unroll
        for (int nt = 0; nt < 8; nt++) {
            const int c0 = wn * 64 + nt * 8 + 2 * t4;
            #pragma unroll
            for (int half = 0; half < 2; half++) {
                int r = r0 + half * 8;
                size_t oidx = (size_t)(bb * SEQ + r) * DMODEL + hh * HDIM + c0;
                *(float2*)(O + oidx) = make_float2(d[mt][nt][half * 2], d[mt][nt][half * 2 + 1]);
            }
        }
    }
}

// =================== fast LoRA-T ===================
#define LCH 512
template <int NM>
__global__ __launch_bounds__(256)
void lora_fast(const float* __restrict__ X, int K,
               const float* __restrict__ A0, const float* __restrict__ A1,
               const float* __restrict__ A2,
               float* __restrict__ T0, float* __restrict__ T1, float* __restrict__ T2)
{
    __shared__ float At[16 * 513];
    const int tid  = threadIdx.x;
    const int lane = tid & 31;
    const int warp = tid >> 5;
    const int row  = blockIdx.x * 8 + warp;

    const float* As[3] = {A0, A1, A2};
    float acc[NM][16];
    #pragma unroll
    for (int m = 0; m < NM; m++)
        #pragma unroll
        for (int r = 0; r < 16; r++) acc[m][r] = 0.f;

    for (int k0 = 0; k0 < K; k0 += LCH) {
        float xs[16];
        #pragma unroll
        for (int j = 0; j < 16; j++)
            xs[j] = X[(size_t)row * K + k0 + lane + 32 * j];
        #pragma unroll
        for (int m = 0; m < NM; m++) {
            __syncthreads();
            const float* Am = As[m];
            for (int i = tid; i < 16 * LCH; i += 256) {
                int k = i >> 4, r = i & 15;
                At[r * 513 + k] = Am[(size_t)(k0 + k) * RLORA + r];
            }
            __syncthreads();
            #pragma unroll
            for (int j = 0; j < 16; j++) {
                int k = lane + 32 * j;
                float xv = xs[j];
                #pragma unroll
                for (int r = 0; r < 16; r++)
                    acc[m][r] += xv * At[r * 513 + k];
            }
        }
    }

    float* Ts[3] = {T0, T1, T2};
    #pragma unroll
    for (int m = 0; m < NM; m++) {
        #pragma unroll
        for (int r = 0; r < 16; r++) {
            float v = acc[m][r];
            #pragma unroll
            for (int o = 16; o > 0; o >>= 1) v += __shfl_xor_sync(0xffffffffu, v, o);
            if (lane == 0) Ts[m][row * RLORA + r] = v;
        }
    }
}

// ---------------- weight column max (per output row of W^T) ----------------
__global__ void colmax_kernel(const float* __restrict__ W, int Kd, int Nd,
                              float* __restrict__ S)
{
    int col = blockIdx.x * 256 + threadIdx.x;
    if (col >= Nd) return;
    float m = 0.f;
    for (int r = 0; r < Kd; r++) m = fmaxf(m, fabsf(W[(size_t)r * Nd + col]));
    S[col] = m * (1.f / 16256.f);
}

// ---------------- weight transpose + int8 dual-digit quantize ----------------
__global__ void transpose_quant(const float* __restrict__ W,
                                int8_t* __restrict__ W1, int8_t* __restrict__ W2,
                                const float* __restrict__ S, int Kd, int Nd)
{
    __shared__ float tile[32][33];
    int n0 = blockIdx.x * 32, k0 = blockIdx.y * 32;
    int x = threadIdx.x, y = threadIdx.y;
    #pragma unroll
    for (int dy = 0; dy < 32; dy += 8)
        tile[y + dy][x] = W[(size_t)(k0 + y + dy) * Nd + n0 + x];
    __syncthreads();
    #pragma unroll
    for (int dy = 0; dy < 32; dy += 8) {
        int n = n0 + y + dy;
        float s = S[n];
        float inv = (s > 0.f) ? (1.f / s) : 0.f;
        float v = tile[x][y + dy];
        int qi = __float2int_rn(v * inv);
        int q1 = (qi + 64) >> 7;
        int q2 = qi - (q1 << 7);
        size_t o = (size_t)n * Kd + k0 + x;
        W1[o] = (int8_t)q1;
        W2[o] = (int8_t)q2;
    }
}

// ---------------- activation row quantize ----------------
__global__ void aquant(const float* __restrict__ X, int K,
                       int8_t* __restrict__ A1, int8_t* __restrict__ A2,
                       float* __restrict__ S)
{
    __shared__ float red[256];
    int row = blockIdx.x;
    int tid = threadIdx.x;
    const float* x = X + (size_t)row * K;
    float m = 0.f;
    for (int k = tid; k < K; k += 256) m = fmaxf(m, fabsf(x[k]));
    red[tid] = m; __syncthreads();
    for (int o = 128; o > 0; o >>= 1) {
        if (tid < o) red[tid] = fmaxf(red[tid], red[tid + o]);
        __syncthreads();
    }
    float mx = red[0];
    float s = mx * (1.f / 16256.f);
    float inv = (mx > 0.f) ? (16256.f / mx) : 0.f;
    if (tid == 0) S[row] = s;
    size_t base = (size_t)row * K;
    for (int k = tid; k < K; k += 256) {
        int qi = __float2int_rn(x[k] * inv);
        int q1 = (qi + 64) >> 7;
        int q2 = qi - (q1 << 7);
        A1[base + k] = (int8_t)q1;
        A2[base + k] = (int8_t)q2;
    }
}

// ---------------- V transpose + split per head ----------------
__global__ void vsplit_t(const float* __restrict__ V,
                         __nv_bfloat16* __restrict__ Vth, __nv_bfloat16* __restrict__ Vtl)
{
    __shared__ float tile[32][33];
    int tok0 = blockIdx.x * 32, d0 = blockIdx.y * 32;
    int x = threadIdx.x, y = threadIdx.y;
    #pragma unroll
    for (int dy = 0; dy < 32; dy += 8)
        tile[y + dy][x] = V[(size_t)(tok0 + y + dy) * DMODEL + d0 + x];
    __syncthreads();
    int bb = tok0 >> 9, s0 = tok0 & 511;
    int hh = d0 >> 7, dd0 = d0 & 127;
    size_t zb = ((size_t)(bb * NHEAD + hh)) * HDIM * SEQ;
    #pragma unroll
    for (int dy = 0; dy < 32; dy += 8) {
        float v = tile[x][y + dy];
        size_t oidx = zb + (size_t)(dd0 + y + dy) * SEQ + s0 + x;
        __nv_bfloat16 h, l;
        split_bf16(v, h, l);
        Vth[oidx] = h; Vtl[oidx] = l;
    }
}

// ---------------- fused embed + rmsnorm(ln1 layer0) ----------------
__global__ void embed_rms(const int* __restrict__ idT, const int* __restrict__ idM,
                          const float* __restrict__ E, const float* __restrict__ W,
                          float* __restrict__ H, float* __restrict__ X)
{
    __shared__ float red[256];
    int t  = blockIdx.x;
    int bb = t >> 9;
    int s  = t & 511;
    int id = (bb < 4) ? idT[bb * SEQ + s] : idM[(bb - 4) * SEQ + s];
    const float* src = E + (size_t)id * DMODEL;
    int tid = threadIdx.x;
    float vals[8];
    float ss = 0.f;
    #pragma unroll
    for (int j = 0; j < 8; j++) {
        float v = src[tid + 256 * j];
        vals[j] = v;
        ss += v * v;
    }
    red[tid] = ss; __syncthreads();
    for (int o = 128; o > 0; o >>= 1) {
        if (tid < o) red[tid] += red[tid + o];
        __syncthreads();
    }
    float scale = rsqrtf(red[0] / (float)DMODEL + 1e-6f);
    size_t base = (size_t)t * DMODEL;
    #pragma unroll
    for (int j = 0; j < 8; j++) {
        int idx = tid + 256 * j;
        H[base + idx] = vals[j];
        X[base + idx] = vals[j] * scale * W[idx];
    }
}

// ---------------- rmsnorm ----------------
__global__ void rmsnorm_kernel(const float* __restrict__ H, const float* __restrict__ W,
                               float* __restrict__ X)
{
    __shared__ float red[256];
    int row = blockIdx.x;
    const float* h = H + (size_t)row * DMODEL;
    int tid = threadIdx.x;
    float vals[8];
    float s = 0.f;
    #pragma unroll
    for (int j = 0; j < 8; j++) {
        float v = h[tid + 256 * j];
        vals[j] = v;
        s += v * v;
    }
    red[tid] = s; __syncthreads();
    for (int o = 128; o > 0; o >>= 1) {
        if (tid < o) red[tid] += red[tid + o];
        __syncthreads();
    }
    float scale = rsqrtf(red[0] / (float)DMODEL + 1e-6f);
    size_t base = (size_t)row * DMODEL;
    #pragma unroll
    for (int j = 0; j < 8; j++) {
        int idx = tid + 256 * j;
        X[base + idx] = vals[j] * scale * W[idx];
    }
}

// ---------------- RoPE (emits bf16 splits for attention) ----------------
__global__ void rope_kernel(const float* __restrict__ Q, const float* __restrict__ Kt,
                            __nv_bfloat16* __restrict__ Qh, __nv_bfloat16* __restrict__ Ql,
                            __nv_bfloat16* __restrict__ Kh, __nv_bfloat16* __restrict__ Kl)
{
    int i = blockIdx.x * blockDim.x + threadIdx.x;
    if (i >= MTOK * NHEAD * 64) return;
    int d = i & 63;
    int h = (i >> 6) & 15;
    int t = i >> 10;
    int s = t & 511;
    float freq = expf(-(float)d * (logf(10000.f) / 64.f));
    float ang = (float)s * freq;
    float sn, cs;
    sincosf(ang, &sn, &cs);
    size_t b0 = (size_t)t * DMODEL + h * HDIM + d;
    __nv_bfloat16 hh, ll;
    float x1 = Q[b0], x2 = Q[b0 + 64];
    float r1 = x1 * cs - x2 * sn;
    float r2 = x1 * sn + x2 * cs;
    split_bf16(r1, hh, ll); Qh[b0] = hh;      Ql[b0] = ll;
    split_bf16(r2, hh, ll); Qh[b0 + 64] = hh; Ql[b0 + 64] = ll;
    x1 = Kt[b0]; x2 = Kt[b0 + 64];
    r1 = x1 * cs - x2 * sn;
    r2 = x1 * sn + x2 * cs;
    split_bf16(r1, hh, ll); Kh[b0] = hh;      Kl[b0] = ll;
    split_bf16(r2, hh, ll); Kh[b0 + 64] = hh; Kl[b0 + 64] = ll;
}

// ---------------- row softmax (emits bf16 split probs) ----------------
__global__ void softmax_kernel(const float* __restrict__ S_,
                               __nv_bfloat16* __restrict__ Ph, __nv_bfloat16* __restrict__ Pl)
{
    __shared__ float red[256];
    const float* p = S_ + (size_t)blockIdx.x * SEQ;
    int t = threadIdx.x;
    float v0 = p[t], v1 = p[t + 256];
    float m = fmaxf(v0, v1);
    red[t] = m; __syncthreads();
    for (int o = 128; o > 0; o >>= 1) {
        if (t < o) red[t] = fmaxf(red[t], red[t + o]);
        __syncthreads();
    }
    m = red[0]; __syncthreads();
    float e0 = expf(v0 - m), e1 = expf(v1 - m);
    red[t] = e0 + e1; __syncthreads();
    for (int o = 128; o > 0; o >>= 1) {
        if (t < o) red[t] += red[t + o];
        __syncthreads();
    }
    float inv = 1.f / red[0];
    size_t base = (size_t)blockIdx.x * SEQ;
    __nv_bfloat16 hh, ll;
    split_bf16(e0 * inv, hh, ll); Ph[base + t] = hh;       Pl[base + t] = ll;
    split_bf16(e1 * inv, hh, ll); Ph[base + t + 256] = hh; Pl[base + t + 256] = ll;
}

// ---------------- swiglu ----------------
__global__ void swiglu_kernel(float* __restrict__ G, const float* __restrict__ U)
{
    size_t i = (size_t)blockIdx.x * blockDim.x + threadIdx.x;
    if (i >= (size_t)MTOK * FFDIM) return;
    float g = G[i];
    float sig = 1.f / (1.f + expf(-g));
    G[i] = g * sig * U[i];
}

// ---------------- reps extraction + L2 normalize ----------------
__global__ void reps_kernel(const float* __restrict__ X, const int* __restrict__ mT,
                            const int* __restrict__ mM, float* __restrict__ R_)
{
    __shared__ int ired[256];
    __shared__ float fred[256];
    __shared__ int sidx;
    int bb = blockIdx.x;
    const int* mask = (bb < 4) ? mT : mM;
    int b = bb & 3;
    int t = threadIdx.x;
    int s = 0;
    for (int j = t; j < SEQ; j += 256) s += mask[b * SEQ + j];
    ired[t] = s; __syncthreads();
    for (int o = 128; o > 0; o >>= 1) {
        if (t < o) ired[t] += ired[t + o];
        __syncthreads();
    }
    if (t == 0) {
        int last = mask[0 * SEQ + 511] + mask[1 * SEQ + 511] +
                   mask[2 * SEQ + 511] + mask[3 * SEQ + 511];
        sidx = (last == BATCH) ? (SEQ - 1) : (ired[0] - 1);
    }
    __syncthreads();
    const float* row = X + (size_t)(bb * SEQ + sidx) * DMODEL;
    float ss = 0.f;
    for (int j = t; j < DMODEL; j += 256) { float v = row[j]; ss += v * v; }
    fred[t] = ss; __syncthreads();
    for (int o = 128; o > 0; o >>= 1) {
        if (t < o) fred[t] += fred[t + o];
        __syncthreads();
    }
    float inv = 1.f / sqrtf(fred[0]);
    for (int j = t; j < DMODEL; j += 256) R_[bb * DMODEL + j] = row[j] * inv;
}

// ---------------- contrastive loss ----------------
__global__ void loss_kernel(const float* __restrict__ R_, float* __restrict__ out)
{
    __shared__ float sims[16];
    int tid = threadIdx.x;
    int warp = tid >> 5, lane = tid & 31;
    for (int p = warp; p < 16; p += 8) {
        int i = p >> 2, j = p & 3;
        const float* a = R_ + i * DMODEL;
        const float* bR = R_ + (4 + j) * DMODEL;
        float d = 0.f;
        for (int k2 = lane; k2 < DMODEL; k2 += 32) d += a[k2] * bR[k2];
        #pragma unroll
        for (int o = 16; o > 0; o >>= 1) d += __shfl_xor_sync(0xffffffff, d, o);
        if (lane == 0) sims[p] = d * 20.f;
    }
    __syncthreads();
    if (tid == 0) {
        float loss = 0.f;
        for (int i = 0; i < 4; i++) {
            float m = -1e30f;
            for (int j = 0; j < 4; j++) m = fmaxf(m, sims[i * 4 + j]);
            float sum = 0.f;
            for (int j = 0; j < 4; j++) sum += expf(sims[i * 4 + j] - m);
            loss += (logf(sum) + m) - sims[i * 4 + i];
        }
        out[0] = loss * 0.25f;
    }
}

// ---------------- host driver ----------------
static void* symaddr_raw(const void* sym)
{
    void* p = nullptr;
    cudaGetSymbolAddress(&p, sym);
    return p;
}

extern "C" void kernel_launch(void* const* d_in, const int* in_sizes, int n_in,
                              void* d_out, int out_size)
{
    const int*   idT = (const int*)d_in[0];
    const int*   mT  = (const int*)d_in[1];
    const int*   idM = (const int*)d_in[2];
    const int*   mM  = (const int*)d_in[3];
    const float* emb = (const float*)d_in[4];
    const float* ln1 = (const float*)d_in[5];
    const float* ln2 = (const float*)d_in[6];
    const float* lnf = (const float*)d_in[7];
    const float* Wq = (const float*)d_in[8],  *Aq = (const float*)d_in[9],  *Bq = (const float*)d_in[10];
    const float* Wk = (const float*)d_in[11], *Ak = (const float*)d_in[12], *Bk = (const float*)d_in[13];
    const float* Wv = (const float*)d_in[14], *Av = (const float*)d_in[15], *Bv = (const float*)d_in[16];
    const float* Wo = (const float*)d_in[17], *Ao = (const float*)d_in[18], *Bo = (const float*)d_in[19];
    const float* Wg = (const float*)d_in[20], *Ag = (const float*)d_in[21], *Bg = (const float*)d_in[22];
    const float* Wu = (const float*)d_in[23], *Au = (const float*)d_in[24], *Bu = (const float*)d_in[25];
    const float* Wd = (const float*)d_in[26], *Ad = (const float*)d_in[27], *Bd = (const float*)d_in[28];

    float* h  = (float*)symaddr_raw(g_h);
    float* x  = (float*)symaddr_raw(g_x);
    float* q  = (float*)symaddr_raw(g_q);
    float* k  = (float*)symaddr_raw(g_k);
    float* v  = (float*)symaddr_raw(g_v);
    float* o  = (float*)symaddr_raw(g_o);
    float* sc = (float*)symaddr_raw(g_sc);
    float* gg = (float*)symaddr_raw(g_gate);
    float* uu = (float*)symaddr_raw(g_up);
    float* t0 = (float*)symaddr_raw(g_t);
    float* t1 = t0 + MTOK * RLORA;
    float* t2 = t0 + 2 * MTOK * RLORA;
    float* rp = (float*)symaddr_raw(g_reps);
    int8_t* aa1 = (int8_t*)symaddr_raw(g_aa1);
    int8_t* aa2 = (int8_t*)symaddr_raw(g_aa2);
    float*  asc = (float*)symaddr_raw(g_asc);
    int8_t* w1  = (int8_t*)symaddr_raw(g_w1);
    int8_t* w2  = (int8_t*)symaddr_raw(g_w2);
    float*  wsc = (float*)symaddr_raw(g_wsc);
    __nv_bfloat16* qh  = (__nv_bfloat16*)symaddr_raw(g_qh);
    __nv_bfloat16* ql  = (__nv_bfloat16*)symaddr_raw(g_ql);
    __nv_bfloat16* kh  = (__nv_bfloat16*)symaddr_raw(g_kh);
    __nv_bfloat16* kl  = (__nv_bfloat16*)symaddr_raw(g_kl);
    __nv_bfloat16* ph  = (__nv_bfloat16*)symaddr_raw(g_ph);
    __nv_bfloat16* pl  = (__nv_bfloat16*)symaddr_raw(g_pl);
    __nv_bfloat16* vth = (__nv_bfloat16*)symaddr_raw(g_vth);
    __nv_bfloat16* vtl = (__nv_bfloat16*)symaddr_raw(g_vtl);

    cudaFuncSetAttribute(gemm_i8,    cudaFuncAttributeMaxDynamicSharedMemorySize, GSMEM);
    cudaFuncSetAttribute(scores_mma, cudaFuncAttributeMaxDynamicSharedMemorySize, SCSM);
    cudaFuncSetAttribute(attnv_mma,  cudaFuncAttributeMaxDynamicSharedMemorySize, AVSM);

    const dim3 tB(32, 8);
    const dim3 gD(DMODEL / 128, MTOK / 128);
    const dim3 gF(FFDIM / 128, MTOK / 128);

    // per-layer weight tables
    const float* Ws[LAYERS][7];
    const float* As[LAYERS][7];
    const float* Bs[LAYERS][7];
    size_t doff[7] = {0, DD, 2 * DD, 3 * DD, 4 * DD, 4 * DD + DF, 4 * DD + 2 * DF};
    int    wN[7]   = {DMODEL, DMODEL, DMODEL, DMODEL, FFDIM, FFDIM, DMODEL};
    int    wK[7]   = {DMODEL, DMODEL, DMODEL, DMODEL, DMODEL, DMODEL, FFDIM};
    size_t soff[7] = {0, 2048, 4096, 6144, 8192, 13824, 19456};
    for (int l = 0; l < LAYERS; l++) {
        Ws[l][0] = Wq + l * DD; Ws[l][1] = Wk + l * DD; Ws[l][2] = Wv + l * DD;
        Ws[l][3] = Wo + l * DD; Ws[l][4] = Wg + l * DF; Ws[l][5] = Wu + l * DF;
        Ws[l][6] = Wd + l * DF;
        As[l][0] = Aq + (size_t)l * DMODEL * RLORA; As[l][1] = Ak + (size_t)l * DMODEL * RLORA;
        As[l][2] = Av + (size_t)l * DMODEL * RLORA; As[l][3] = Ao + (size_t)l * DMODEL * RLORA;
        As[l][4] = Ag + (size_t)l * DMODEL * RLORA; As[l][5] = Au + (size_t)l * DMODEL * RLORA;
        As[l][6] = Ad + (size_t)l * FFDIM * RLORA;
        Bs[l][0] = Bq + (size_t)l * RLORA * DMODEL; Bs[l][1] = Bk + (size_t)l * RLORA * DMODEL;
        Bs[l][2] = Bv + (size_t)l * RLORA * DMODEL; Bs[l][3] = Bo + (size_t)l * RLORA * DMODEL;
        Bs[l][4] = Bg + (size_t)l * RLORA * FFDIM;  Bs[l][5] = Bu + (size_t)l * RLORA * FFDIM;
        Bs[l][6] = Bd + (size_t)l * RLORA * DMODEL;
    }
    auto wprep = [&](int l, int m) {
        int N = wN[m], K = wK[m];
        float* s = wsc + (size_t)l * WSL + soff[m];
        colmax_kernel<<<(N + 255) / 256, 256>>>(Ws[l][m], K, N, s);
        transpose_quant<<<dim3(N / 32, K / 32), tB>>>(Ws[l][m],
            w1 + (size_t)l * LSTR + doff[m], w2 + (size_t)l * LSTR + doff[m], s, K, N);
    };
    auto wdig1 = [&](int l, int m) { return w1 + (size_t)l * LSTR + doff[m]; };
    auto wdig2 = [&](int l, int m) { return w2 + (size_t)l * LSTR + doff[m]; };
    auto wscal = [&](int l, int m) { return wsc + (size_t)l * WSL + soff[m]; };

    // ---- prologue ordered so an early ncu slot lands on gemm_i8 ----
    embed_rms<<<MTOK, 256>>>(idT, idM, emb, ln1, h, x);          // 0
    colmax_kernel<<<(DMODEL + 255) / 256, 256>>>(Wq, DMODEL, DMODEL, wscal(0, 0)); // 1
    transpose_quant<<<dim3(DMODEL / 32, DMODEL / 32), tB>>>(Wq, wdig1(0, 0), wdig2(0, 0), wscal(0, 0), DMODEL, DMODEL); // 2
    aquant<<<MTOK, 256>>>(x, DMODEL, aa1, aa2, asc);             // 3
    lora_fast<3><<<MTOK / 8, 256>>>(x, DMODEL, As[0][0], As[0][1], As[0][2], t0, t1, t2); // 4
    gemm_i8<<<gD, 512, GSMEM>>>(aa1, aa2, asc, wdig1(0, 0), wdig2(0, 0), wscal(0, 0),
                                q, MTOK, DMODEL, DMODEL, t0, Bs[0][0], 0);               // 5

    // remaining weight prep
    for (int m = 1; m < 7; m++) wprep(0, m);
    for (int m = 0; m < 7; m++) wprep(1, m);

    for (int l = 0; l < LAYERS; l++) {
        if (l > 0) {
            rmsnorm_kernel<<<MTOK, 256>>>(h, ln1 + l * DMODEL, x);
            aquant<<<MTOK, 256>>>(x, DMODEL, aa1, aa2, asc);
            lora_fast<3><<<MTOK / 8, 256>>>(x, DMODEL, As[l][0], As[l][1], As[l][2], t0, t1, t2);
            gemm_i8<<<gD, 512, GSMEM>>>(aa1, aa2, asc, wdig1(l, 0), wdig2(l, 0), wscal(l, 0),
                                        q, MTOK, DMODEL, DMODEL, t0, Bs[l][0], 0);
        }
        gemm_i8<<<gD, 512, GSMEM>>>(aa1, aa2, asc, wdig1(l, 1), wdig2(l, 1), wscal(l, 1),
                                    k, MTOK, DMODEL, DMODEL, t1, Bs[l][1], 0);
        gemm_i8<<<gD, 512, GSMEM>>>(aa1, aa2, asc, wdig1(l, 2), wdig2(l, 2), wscal(l, 2),
                                    v, MTOK, DMODEL, DMODEL, t2, Bs[l][2], 0);

        rope_kernel<<<(MTOK * NHEAD * 64 + 255) / 256, 256>>>(q, k, qh, ql, kh, kl);
        vsplit_t<<<dim3(MTOK / 32, DMODEL / 32), tB>>>(v, vth, vtl);

        scores_mma<<<dim3(4, 4, BB * NHEAD), 256, SCSM>>>(qh, ql, kh, kl, mT, mM, sc);
        softmax_kernel<<<BB * NHEAD * SEQ, 256>>>(sc, ph, pl);
        attnv_mma<<<dim3(1, 4, BB * NHEAD), 256, AVSM>>>(ph, pl, vth, vtl, o);

        aquant<<<MTOK, 256>>>(o, DMODEL, aa1, aa2, asc);
        lora_fast<1><<<MTOK / 8, 256>>>(o, DMODEL, As[l][3], nullptr, nullptr, t0, nullptr, nullptr);
        gemm_i8<<<gD, 512, GSMEM>>>(aa1, aa2, asc, wdig1(l, 3), wdig2(l, 3), wscal(l, 3),
                                    h, MTOK, DMODEL, DMODEL, t0, Bs[l][3], 1);

        rmsnorm_kernel<<<MTOK, 256>>>(h, ln2 + l * DMODEL, x);
        aquant<<<MTOK, 256>>>(x, DMODEL, aa1, aa2, asc);
        lora_fast<2><<<MTOK / 8, 256>>>(x, DMODEL, As[l][4], As[l][5], nullptr, t0, t1, nullptr);
        gemm_i8<<<gF, 512, GSMEM>>>(aa1, aa2, asc, wdig1(l, 4), wdig2(l, 4), wscal(l, 4),
                                    gg, MTOK, FFDIM, DMODEL, t0, Bs[l][4], 0);
        gemm_i8<<<gF, 512, GSMEM>>>(aa1, aa2, asc, wdig1(l, 5), wdig2(l, 5), wscal(l, 5),
                                    uu, MTOK, FFDIM, DMODEL, t1, Bs[l][5], 0);

        swiglu_kernel<<<(int)(((size_t)MTOK * FFDIM + 255) / 256), 256>>>(gg, uu);

        aquant<<<MTOK, 256>>>(gg, FFDIM, aa1, aa2, asc);
        lora_fast<1><<<MTOK / 8, 256>>>(gg, FFDIM, As[l][6], nullptr, nullptr, t0, nullptr, nullptr);
        gemm_i8<<<gD, 512, GSMEM>>>(aa1, aa2, asc, wdig1(l, 6), wdig2(l, 6), wscal(l, 6),
                                    h, MTOK, DMODEL, FFDIM, t0, Bs[l][6], 1);
    }

    rmsnorm_kernel<<<MTOK, 256>>>(h, lnf, x);
    reps_kernel<<<BB, 256>>>(x, mT, mM, rp);
    loss_kernel<<<1, 256>>>(rp, (float*)d_out);
}

// round 13
// speedup vs baseline: 2.5280x; 2.5280x over previous
#include <cuda_runtime.h>
#include <cuda_bf16.h>
#include <math.h>
#include <stdint.h>

// Problem constants
#define LAYERS 2
#define DMODEL 2048
#define NHEAD  16
#define HDIM   128
#define FFDIM  5632
#define RLORA  16
#define BATCH  4
#define SEQ    512
#define BB     8
#define MTOK   (BB*SEQ)
#define LORA_SCALE 1.4f
#define SCALE_QK 0.08838834764831845f

// ---------------- scratch ----------------
__device__ float g_h   [MTOK * DMODEL];
__device__ float g_x   [MTOK * DMODEL];
__device__ float g_q   [MTOK * DMODEL];
__device__ float g_k   [MTOK * DMODEL];
__device__ float g_v   [MTOK * DMODEL];
__device__ float g_o   [MTOK * DMODEL];
__device__ float g_sc  [BB * NHEAD * SEQ * SEQ];
__device__ float g_gate[MTOK * FFDIM];
__device__ float g_t   [3 * MTOK * RLORA];
__device__ float g_reps[BB * DMODEL];
__device__ __nv_bfloat16 g_ah[MTOK * FFDIM];
__device__ __nv_bfloat16 g_al[MTOK * FFDIM];
__device__ __nv_bfloat16 g_wh[2 * (4 * DMODEL * DMODEL + 3 * DMODEL * FFDIM)];
__device__ __nv_bfloat16 g_wl[2 * (4 * DMODEL * DMODEL + 3 * DMODEL * FFDIM)];
__device__ __nv_bfloat16 g_qh[MTOK * DMODEL];
__device__ __nv_bfloat16 g_ql[MTOK * DMODEL];
__device__ __nv_bfloat16 g_kh[MTOK * DMODEL];
__device__ __nv_bfloat16 g_kl[MTOK * DMODEL];
// ph/pl double as: attention probs (BB*NHEAD*SEQ*SEQ = 33.5M) AND swiglu split output (23M)
__device__ __nv_bfloat16 g_ph[BB * NHEAD * SEQ * SEQ];
__device__ __nv_bfloat16 g_pl[BB * NHEAD * SEQ * SEQ];
__device__ __nv_bfloat16 g_vth[MTOK * DMODEL];
__device__ __nv_bfloat16 g_vtl[MTOK * DMODEL];

// =================== helpers ===================
__device__ __forceinline__ uint32_t smem_u32(const void* p) {
    uint32_t a;
    asm("{ .reg .u64 t; cvta.to.shared.u64 t, %1; cvt.u32.u64 %0, t; }" : "=r"(a) : "l"(p));
    return a;
}
__device__ __forceinline__ void cp_async16(uint32_t saddr, const void* gptr) {
    asm volatile("cp.async.cg.shared.global [%0], [%1], 16;" :: "r"(saddr), "l"(gptr));
}
__device__ __forceinline__ void cp_commit() { asm volatile("cp.async.commit_group;"); }
template <int NWAIT>
__device__ __forceinline__ void cp_wait() {
    asm volatile("cp.async.wait_group %0;" :: "n"(NWAIT));
}
__device__ __forceinline__ void mma16(float* d, const uint32_t* a, uint32_t b0, uint32_t b1) {
    asm volatile(
        "mma.sync.aligned.m16n8k16.row.col.f32.bf16.bf16.f32 "
        "{%0,%1,%2,%3}, {%4,%5,%6,%7}, {%8,%9}, {%0,%1,%2,%3};"
        : "+f"(d[0]), "+f"(d[1]), "+f"(d[2]), "+f"(d[3])
        : "r"(a[0]), "r"(a[1]), "r"(a[2]), "r"(a[3]), "r"(b0), "r"(b1));
}
__device__ __forceinline__ void ldm_x4(uint32_t* r, uint32_t addr) {
    asm volatile("ldmatrix.sync.aligned.m8n8.x4.shared.b16 {%0,%1,%2,%3}, [%4];"
                 : "=r"(r[0]), "=r"(r[1]), "=r"(r[2]), "=r"(r[3]) : "r"(addr));
}
__device__ __forceinline__ void split_bf16(float v, __nv_bfloat16& h, __nv_bfloat16& l) {
    h = __float2bfloat16(v);
    l = __float2bfloat16(v - __bfloat162float(h));
}

// 4-stage pipeline, BK=16. Per-stage arrays: 128 rows x 16 bf16, 48B row stride.
#define SMSB16  48
#define ARRB16  6144
#define STGB16  24576
#define NSTAGE  4
#define LA_OFF  98304
#define LB_OFF  104448
#define GSMEM   110592
#define SCSM    98816
#define AVSM    98304

// ---- compute one 128x16 stage (bf16x3), accumulator-interleaved ----
#define COMPUTE16(stbase)                                                         \
    {                                                                             \
        uint32_t ahf[2][4], alf[2][4];                                            \
        int grp = lane >> 3, r8 = lane & 7;                                       \
        int mm = (grp & 1) * 8 + r8;                                              \
        int koff = (grp >> 1) * 8;                                                \
        _Pragma("unroll")                                                         \
        for (int mt = 0; mt < 2; mt++) {                                          \
            uint32_t ad = (stbase) + (wm * 32 + mt * 16 + mm) * SMSB16 + koff * 2;\
            ldm_x4(ahf[mt], ad);                                                  \
            ldm_x4(alf[mt], ad + ARRB16);                                         \
        }                                                                         \
        _Pragma("unroll")                                                         \
        for (int np = 0; np < 4; np++) {                                          \
            int nn = (grp >> 1) * 8 + r8;                                         \
            int koffb = (grp & 1) * 8;                                            \
            uint32_t bd = (stbase) + 2 * ARRB16 + (wn * 64 + np * 16 + nn) * SMSB16 + koffb * 2; \
            uint32_t bh[4], bl[4];                                                \
            ldm_x4(bh, bd);                                                       \
            ldm_x4(bl, bd + ARRB16);                                              \
            mma16(d[0][np * 2],     ahf[0], bh[0], bh[1]);                        \
            mma16(d[0][np * 2 + 1], ahf[0], bh[2], bh[3]);                        \
            mma16(d[1][np * 2],     ahf[1], bh[0], bh[1]);                        \
            mma16(d[1][np * 2 + 1], ahf[1], bh[2], bh[3]);                        \
            mma16(d[0][np * 2],     ahf[0], bl[0], bl[1]);                        \
            mma16(d[0][np * 2 + 1], ahf[0], bl[2], bl[3]);                        \
            mma16(d[1][np * 2],     ahf[1], bl[0], bl[1]);                        \
            mma16(d[1][np * 2 + 1], ahf[1], bl[2], bl[3]);                        \
            mma16(d[0][np * 2],     alf[0], bh[0], bh[1]);                        \
            mma16(d[0][np * 2 + 1], alf[0], bh[2], bh[3]);                        \
            mma16(d[1][np * 2],     alf[1], bh[0], bh[1]);                        \
            mma16(d[1][np * 2 + 1], alf[1], bh[2], bh[3]);                        \
        }                                                                         \
    }

#define ISSUE16(kt, aH, aL, bH, bL, LDA, LDB)                                     \
    {                                                                             \
        const int k0_ = (kt) << 4;                                                \
        const int buf_ = (kt) & (NSTAGE - 1);                                     \
        _Pragma("unroll")                                                         \
        for (int j = 0; j < 4; j++) {                                             \
            int e = tid + j * 256;                                                \
            int arr = e >> 8;                                                     \
            int i = e & 255;                                                      \
            int row = i >> 1;                                                     \
            int cg = (i & 1) << 3;                                                \
            const __nv_bfloat16* gp;                                              \
            if (arr == 0)      gp = (aH) + (size_t)row * (LDA) + k0_ + cg;        \
            else if (arr == 1) gp = (aL) + (size_t)row * (LDA) + k0_ + cg;        \
            else if (arr == 2) gp = (bH) + (size_t)row * (LDB) + k0_ + cg;        \
            else               gp = (bL) + (size_t)row * (LDB) + k0_ + cg;        \
            cp_async16(sb + buf_ * STGB16 + arr * ARRB16 + row * SMSB16 + cg * 2, gp); \
        }                                                                         \
        cp_commit();                                                              \
    }

#define MAINLOOP(nk, aH, aL, bH, bL, LDA, LDB)                                    \
    {                                                                             \
        ISSUE16(0, aH, aL, bH, bL, LDA, LDB);                                     \
        ISSUE16(1, aH, aL, bH, bL, LDA, LDB);                                     \
        ISSUE16(2, aH, aL, bH, bL, LDA, LDB);                                     \
        for (int kt = 0; kt < (nk); kt++) {                                       \
            cp_wait<2>();                                                         \
            __syncthreads();                                                      \
            const uint32_t st_ = sb + (kt & (NSTAGE - 1)) * STGB16;               \
            COMPUTE16(st_)                                                        \
            if (kt + 3 < (nk)) { ISSUE16(kt + 3, aH, aL, bH, bL, LDA, LDB); }     \
            else               { cp_commit(); }                                   \
        }                                                                         \
        cp_wait<0>();                                                             \
        __syncthreads();                                                          \
    }

// =================== main GEMM with fused LoRA + residual / swiglu ===================
// mode 0: C = result.  mode 1: C += result (residual).
// mode 2: v = silu(G[idx]) * result; C = v; Oh/Ol = split(v).  (Oh/Ol must NOT alias A operands)
__global__ __launch_bounds__(256, 2)
void gemm_tc(const __nv_bfloat16* __restrict__ Agh, const __nv_bfloat16* __restrict__ Agl,
             const __nv_bfloat16* __restrict__ Wgh, const __nv_bfloat16* __restrict__ Wgl,
             float* __restrict__ C, int M, int N, int K,
             const float* __restrict__ lT, const float* __restrict__ lB, int mode,
             const float* __restrict__ G,
             __nv_bfloat16* __restrict__ Oh, __nv_bfloat16* __restrict__ Ol)
{
    extern __shared__ char smc[];
    const int tid  = threadIdx.x;
    const int wid  = tid >> 5;
    const int lane = tid & 31;
    const int t4   = lane & 3;
    const int g    = lane >> 2;
    const int wm   = wid >> 1;
    const int wn   = wid & 1;
    const int bm   = blockIdx.y * 128;
    const int bn   = blockIdx.x * 128;
    const uint32_t sb = smem_u32(smc);

    __nv_bfloat16* la = (__nv_bfloat16*)(smc + LA_OFF);
    __nv_bfloat16* lb = (__nv_bfloat16*)(smc + LB_OFF);
    for (int i = tid; i < 2048; i += 256) {
        int row = i >> 4, r = i & 15;
        la[row * 24 + r] = __float2bfloat16(LORA_SCALE * lT[(size_t)(bm + row) * RLORA + r]);
        lb[row * 24 + r] = __float2bfloat16(lB[(size_t)r * N + bn + row]);
    }

    float d[2][8][4];
    #pragma unroll
    for (int mt = 0; mt < 2; mt++)
        #pragma unroll
        for (int nt = 0; nt < 8; nt++)
            #pragma unroll
            for (int j = 0; j < 4; j++) d[mt][nt][j] = 0.f;

    const __nv_bfloat16* aH = Agh + (size_t)bm * K;
    const __nv_bfloat16* aL = Agl + (size_t)bm * K;
    const __nv_bfloat16* bH = Wgh + (size_t)bn * K;
    const __nv_bfloat16* bL = Wgl + (size_t)bn * K;

    const int nk = K >> 4;
    MAINLOOP(nk, aH, aL, bH, bL, K, K)

    // LoRA tail (hi-only, K=16)
    {
        uint32_t a[2][4];
        #pragma unroll
        for (int mt = 0; mt < 2; mt++) {
            const char* pa = (const char*)la + (wm * 32 + mt * 16 + g) * 48 + t4 * 4;
            a[mt][0] = *(const uint32_t*)(pa);
            a[mt][1] = *(const uint32_t*)(pa + 8 * 48);
            a[mt][2] = *(const uint32_t*)(pa + 16);
            a[mt][3] = *(const uint32_t*)(pa + 8 * 48 + 16);
        }
        #pragma unroll
        for (int nt = 0; nt < 8; nt++) {
            const char* pb = (const char*)lb + (wn * 64 + nt * 8 + g) * 48 + t4 * 4;
            uint32_t b0 = *(const uint32_t*)(pb);
            uint32_t b1 = *(const uint32_t*)(pb + 16);
            #pragma unroll
            for (int mt = 0; mt < 2; mt++) mma16(d[mt][nt], a[mt], b0, b1);
        }
    }

    #pragma unroll
    for (int mt = 0; mt < 2; mt++) {
        #pragma unroll
        for (int half = 0; half < 2; half++) {
            const int r0 = bm + wm * 32 + mt * 16 + half * 8 + g;
            #pragma unroll
            for (int nt = 0; nt < 8; nt++) {
                const int c0 = bn + wn * 64 + nt * 8 + 2 * t4;
                float va = d[mt][nt][half * 2];
                float vb = d[mt][nt][half * 2 + 1];
                size_t ofs = (size_t)r0 * N + c0;
                if (mode == 2) {
                    float g0 = G[ofs], g1 = G[ofs + 1];
                    float s0 = g0 / (1.f + expf(-g0));
                    float s1 = g1 / (1.f + expf(-g1));
                    va = s0 * va;
                    vb = s1 * vb;
                    __nv_bfloat16 h0, l0, h1, l1;
                    split_bf16(va, h0, l0);
                    split_bf16(vb, h1, l1);
                    Oh[ofs] = h0; Oh[ofs + 1] = h1;
                    Ol[ofs] = l0; Ol[ofs + 1] = l1;
                } else if (mode == 1) {
                    float2 old = *(const float2*)(C + ofs);
                    va += old.x; vb += old.y;
                }
                *(float2*)(C + ofs) = make_float2(va, vb);
            }
        }
    }
}

// =================== scores (skip masked tiles entirely) ===================
__global__ __launch_bounds__(256, 2)
void scores_mma(const __nv_bfloat16* __restrict__ Qh, const __nv_bfloat16* __restrict__ Ql,
                const __nv_bfloat16* __restrict__ Kh, const __nv_bfloat16* __restrict__ Kl,
                const int* __restrict__ mT, const int* __restrict__ mM,
                float* __restrict__ S_)
{
    extern __shared__ char smc[];
    const int tid  = threadIdx.x;
    const int wid  = tid >> 5;
    const int lane = tid & 31;
    const int t4   = lane & 3;
    const int g    = lane >> 2;
    const int wm   = wid >> 1;
    const int wn   = wid & 1;
    const int z    = blockIdx.z;
    const int bb   = z >> 4;
    const int hh   = z & 15;
    const int bm   = blockIdx.y * 128;
    const int bn   = blockIdx.x * 128;
    if (bn > bm) return;   // softmax never reads cols > row

    const uint32_t sb = smem_u32(smc);
    int* msk = (int*)(smc + NSTAGE * STGB16);

    const int* mask = (bb < 4) ? (mT + bb * SEQ) : (mM + (bb - 4) * SEQ);
    if (tid < 128) msk[tid] = mask[bn + tid];

    float* Sbase = S_ + (size_t)z * SEQ * SEQ;

    float d[2][8][4];
    #pragma unroll
    for (int mt = 0; mt < 2; mt++)
        #pragma unroll
        for (int nt = 0; nt < 8; nt++)
            #pragma unroll
            for (int j = 0; j < 4; j++) d[mt][nt][j] = 0.f;

    const __nv_bfloat16* aH = Qh + (size_t)(bb * SEQ + bm) * DMODEL + hh * HDIM;
    const __nv_bfloat16* aL = Ql + (size_t)(bb * SEQ + bm) * DMODEL + hh * HDIM;
    const __nv_bfloat16* bH = Kh + (size_t)(bb * SEQ + bn) * DMODEL + hh * HDIM;
    const __nv_bfloat16* bL = Kl + (size_t)(bb * SEQ + bn) * DMODEL + hh * HDIM;

    const int nk = HDIM >> 4;
    MAINLOOP(nk, aH, aL, bH, bL, DMODEL, DMODEL)

    #pragma unroll
    for (int mt = 0; mt < 2; mt++) {
        const int r0 = wm * 32 + mt * 16 + g;
        #pragma unroll
        for (int nt = 0; nt < 8; nt++) {
            const int c0 = wn * 64 + nt * 8 + 2 * t4;
            #pragma unroll
            for (int half = 0; half < 2; half++) {
                int r = r0 + half * 8;
                int sq = bm + r, sk0 = bn + c0;
                float va = d[mt][nt][half * 2], vb = d[mt][nt][half * 2 + 1];
                bool ok0 = (sk0 <= sq) && (msk[c0] > 0);
                bool ok1 = (sk0 + 1 <= sq) && (msk[c0 + 1] > 0);
                float2 out;
                out.x = va * SCALE_QK + (ok0 ? 0.f : -1e9f);
                out.y = vb * SCALE_QK + (ok1 ? 0.f : -1e9f);
                *(float2*)(Sbase + (size_t)sq * SEQ + sk0) = out;
            }
        }
    }
}

// =================== attnv (causal-truncated) ===================
__global__ __launch_bounds__(256, 2)
void attnv_mma(const __nv_bfloat16* __restrict__ Ph, const __nv_bfloat16* __restrict__ Pl,
               const __nv_bfloat16* __restrict__ Vth, const __nv_bfloat16* __restrict__ Vtl,
               float* __restrict__ O,
               __nv_bfloat16* __restrict__ Oh, __nv_bfloat16* __restrict__ Ol)
{
    extern __shared__ char smc[];
    const int tid  = threadIdx.x;
    const int wid  = tid >> 5;
    const int lane = tid & 31;
    const int t4   = lane & 3;
    const int g    = lane >> 2;
    const int wm   = wid >> 1;
    const int wn   = wid & 1;
    const int z    = blockIdx.z;
    const int bb   = z >> 4;
    const int hh   = z & 15;
    const int bm   = blockIdx.y * 128;
    const uint32_t sb = smem_u32(smc);

    float d[2][8][4];
    #pragma unroll
    for (int mt = 0; mt < 2; mt++)
        #pragma unroll
        for (int nt = 0; nt < 8; nt++)
            #pragma unroll
            for (int j = 0; j < 4; j++) d[mt][nt][j] = 0.f;

    const __nv_bfloat16* aH = Ph + ((size_t)z * SEQ + bm) * SEQ;
    const __nv_bfloat16* aL = Pl + ((size_t)z * SEQ + bm) * SEQ;
    const __nv_bfloat16* bH = Vth + (size_t)z * HDIM * SEQ;
    const __nv_bfloat16* bL = Vtl + (size_t)z * HDIM * SEQ;

    const int nk = (bm >> 4) + 8;
    MAINLOOP(nk, aH, aL, bH, bL, SEQ, SEQ)

    #pragma unroll
    for (int mt = 0; mt < 2; mt++) {
        const int r0 = bm + wm * 32 + mt * 16 + g;
        #pragma unroll
        for (int nt = 0; nt < 8; nt++) {
            const int c0 = wn * 64 + nt * 8 + 2 * t4;
            #pragma unroll
            for (int half = 0; half < 2; half++) {
                int r = r0 + half * 8;
                size_t oidx = (size_t)(bb * SEQ + r) * DMODEL + hh * HDIM + c0;
                float va = d[mt][nt][half * 2], vb = d[mt][nt][half * 2 + 1];
                *(float2*)(O + oidx) = make_float2(va, vb);
                __nv_bfloat16 h0, l0, h1, l1;
                split_bf16(va, h0, l0);
                split_bf16(vb, h1, l1);
                Oh[oidx] = h0; Oh[oidx + 1] = h1;
                Ol[oidx] = l0; Ol[oidx + 1] = l1;
            }
        }
    }
}

// =================== fast LoRA-T ===================
#define LCH 512
template <int NM>
__global__ __launch_bounds__(256)
void lora_fast(const float* __restrict__ X, int K,
               const float* __restrict__ A0, const float* __restrict__ A1,
               const float* __restrict__ A2,
               float* __restrict__ T0, float* __restrict__ T1, float* __restrict__ T2)
{
    __shared__ float At[16 * 513];
    const int tid  = threadIdx.x;
    const int lane = tid & 31;
    const int warp = tid >> 5;
    const int row  = blockIdx.x * 8 + warp;

    const float* As[3] = {A0, A1, A2};
    float acc[NM][16];
    #pragma unroll
    for (int m = 0; m < NM; m++)
        #pragma unroll
        for (int r = 0; r < 16; r++) acc[m][r] = 0.f;

    for (int k0 = 0; k0 < K; k0 += LCH) {
        float xs[16];
        #pragma unroll
        for (int j = 0; j < 16; j++)
            xs[j] = X[(size_t)row * K + k0 + lane + 32 * j];
        #pragma unroll
        for (int m = 0; m < NM; m++) {
            __syncthreads();
            const float* Am = As[m];
            for (int i = tid; i < 16 * LCH; i += 256) {
                int k = i >> 4, r = i & 15;
                At[r * 513 + k] = Am[(size_t)(k0 + k) * RLORA + r];
            }
            __syncthreads();
            #pragma unroll
            for (int j = 0; j < 16; j++) {
                int k = lane + 32 * j;
                float xv = xs[j];
                #pragma unroll
                for (int r = 0; r < 16; r++)
                    acc[m][r] += xv * At[r * 513 + k];
            }
        }
    }

    float* Ts[3] = {T0, T1, T2};
    #pragma unroll
    for (int m = 0; m < NM; m++) {
        #pragma unroll
        for (int r = 0; r < 16; r++) {
            float v = acc[m][r];
            #pragma unroll
            for (int o = 16; o > 0; o >>= 1) v += __shfl_xor_sync(0xffffffffu, v, o);
            if (lane == 0) Ts[m][row * RLORA + r] = v;
        }
    }
}

// ---------------- weight transpose + split ----------------
__global__ void transpose_split(const float* __restrict__ W,
                                __nv_bfloat16* __restrict__ Wh, __nv_bfloat16* __restrict__ Wl,
                                int Kd, int Nd)
{
    __shared__ float tile[32][33];
    int n0 = blockIdx.x * 32, k0 = blockIdx.y * 32;
    int x = threadIdx.x, y = threadIdx.y;
    #pragma unroll
    for (int dy = 0; dy < 32; dy += 8)
        tile[y + dy][x] = W[(size_t)(k0 + y + dy) * Nd + n0 + x];
    __syncthreads();
    #pragma unroll
    for (int dy = 0; dy < 32; dy += 8) {
        float v = tile[x][y + dy];
        size_t o = (size_t)(n0 + y + dy) * Kd + k0 + x;
        __nv_bfloat16 h, l;
        split_bf16(v, h, l);
        Wh[o] = h; Wl[o] = l;
    }
}

// ---------------- V transpose + split per head ----------------
__global__ void vsplit_t(const float* __restrict__ V,
                         __nv_bfloat16* __restrict__ Vth, __nv_bfloat16* __restrict__ Vtl)
{
    __shared__ float tile[32][33];
    int tok0 = blockIdx.x * 32, d0 = blockIdx.y * 32;
    int x = threadIdx.x, y = threadIdx.y;
    #pragma unroll
    for (int dy = 0; dy < 32; dy += 8)
        tile[y + dy][x] = V[(size_t)(tok0 + y + dy) * DMODEL + d0 + x];
    __syncthreads();
    int bb = tok0 >> 9, s0 = tok0 & 511;
    int hh = d0 >> 7, dd0 = d0 & 127;
    size_t zb = ((size_t)(bb * NHEAD + hh)) * HDIM * SEQ;
    #pragma unroll
    for (int dy = 0; dy < 32; dy += 8) {
        float v = tile[x][y + dy];
        size_t oidx = zb + (size_t)(dd0 + y + dy) * SEQ + s0 + x;
        __nv_bfloat16 h, l;
        split_bf16(v, h, l);
        Vth[oidx] = h; Vtl[oidx] = l;
    }
}

// ---------------- fused embed + rmsnorm(ln1 layer0) ----------------
__global__ void embed_rms(const int* __restrict__ idT, const int* __restrict__ idM,
                          const float* __restrict__ E, const float* __restrict__ W,
                          float* __restrict__ H, float* __restrict__ X,
                          __nv_bfloat16* __restrict__ Xh, __nv_bfloat16* __restrict__ Xl)
{
    __shared__ float red[256];
    int t  = blockIdx.x;
    int bb = t >> 9;
    int s  = t & 511;
    int id = (bb < 4) ? idT[bb * SEQ + s] : idM[(bb - 4) * SEQ + s];
    const float* src = E + (size_t)id * DMODEL;
    int tid = threadIdx.x;
    float vals[8];
    float ss = 0.f;
    #pragma unroll
    for (int j = 0; j < 8; j++) {
        float v = src[tid + 256 * j];
        vals[j] = v;
        ss += v * v;
    }
    red[tid] = ss; __syncthreads();
    for (int o = 128; o > 0; o >>= 1) {
        if (tid < o) red[tid] += red[tid + o];
        __syncthreads();
    }
    float scale = rsqrtf(red[0] / (float)DMODEL + 1e-6f);
    size_t base = (size_t)t * DMODEL;
    #pragma unroll
    for (int j = 0; j < 8; j++) {
        int idx = tid + 256 * j;
        float v = vals[j];
        H[base + idx] = v;
        float xv = v * scale * W[idx];
        X[base + idx] = xv;
        __nv_bfloat16 hh, ll;
        split_bf16(xv, hh, ll);
        Xh[base + idx] = hh; Xl[base + idx] = ll;
    }
}

// ---------------- rmsnorm ----------------
__global__ void rmsnorm_kernel(const float* __restrict__ H, const float* __restrict__ W,
                               float* __restrict__ X,
                               __nv_bfloat16* __restrict__ Xh, __nv_bfloat16* __restrict__ Xl)
{
    __shared__ float red[256];
    int row = blockIdx.x;
    const float* h = H + (size_t)row * DMODEL;
    int tid = threadIdx.x;
    float vals[8];
    float s = 0.f;
    #pragma unroll
    for (int j = 0; j < 8; j++) {
        float v = h[tid + 256 * j];
        vals[j] = v;
        s += v * v;
    }
    red[tid] = s; __syncthreads();
    for (int o = 128; o > 0; o >>= 1) {
        if (tid < o) red[tid] += red[tid + o];
        __syncthreads();
    }
    float scale = rsqrtf(red[0] / (float)DMODEL + 1e-6f);
    size_t base = (size_t)row * DMODEL;
    #pragma unroll
    for (int j = 0; j < 8; j++) {
        int idx = tid + 256 * j;
        float v = vals[j] * scale * W[idx];
        X[base + idx] = v;
        __nv_bfloat16 hh, ll;
        split_bf16(v, hh, ll);
        Xh[base + idx] = hh; Xl[base + idx] = ll;
    }
}

// ---------------- RoPE ----------------
__global__ void rope_kernel(const float* __restrict__ Q, const float* __restrict__ Kt,
                            __nv_bfloat16* __restrict__ Qh, __nv_bfloat16* __restrict__ Ql,
                            __nv_bfloat16* __restrict__ Kh, __nv_bfloat16* __restrict__ Kl)
{
    int i = blockIdx.x * blockDim.x + threadIdx.x;
    if (i >= MTOK * NHEAD * 64) return;
    int d = i & 63;
    int h = (i >> 6) & 15;
    int t = i >> 10;
    int s = t & 511;
    float freq = expf(-(float)d * (logf(10000.f) / 64.f));
    float ang = (float)s * freq;
    float sn, cs;
    sincosf(ang, &sn, &cs);
    size_t b0 = (size_t)t * DMODEL + h * HDIM + d;
    __nv_bfloat16 hh, ll;
    float x1 = Q[b0], x2 = Q[b0 + 64];
    float r1 = x1 * cs - x2 * sn;
    float r2 = x1 * sn + x2 * cs;
    split_bf16(r1, hh, ll); Qh[b0] = hh;      Ql[b0] = ll;
    split_bf16(r2, hh, ll); Qh[b0 + 64] = hh; Ql[b0 + 64] = ll;
    x1 = Kt[b0]; x2 = Kt[b0 + 64];
    r1 = x1 * cs - x2 * sn;
    r2 = x1 * sn + x2 * cs;
    split_bf16(r1, hh, ll); Kh[b0] = hh;      Kl[b0] = ll;
    split_bf16(r2, hh, ll); Kh[b0 + 64] = hh; Kl[b0 + 64] = ll;
}

// ---------------- causal-aware row softmax ----------------
__global__ void softmax_kernel(const float* __restrict__ S_,
                               __nv_bfloat16* __restrict__ Ph, __nv_bfloat16* __restrict__ Pl)
{
    __shared__ float red[256];
    const float* p = S_ + (size_t)blockIdx.x * SEQ;
    int sq = blockIdx.x & (SEQ - 1);
    int t = threadIdx.x;
    bool ok0 = (t <= sq);
    bool ok1 = (t + 256 <= sq);
    float v0 = ok0 ? p[t] : -1e30f;
    float v1 = ok1 ? p[t + 256] : -1e30f;
    float m = fmaxf(v0, v1);
    red[t] = m; __syncthreads();
    for (int o = 128; o > 0; o >>= 1) {
        if (t < o) red[t] = fmaxf(red[t], red[t + o]);
        __syncthreads();
    }
    m = red[0]; __syncthreads();
    float e0 = ok0 ? expf(v0 - m) : 0.f;
    float e1 = ok1 ? expf(v1 - m) : 0.f;
    red[t] = e0 + e1; __syncthreads();
    for (int o = 128; o > 0; o >>= 1) {
        if (t < o) red[t] += red[t + o];
        __syncthreads();
    }
    float inv = 1.f / red[0];
    size_t base = (size_t)blockIdx.x * SEQ;
    __nv_bfloat16 hh, ll;
    split_bf16(e0 * inv, hh, ll); Ph[base + t] = hh;       Pl[base + t] = ll;
    split_bf16(e1 * inv, hh, ll); Ph[base + t + 256] = hh; Pl[base + t + 256] = ll;
}

// ---------------- reps extraction + L2 normalize ----------------
__global__ void reps_kernel(const float* __restrict__ X, const int* __restrict__ mT,
                            const int* __restrict__ mM, float* __restrict__ R_)
{
    __shared__ int ired[256];
    __shared__ float fred[256];
    __shared__ int sidx;
    int bb = blockIdx.x;
    const int* mask = (bb < 4) ? mT : mM;
    int b = bb & 3;
    int t = threadIdx.x;
    int s = 0;
    for (int j = t; j < SEQ; j += 256) s += mask[b * SEQ + j];
    ired[t] = s; __syncthreads();
    for (int o = 128; o > 0; o >>= 1) {
        if (t < o) ired[t] += ired[t + o];
        __syncthreads();
    }
    if (t == 0) {
        int last = mask[0 * SEQ + 511] + mask[1 * SEQ + 511] +
                   mask[2 * SEQ + 511] + mask[3 * SEQ + 511];
        sidx = (last == BATCH) ? (SEQ - 1) : (ired[0] - 1);
    }
    __syncthreads();
    const float* row = X + (size_t)(bb * SEQ + sidx) * DMODEL;
    float ss = 0.f;
    for (int j = t; j < DMODEL; j += 256) { float v = row[j]; ss += v * v; }
    fred[t] = ss; __syncthreads();
    for (int o = 128; o > 0; o >>= 1) {
        if (t < o) fred[t] += fred[t + o];
        __syncthreads();
    }
    float inv = 1.f / sqrtf(fred[0]);
    for (int j = t; j < DMODEL; j += 256) R_[bb * DMODEL + j] = row[j] * inv;
}

// ---------------- contrastive loss ----------------
__global__ void loss_kernel(const float* __restrict__ R_, float* __restrict__ out)
{
    __shared__ float sims[16];
    int tid = threadIdx.x;
    int warp = tid >> 5, lane = tid & 31;
    for (int p = warp; p < 16; p += 8) {
        int i = p >> 2, j = p & 3;
        const float* a = R_ + i * DMODEL;
        const float* bR = R_ + (4 + j) * DMODEL;
        float d = 0.f;
        for (int k2 = lane; k2 < DMODEL; k2 += 32) d += a[k2] * bR[k2];
        #pragma unroll
        for (int o = 16; o > 0; o >>= 1) d += __shfl_xor_sync(0xffffffff, d, o);
        if (lane == 0) sims[p] = d * 20.f;
    }
    __syncthreads();
    if (tid == 0) {
        float loss = 0.f;
        for (int i = 0; i < 4; i++) {
            float m = -1e30f;
            for (int j = 0; j < 4; j++) m = fmaxf(m, sims[i * 4 + j]);
            float sum = 0.f;
            for (int j = 0; j < 4; j++) sum += expf(sims[i * 4 + j] - m);
            loss += (logf(sum) + m) - sims[i * 4 + i];
        }
        out[0] = loss * 0.25f;
    }
}

// ---------------- host driver ----------------
static void* symaddr_raw(const void* sym)
{
    void* p = nullptr;
    cudaGetSymbolAddress(&p, sym);
    return p;
}

extern "C" void kernel_launch(void* const* d_in, const int* in_sizes, int n_in,
                              void* d_out, int out_size)
{
    const int*   idT = (const int*)d_in[0];
    const int*   mT  = (const int*)d_in[1];
    const int*   idM = (const int*)d_in[2];
    const int*   mM  = (const int*)d_in[3];
    const float* emb = (const float*)d_in[4];
    const float* ln1 = (const float*)d_in[5];
    const float* ln2 = (const float*)d_in[6];
    const float* lnf = (const float*)d_in[7];
    const float* Wq = (const float*)d_in[8],  *Aq = (const float*)d_in[9],  *Bq = (const float*)d_in[10];
    const float* Wk = (const float*)d_in[11], *Ak = (const float*)d_in[12], *Bk = (const float*)d_in[13];
    const float* Wv = (const float*)d_in[14], *Av = (const float*)d_in[15], *Bv = (const float*)d_in[16];
    const float* Wo = (const float*)d_in[17], *Ao = (const float*)d_in[18], *Bo = (const float*)d_in[19];
    const float* Wg = (const float*)d_in[20], *Ag = (const float*)d_in[21], *Bg = (const float*)d_in[22];
    const float* Wu = (const float*)d_in[23], *Au = (const float*)d_in[24], *Bu = (const float*)d_in[25];
    const float* Wd = (const float*)d_in[26], *Ad = (const float*)d_in[27], *Bd = (const float*)d_in[28];

    float* h  = (float*)symaddr_raw(g_h);
    float* x  = (float*)symaddr_raw(g_x);
    float* q  = (float*)symaddr_raw(g_q);
    float* k  = (float*)symaddr_raw(g_k);
    float* v  = (float*)symaddr_raw(g_v);
    float* o  = (float*)symaddr_raw(g_o);
    float* sc = (float*)symaddr_raw(g_sc);
    float* gg = (float*)symaddr_raw(g_gate);
    float* t0 = (float*)symaddr_raw(g_t);
    float* t1 = t0 + MTOK * RLORA;
    float* t2 = t0 + 2 * MTOK * RLORA;
    float* rp = (float*)symaddr_raw(g_reps);
    __nv_bfloat16* ah  = (__nv_bfloat16*)symaddr_raw(g_ah);
    __nv_bfloat16* al  = (__nv_bfloat16*)symaddr_raw(g_al);
    __nv_bfloat16* wh  = (__nv_bfloat16*)symaddr_raw(g_wh);
    __nv_bfloat16* wl  = (__nv_bfloat16*)symaddr_raw(g_wl);
    __nv_bfloat16* qh  = (__nv_bfloat16*)symaddr_raw(g_qh);
    __nv_bfloat16* ql  = (__nv_bfloat16*)symaddr_raw(g_ql);
    __nv_bfloat16* kh  = (__nv_bfloat16*)symaddr_raw(g_kh);
    __nv_bfloat16* kl  = (__nv_bfloat16*)symaddr_raw(g_kl);
    __nv_bfloat16* ph  = (__nv_bfloat16*)symaddr_raw(g_ph);
    __nv_bfloat16* pl  = (__nv_bfloat16*)symaddr_raw(g_pl);
    __nv_bfloat16* vth = (__nv_bfloat16*)symaddr_raw(g_vth);
    __nv_bfloat16* vtl = (__nv_bfloat16*)symaddr_raw(g_vtl);

    cudaFuncSetAttribute(gemm_tc,    cudaFuncAttributeMaxDynamicSharedMemorySize, GSMEM);
    cudaFuncSetAttribute(scores_mma, cudaFuncAttributeMaxDynamicSharedMemorySize, SCSM);
    cudaFuncSetAttribute(attnv_mma,  cudaFuncAttributeMaxDynamicSharedMemorySize, AVSM);

    const size_t DD = (size_t)DMODEL * DMODEL;
    const size_t DF = (size_t)DMODEL * FFDIM;
    const size_t LSTR = 4 * DD + 3 * DF;
    const dim3 tD(DMODEL / 32, DMODEL / 32), tB(32, 8);
    const dim3 tF(FFDIM / 32, DMODEL / 32);
    const dim3 tFd(DMODEL / 32, FFDIM / 32);
    const dim3 gD(DMODEL / 128, MTOK / 128);
    const dim3 gF(FFDIM / 128, MTOK / 128);

    // ---- prologue ----
    transpose_split<<<tD, tB>>>(Wq, wh, wl, DMODEL, DMODEL);
    embed_rms<<<MTOK, 256>>>(idT, idM, emb, ln1, h, x, ah, al);
    lora_fast<3><<<MTOK / 8, 256>>>(x, DMODEL, Aq, Ak, Av, t0, t1, t2);
    gemm_tc<<<gD, 256, GSMEM>>>(ah, al, wh, wl, q, MTOK, DMODEL, DMODEL, t0, Bq, 0,
                                nullptr, nullptr, nullptr);
    transpose_split<<<tD, tB>>>(Wk, wh + DD, wl + DD, DMODEL, DMODEL);
    gemm_tc<<<gD, 256, GSMEM>>>(ah, al, wh + DD, wl + DD, k, MTOK, DMODEL, DMODEL, t1, Bk, 0,
                                nullptr, nullptr, nullptr);
    transpose_split<<<tD, tB>>>(Wv, wh + 2 * DD, wl + 2 * DD, DMODEL, DMODEL);
    gemm_tc<<<gD, 256, GSMEM>>>(ah, al, wh + 2 * DD, wl + 2 * DD, v, MTOK, DMODEL, DMODEL, t2, Bv, 0,
                                nullptr, nullptr, nullptr);

    // remaining transposes
    transpose_split<<<tD, tB>>>(Wo, wh + 3 * DD, wl + 3 * DD, DMODEL, DMODEL);
    transpose_split<<<tF, tB>>>(Wg, wh + 4 * DD, wl + 4 * DD, DMODEL, FFDIM);
    transpose_split<<<tF, tB>>>(Wu, wh + 4 * DD + DF, wl + 4 * DD + DF, DMODEL, FFDIM);
    transpose_split<<<tFd, tB>>>(Wd, wh + 4 * DD + 2 * DF, wl + 4 * DD + 2 * DF, FFDIM, DMODEL);
    for (int l = 1; l < LAYERS; l++) {
        size_t off = (size_t)l * LSTR;
        transpose_split<<<tD, tB>>>(Wq + l * DD, wh + off,          wl + off,          DMODEL, DMODEL);
        transpose_split<<<tD, tB>>>(Wk + l * DD, wh + off + DD,     wl + off + DD,     DMODEL, DMODEL);
        transpose_split<<<tD, tB>>>(Wv + l * DD, wh + off + 2 * DD, wl + off + 2 * DD, DMODEL, DMODEL);
        transpose_split<<<tD, tB>>>(Wo + l * DD, wh + off + 3 * DD, wl + off + 3 * DD, DMODEL, DMODEL);
        transpose_split<<<tF, tB>>>(Wg + l * DF, wh + off + 4 * DD, wl + off + 4 * DD, DMODEL, FFDIM);
        transpose_split<<<tF, tB>>>(Wu + l * DF, wh + off + 4 * DD + DF, wl + off + 4 * DD + DF, DMODEL, FFDIM);
        transpose_split<<<tFd, tB>>>(Wd + l * DF, wh + off + 4 * DD + 2 * DF, wl + off + 4 * DD + 2 * DF, FFDIM, DMODEL);
    }

    for (int l = 0; l < LAYERS; l++) {
        size_t off = (size_t)l * LSTR;
        const __nv_bfloat16 *Wq_h = wh + off,               *Wq_l = wl + off;
        const __nv_bfloat16 *Wk_h = wh + off + DD,          *Wk_l = wl + off + DD;
        const __nv_bfloat16 *Wv_h = wh + off + 2 * DD,      *Wv_l = wl + off + 2 * DD;
        const __nv_bfloat16 *Wo_h = wh + off + 3 * DD,      *Wo_l = wl + off + 3 * DD;
        const __nv_bfloat16 *Wg_h = wh + off + 4 * DD,      *Wg_l = wl + off + 4 * DD;
        const __nv_bfloat16 *Wu_h = wh + off + 4 * DD + DF, *Wu_l = wl + off + 4 * DD + DF;
        const __nv_bfloat16 *Wd_h = wh + off + 4 * DD + 2 * DF, *Wd_l = wl + off + 4 * DD + 2 * DF;
        const float* Bq_l = Bq + (size_t)l * RLORA * DMODEL;
        const float* Bk_l = Bk + (size_t)l * RLORA * DMODEL;
        const float* Bv_l = Bv + (size_t)l * RLORA * DMODEL;
        const float* Bo_l = Bo + (size_t)l * RLORA * DMODEL;
        const float* Bg_l = Bg + (size_t)l * RLORA * FFDIM;
        const float* Bu_l = Bu + (size_t)l * RLORA * FFDIM;
        const float* Bd_l = Bd + (size_t)l * RLORA * DMODEL;

        if (l > 0) {
            rmsnorm_kernel<<<MTOK, 256>>>(h, ln1 + l * DMODEL, x, ah, al);
            lora_fast<3><<<MTOK / 8, 256>>>(x, DMODEL, Aq + l * DMODEL * RLORA,
                                            Ak + l * DMODEL * RLORA, Av + l * DMODEL * RLORA,
                                            t0, t1, t2);
            gemm_tc<<<gD, 256, GSMEM>>>(ah, al, Wq_h, Wq_l, q, MTOK, DMODEL, DMODEL, t0, Bq_l, 0,
                                        nullptr, nullptr, nullptr);
            gemm_tc<<<gD, 256, GSMEM>>>(ah, al, Wk_h, Wk_l, k, MTOK, DMODEL, DMODEL, t1, Bk_l, 0,
                                        nullptr, nullptr, nullptr);
            gemm_tc<<<gD, 256, GSMEM>>>(ah, al, Wv_h, Wv_l, v, MTOK, DMODEL, DMODEL, t2, Bv_l, 0,
                                        nullptr, nullptr, nullptr);
        }

        rope_kernel<<<(MTOK * NHEAD * 64 + 255) / 256, 256>>>(q, k, qh, ql, kh, kl);
        vsplit_t<<<dim3(MTOK / 32, DMODEL / 32), tB>>>(v, vth, vtl);

        scores_mma<<<dim3(4, 4, BB * NHEAD), 256, SCSM>>>(qh, ql, kh, kl, mT, mM, sc);
        softmax_kernel<<<BB * NHEAD * SEQ, 256>>>(sc, ph, pl);
        attnv_mma<<<dim3(1, 4, BB * NHEAD), 256, AVSM>>>(ph, pl, vth, vtl, o, ah, al);

        lora_fast<1><<<MTOK / 8, 256>>>(o, DMODEL, Ao + (size_t)l * DMODEL * RLORA,
                                        nullptr, nullptr, t0, nullptr, nullptr);
        gemm_tc<<<gD, 256, GSMEM>>>(ah, al, Wo_h, Wo_l, h, MTOK, DMODEL, DMODEL, t0, Bo_l, 1,
                                    nullptr, nullptr, nullptr);

        rmsnorm_kernel<<<MTOK, 256>>>(h, ln2 + l * DMODEL, x, ah, al);
        lora_fast<2><<<MTOK / 8, 256>>>(x, DMODEL, Ag + (size_t)l * DMODEL * RLORA,
                                        Au + (size_t)l * DMODEL * RLORA, nullptr,
                                        t0, t1, nullptr);
        gemm_tc<<<gF, 256, GSMEM>>>(ah, al, Wg_h, Wg_l, gg, MTOK, FFDIM, DMODEL, t0, Bg_l, 0,
                                    nullptr, nullptr, nullptr);
        // up-GEMM with fused swiglu: reads ah/al (x splits), writes fp32 into gg and
        // bf16 splits into ph/pl (dead after attnv -> no aliasing with operands)
        gemm_tc<<<gF, 256, GSMEM>>>(ah, al, Wu_h, Wu_l, gg, MTOK, FFDIM, DMODEL, t1, Bu_l, 2,
                                    gg, ph, pl);

        lora_fast<1><<<MTOK / 8, 256>>>(gg, FFDIM, Ad + (size_t)l * FFDIM * RLORA,
                                        nullptr, nullptr, t0, nullptr, nullptr);
        gemm_tc<<<gD, 256, GSMEM>>>(ph, pl, Wd_h, Wd_l, h, MTOK, DMODEL, FFDIM, t0, Bd_l, 1,
                                    nullptr, nullptr, nullptr);
    }

    rmsnorm_kernel<<<MTOK, 256>>>(h, lnf, x, ah, al);
    reps_kernel<<<BB, 256>>>(x, mT, mM, rp);
    loss_kernel<<<1, 256>>>(rp, (float*)d_out);
}

// round 14
// speedup vs baseline: 2.5938x; 1.0260x over previous
#include <cuda_runtime.h>
#include <cuda_bf16.h>
#include <math.h>
#include <stdint.h>

// Problem constants
#define LAYERS 2
#define DMODEL 2048
#define NHEAD  16
#define HDIM   128
#define FFDIM  5632
#define RLORA  16
#define BATCH  4
#define SEQ    512
#define BB     8
#define MTOK   (BB*SEQ)
#define LORA_SCALE 1.4f
#define SCALE_QK 0.08838834764831845f

// ---------------- scratch ----------------
__device__ float g_h   [MTOK * DMODEL];
__device__ float g_x   [MTOK * DMODEL];
__device__ float g_q   [MTOK * DMODEL];
__device__ float g_k   [MTOK * DMODEL];
__device__ float g_v   [MTOK * DMODEL];
__device__ float g_o   [MTOK * DMODEL];
__device__ float g_sc  [BB * NHEAD * SEQ * SEQ];
__device__ float g_gate[MTOK * FFDIM];
__device__ float g_up  [MTOK * FFDIM];
__device__ float g_t   [3 * MTOK * RLORA];
__device__ float g_reps[BB * DMODEL];
__device__ __nv_bfloat16 g_ah[MTOK * FFDIM];
__device__ __nv_bfloat16 g_al[MTOK * FFDIM];
__device__ __nv_bfloat16 g_wh[2 * (4 * DMODEL * DMODEL + 3 * DMODEL * FFDIM)];
__device__ __nv_bfloat16 g_wl[2 * (4 * DMODEL * DMODEL + 3 * DMODEL * FFDIM)];
__device__ __nv_bfloat16 g_qh[MTOK * DMODEL];
__device__ __nv_bfloat16 g_ql[MTOK * DMODEL];
__device__ __nv_bfloat16 g_kh[MTOK * DMODEL];
__device__ __nv_bfloat16 g_kl[MTOK * DMODEL];
__device__ __nv_bfloat16 g_ph[BB * NHEAD * SEQ * SEQ];
__device__ __nv_bfloat16 g_pl[BB * NHEAD * SEQ * SEQ];
__device__ __nv_bfloat16 g_vth[MTOK * DMODEL];
__device__ __nv_bfloat16 g_vtl[MTOK * DMODEL];

// =================== helpers ===================
__device__ __forceinline__ uint32_t smem_u32(const void* p) {
    uint32_t a;
    asm("{ .reg .u64 t; cvta.to.shared.u64 t, %1; cvt.u32.u64 %0, t; }" : "=r"(a) : "l"(p));
    return a;
}
__device__ __forceinline__ void cp_async16(uint32_t saddr, const void* gptr) {
    asm volatile("cp.async.cg.shared.global [%0], [%1], 16;" :: "r"(saddr), "l"(gptr));
}
__device__ __forceinline__ void cp_commit() { asm volatile("cp.async.commit_group;"); }
template <int NWAIT>
__device__ __forceinline__ void cp_wait() {
    asm volatile("cp.async.wait_group %0;" :: "n"(NWAIT));
}
__device__ __forceinline__ void mma16(float* d, const uint32_t* a, uint32_t b0, uint32_t b1) {
    asm volatile(
        "mma.sync.aligned.m16n8k16.row.col.f32.bf16.bf16.f32 "
        "{%0,%1,%2,%3}, {%4,%5,%6,%7}, {%8,%9}, {%0,%1,%2,%3};"
        : "+f"(d[0]), "+f"(d[1]), "+f"(d[2]), "+f"(d[3])
        : "r"(a[0]), "r"(a[1]), "r"(a[2]), "r"(a[3]), "r"(b0), "r"(b1));
}
__device__ __forceinline__ void ldm_x4(uint32_t* r, uint32_t addr) {
    asm volatile("ldmatrix.sync.aligned.m8n8.x4.shared.b16 {%0,%1,%2,%3}, [%4];"
                 : "=r"(r[0]), "=r"(r[1]), "=r"(r[2]), "=r"(r[3]) : "r"(addr));
}
__device__ __forceinline__ void split_bf16(float v, __nv_bfloat16& h, __nv_bfloat16& l) {
    h = __float2bfloat16(v);
    l = __float2bfloat16(v - __bfloat162float(h));
}
__device__ __forceinline__ uint32_t pack_bf2(__nv_bfloat16 a, __nv_bfloat16 b) {
    uint16_t ua = *reinterpret_cast<uint16_t*>(&a);
    uint16_t ub = *reinterpret_cast<uint16_t*>(&b);
    return (uint32_t)ua | ((uint32_t)ub << 16);
}

// 4-stage pipeline, BK=16. Per-stage arrays: 128 rows x 16 bf16, 48B row stride.
#define SMSB16  48
#define ARRB16  6144
#define STGB16  24576
#define NSTAGE  4
#define LA_OFF  98304
#define LB_OFF  104448
#define GSMEM   110592
#define SCSM    98816
#define AVSM    98304

// ---- compute one 128x16 stage (bf16x3), accumulator-interleaved ----
#define COMPUTE16(stbase)                                                         \
    {                                                                             \
        uint32_t ahf[2][4], alf[2][4];                                            \
        int grp = lane >> 3, r8 = lane & 7;                                       \
        int mm = (grp & 1) * 8 + r8;                                              \
        int koff = (grp >> 1) * 8;                                                \
        _Pragma("unroll")                                                         \
        for (int mt = 0; mt < 2; mt++) {                                          \
            uint32_t ad = (stbase) + (wm * 32 + mt * 16 + mm) * SMSB16 + koff * 2;\
            ldm_x4(ahf[mt], ad);                                                  \
            ldm_x4(alf[mt], ad + ARRB16);                                         \
        }                                                                         \
        _Pragma("unroll")                                                         \
        for (int np = 0; np < 4; np++) {                                          \
            int nn = (grp >> 1) * 8 + r8;                                         \
            int koffb = (grp & 1) * 8;                                            \
            uint32_t bd = (stbase) + 2 * ARRB16 + (wn * 64 + np * 16 + nn) * SMSB16 + koffb * 2; \
            uint32_t bh[4], bl[4];                                                \
            ldm_x4(bh, bd);                                                       \
            ldm_x4(bl, bd + ARRB16);                                              \
            mma16(d[0][np * 2],     ahf[0], bh[0], bh[1]);                        \
            mma16(d[0][np * 2 + 1], ahf[0], bh[2], bh[3]);                        \
            mma16(d[1][np * 2],     ahf[1], bh[0], bh[1]);                        \
            mma16(d[1][np * 2 + 1], ahf[1], bh[2], bh[3]);                        \
            mma16(d[0][np * 2],     ahf[0], bl[0], bl[1]);                        \
            mma16(d[0][np * 2 + 1], ahf[0], bl[2], bl[3]);                        \
            mma16(d[1][np * 2],     ahf[1], bl[0], bl[1]);                        \
            mma16(d[1][np * 2 + 1], ahf[1], bl[2], bl[3]);                        \
            mma16(d[0][np * 2],     alf[0], bh[0], bh[1]);                        \
            mma16(d[0][np * 2 + 1], alf[0], bh[2], bh[3]);                        \
            mma16(d[1][np * 2],     alf[1], bh[0], bh[1]);                        \
            mma16(d[1][np * 2 + 1], alf[1], bh[2], bh[3]);                        \
        }                                                                         \
    }

#define ISSUE16(kt, aH, aL, bH, bL, LDA, LDB)                                     \
    {                                                                             \
        const int k0_ = (kt) << 4;                                                \
        const int buf_ = (kt) & (NSTAGE - 1);                                     \
        _Pragma("unroll")                                                         \
        for (int j = 0; j < 4; j++) {                                             \
            int e = tid + j * 256;                                                \
            int arr = e >> 8;                                                     \
            int i = e & 255;                                                      \
            int row = i >> 1;                                                     \
            int cg = (i & 1) << 3;                                                \
            const __nv_bfloat16* gp;                                              \
            if (arr == 0)      gp = (aH) + (size_t)row * (LDA) + k0_ + cg;        \
            else if (arr == 1) gp = (aL) + (size_t)row * (LDA) + k0_ + cg;        \
            else if (arr == 2) gp = (bH) + (size_t)row * (LDB) + k0_ + cg;        \
            else               gp = (bL) + (size_t)row * (LDB) + k0_ + cg;        \
            cp_async16(sb + buf_ * STGB16 + arr * ARRB16 + row * SMSB16 + cg * 2, gp); \
        }                                                                         \
        cp_commit();                                                              \
    }

#define MAINLOOP(nk, aH, aL, bH, bL, LDA, LDB)                                    \
    {                                                                             \
        ISSUE16(0, aH, aL, bH, bL, LDA, LDB);                                     \
        ISSUE16(1, aH, aL, bH, bL, LDA, LDB);                                     \
        ISSUE16(2, aH, aL, bH, bL, LDA, LDB);                                     \
        for (int kt = 0; kt < (nk); kt++) {                                       \
            cp_wait<2>();                                                         \
            __syncthreads();                                                      \
            const uint32_t st_ = sb + (kt & (NSTAGE - 1)) * STGB16;               \
            COMPUTE16(st_)                                                        \
            if (kt + 3 < (nk)) { ISSUE16(kt + 3, aH, aL, bH, bL, LDA, LDB); }     \
            else               { cp_commit(); }                                   \
        }                                                                         \
        cp_wait<0>();                                                             \
        __syncthreads();                                                          \
    }

// =================== main GEMM with fused LoRA + residual ===================
__global__ __launch_bounds__(256, 2)
void gemm_tc(const __nv_bfloat16* __restrict__ Agh, const __nv_bfloat16* __restrict__ Agl,
             const __nv_bfloat16* __restrict__ Wgh, const __nv_bfloat16* __restrict__ Wgl,
             float* __restrict__ C, int M, int N, int K,
             const float* __restrict__ lT, const float* __restrict__ lB, int accum)
{
    extern __shared__ char smc[];
    const int tid  = threadIdx.x;
    const int wid  = tid >> 5;
    const int lane = tid & 31;
    const int t4   = lane & 3;
    const int g    = lane >> 2;
    const int wm   = wid >> 1;
    const int wn   = wid & 1;
    const int bm   = blockIdx.y * 128;
    const int bn   = blockIdx.x * 128;
    const uint32_t sb = smem_u32(smc);

    __nv_bfloat16* la = (__nv_bfloat16*)(smc + LA_OFF);
    __nv_bfloat16* lb = (__nv_bfloat16*)(smc + LB_OFF);
    for (int i = tid; i < 2048; i += 256) {
        int row = i >> 4, r = i & 15;
        la[row * 24 + r] = __float2bfloat16(LORA_SCALE * lT[(size_t)(bm + row) * RLORA + r]);
        lb[row * 24 + r] = __float2bfloat16(lB[(size_t)r * N + bn + row]);
    }

    float d[2][8][4];
    #pragma unroll
    for (int mt = 0; mt < 2; mt++)
        #pragma unroll
        for (int nt = 0; nt < 8; nt++)
            #pragma unroll
            for (int j = 0; j < 4; j++) d[mt][nt][j] = 0.f;

    const __nv_bfloat16* aH = Agh + (size_t)bm * K;
    const __nv_bfloat16* aL = Agl + (size_t)bm * K;
    const __nv_bfloat16* bH = Wgh + (size_t)bn * K;
    const __nv_bfloat16* bL = Wgl + (size_t)bn * K;

    const int nk = K >> 4;
    MAINLOOP(nk, aH, aL, bH, bL, K, K)

    // LoRA tail (hi-only, K=16)
    {
        uint32_t a[2][4];
        #pragma unroll
        for (int mt = 0; mt < 2; mt++) {
            const char* pa = (const char*)la + (wm * 32 + mt * 16 + g) * 48 + t4 * 4;
            a[mt][0] = *(const uint32_t*)(pa);
            a[mt][1] = *(const uint32_t*)(pa + 8 * 48);
            a[mt][2] = *(const uint32_t*)(pa + 16);
            a[mt][3] = *(const uint32_t*)(pa + 8 * 48 + 16);
        }
        #pragma unroll
        for (int nt = 0; nt < 8; nt++) {
            const char* pb = (const char*)lb + (wn * 64 + nt * 8 + g) * 48 + t4 * 4;
            uint32_t b0 = *(const uint32_t*)(pb);
            uint32_t b1 = *(const uint32_t*)(pb + 16);
            #pragma unroll
            for (int mt = 0; mt < 2; mt++) mma16(d[mt][nt], a[mt], b0, b1);
        }
    }

    #pragma unroll
    for (int mt = 0; mt < 2; mt++) {
        const int r0 = bm + wm * 32 + mt * 16 + g;
        #pragma unroll
        for (int nt = 0; nt < 8; nt++) {
            const int c0 = bn + wn * 64 + nt * 8 + 2 * t4;
            float2 v0 = make_float2(d[mt][nt][0], d[mt][nt][1]);
            float2 v1 = make_float2(d[mt][nt][2], d[mt][nt][3]);
            float* p0 = C + (size_t)r0 * N + c0;
            float* p1 = C + (size_t)(r0 + 8) * N + c0;
            if (accum) {
                float2 o0 = *(const float2*)p0;
                float2 o1 = *(const float2*)p1;
                v0.x += o0.x; v0.y += o0.y;
                v1.x += o1.x; v1.y += o1.y;
            }
            *(float2*)p0 = v0;
            *(float2*)p1 = v1;
        }
    }
}

// =================== scores (skip masked tiles entirely) ===================
__global__ __launch_bounds__(256, 2)
void scores_mma(const __nv_bfloat16* __restrict__ Qh, const __nv_bfloat16* __restrict__ Ql,
                const __nv_bfloat16* __restrict__ Kh, const __nv_bfloat16* __restrict__ Kl,
                const int* __restrict__ mT, const int* __restrict__ mM,
                float* __restrict__ S_)
{
    extern __shared__ char smc[];
    const int tid  = threadIdx.x;
    const int wid  = tid >> 5;
    const int lane = tid & 31;
    const int t4   = lane & 3;
    const int g    = lane >> 2;
    const int wm   = wid >> 1;
    const int wn   = wid & 1;
    const int z    = blockIdx.z;
    const int bb   = z >> 4;
    const int hh   = z & 15;
    const int bm   = blockIdx.y * 128;
    const int bn   = blockIdx.x * 128;
    if (bn > bm) return;   // causal softmax never reads cols > row

    const uint32_t sb = smem_u32(smc);
    int* msk = (int*)(smc + NSTAGE * STGB16);

    const int* mask = (bb < 4) ? (mT + bb * SEQ) : (mM + (bb - 4) * SEQ);
    if (tid < 128) msk[tid] = mask[bn + tid];

    float* Sbase = S_ + (size_t)z * SEQ * SEQ;

    float d[2][8][4];
    #pragma unroll
    for (int mt = 0; mt < 2; mt++)
        #pragma unroll
        for (int nt = 0; nt < 8; nt++)
            #pragma unroll
            for (int j = 0; j < 4; j++) d[mt][nt][j] = 0.f;

    const __nv_bfloat16* aH = Qh + (size_t)(bb * SEQ + bm) * DMODEL + hh * HDIM;
    const __nv_bfloat16* aL = Ql + (size_t)(bb * SEQ + bm) * DMODEL + hh * HDIM;
    const __nv_bfloat16* bH = Kh + (size_t)(bb * SEQ + bn) * DMODEL + hh * HDIM;
    const __nv_bfloat16* bL = Kl + (size_t)(bb * SEQ + bn) * DMODEL + hh * HDIM;

    const int nk = HDIM >> 4;
    MAINLOOP(nk, aH, aL, bH, bL, DMODEL, DMODEL)

    #pragma unroll
    for (int mt = 0; mt < 2; mt++) {
        const int r0 = wm * 32 + mt * 16 + g;
        #pragma unroll
        for (int nt = 0; nt < 8; nt++) {
            const int c0 = wn * 64 + nt * 8 + 2 * t4;
            #pragma unroll
            for (int half = 0; half < 2; half++) {
                int r = r0 + half * 8;
                int sq = bm + r, sk0 = bn + c0;
                float va = d[mt][nt][half * 2], vb = d[mt][nt][half * 2 + 1];
                bool ok0 = (sk0 <= sq) && (msk[c0] > 0);
                bool ok1 = (sk0 + 1 <= sq) && (msk[c0 + 1] > 0);
                float2 out;
                out.x = va * SCALE_QK + (ok0 ? 0.f : -1e9f);
                out.y = vb * SCALE_QK + (ok1 ? 0.f : -1e9f);
                *(float2*)(Sbase + (size_t)sq * SEQ + sk0) = out;
            }
        }
    }
}

// =================== attnv (causal-truncated, packed bf16 stores) ===================
__global__ __launch_bounds__(256, 2)
void attnv_mma(const __nv_bfloat16* __restrict__ Ph, const __nv_bfloat16* __restrict__ Pl,
               const __nv_bfloat16* __restrict__ Vth, const __nv_bfloat16* __restrict__ Vtl,
               float* __restrict__ O,
               __nv_bfloat16* __restrict__ Oh, __nv_bfloat16* __restrict__ Ol)
{
    extern __shared__ char smc[];
    const int tid  = threadIdx.x;
    const int wid  = tid >> 5;
    const int lane = tid & 31;
    const int t4   = lane & 3;
    const int g    = lane >> 2;
    const int wm   = wid >> 1;
    const int wn   = wid & 1;
    const int z    = blockIdx.z;
    const int bb   = z >> 4;
    const int hh   = z & 15;
    const int bm   = blockIdx.y * 128;
    const uint32_t sb = smem_u32(smc);

    float d[2][8][4];
    #pragma unroll
    for (int mt = 0; mt < 2; mt++)
        #pragma unroll
        for (int nt = 0; nt < 8; nt++)
            #pragma unroll
            for (int j = 0; j < 4; j++) d[mt][nt][j] = 0.f;

    const __nv_bfloat16* aH = Ph + ((size_t)z * SEQ + bm) * SEQ;
    const __nv_bfloat16* aL = Pl + ((size_t)z * SEQ + bm) * SEQ;
    const __nv_bfloat16* bH = Vth + (size_t)z * HDIM * SEQ;
    const __nv_bfloat16* bL = Vtl + (size_t)z * HDIM * SEQ;

    const int nk = (bm >> 4) + 8;
    MAINLOOP(nk, aH, aL, bH, bL, SEQ, SEQ)

    #pragma unroll
    for (int mt = 0; mt < 2; mt++) {
        const int r0 = bm + wm * 32 + mt * 16 + g;
        #pragma unroll
        for (int nt = 0; nt < 8; nt++) {
            const int c0 = wn * 64 + nt * 8 + 2 * t4;
            #pragma unroll
            for (int half = 0; half < 2; half++) {
                int r = r0 + half * 8;
                size_t oidx = (size_t)(bb * SEQ + r) * DMODEL + hh * HDIM + c0;
                float va = d[mt][nt][half * 2], vb = d[mt][nt][half * 2 + 1];
                *(float2*)(O + oidx) = make_float2(va, vb);
                __nv_bfloat16 h0, l0, h1, l1;
                split_bf16(va, h0, l0);
                split_bf16(vb, h1, l1);
                *(uint32_t*)(Oh + oidx) = pack_bf2(h0, h1);
                *(uint32_t*)(Ol + oidx) = pack_bf2(l0, l1);
            }
        }
    }
}

// =================== fast LoRA-T ===================
#define LCH 512
template <int NM>
__global__ __launch_bounds__(256)
void lora_fast(const float* __restrict__ X, int K,
               const float* __restrict__ A0, const float* __restrict__ A1,
               const float* __restrict__ A2,
               float* __restrict__ T0, float* __restrict__ T1, float* __restrict__ T2)
{
    __shared__ float At[16 * 513];
    const int tid  = threadIdx.x;
    const int lane = tid & 31;
    const int warp = tid >> 5;
    const int row  = blockIdx.x * 8 + warp;

    const float* As[3] = {A0, A1, A2};
    float acc[NM][16];
    #pragma unroll
    for (int m = 0; m < NM; m++)
        #pragma unroll
        for (int r = 0; r < 16; r++) acc[m][r] = 0.f;

    for (int k0 = 0; k0 < K; k0 += LCH) {
        float xs[16];
        #pragma unroll
        for (int j = 0; j < 16; j++)
            xs[j] = X[(size_t)row * K + k0 + lane + 32 * j];
        #pragma unroll
        for (int m = 0; m < NM; m++) {
            __syncthreads();
            const float* Am = As[m];
            for (int i = tid; i < 16 * LCH; i += 256) {
                int k = i >> 4, r = i & 15;
                At[r * 513 + k] = Am[(size_t)(k0 + k) * RLORA + r];
            }
            __syncthreads();
            #pragma unroll
            for (int j = 0; j < 16; j++) {
                int k = lane + 32 * j;
                float xv = xs[j];
                #pragma unroll
                for (int r = 0; r < 16; r++)
                    acc[m][r] += xv * At[r * 513 + k];
            }
        }
    }

    float* Ts[3] = {T0, T1, T2};
    #pragma unroll
    for (int m = 0; m < NM; m++) {
        #pragma unroll
        for (int r = 0; r < 16; r++) {
            float v = acc[m][r];
            #pragma unroll
            for (int o = 16; o > 0; o >>= 1) v += __shfl_xor_sync(0xffffffffu, v, o);
            if (lane == 0) Ts[m][row * RLORA + r] = v;
        }
    }
}

// ---------------- weight transpose + split ----------------
__global__ void transpose_split(const float* __restrict__ W,
                                __nv_bfloat16* __restrict__ Wh, __nv_bfloat16* __restrict__ Wl,
                                int Kd, int Nd)
{
    __shared__ float tile[32][33];
    int n0 = blockIdx.x * 32, k0 = blockIdx.y * 32;
    int x = threadIdx.x, y = threadIdx.y;
    #pragma unroll
    for (int dy = 0; dy < 32; dy += 8)
        tile[y + dy][x] = W[(size_t)(k0 + y + dy) * Nd + n0 + x];
    __syncthreads();
    #pragma unroll
    for (int dy = 0; dy < 32; dy += 8) {
        float v = tile[x][y + dy];
        size_t o = (size_t)(n0 + y + dy) * Kd + k0 + x;
        __nv_bfloat16 h, l;
        split_bf16(v, h, l);
        Wh[o] = h; Wl[o] = l;
    }
}

// ---------------- V transpose + split per head ----------------
__global__ void vsplit_t(const float* __restrict__ V,
                         __nv_bfloat16* __restrict__ Vth, __nv_bfloat16* __restrict__ Vtl)
{
    __shared__ float tile[32][33];
    int tok0 = blockIdx.x * 32, d0 = blockIdx.y * 32;
    int x = threadIdx.x, y = threadIdx.y;
    #pragma unroll
    for (int dy = 0; dy < 32; dy += 8)
        tile[y + dy][x] = V[(size_t)(tok0 + y + dy) * DMODEL + d0 + x];
    __syncthreads();
    int bb = tok0 >> 9, s0 = tok0 & 511;
    int hh = d0 >> 7, dd0 = d0 & 127;
    size_t zb = ((size_t)(bb * NHEAD + hh)) * HDIM * SEQ;
    #pragma unroll
    for (int dy = 0; dy < 32; dy += 8) {
        float v = tile[x][y + dy];
        size_t oidx = zb + (size_t)(dd0 + y + dy) * SEQ + s0 + x;
        __nv_bfloat16 h, l;
        split_bf16(v, h, l);
        Vth[oidx] = h; Vtl[oidx] = l;
    }
}

// ---------------- fused embed + rmsnorm(ln1 layer0) ----------------
__global__ void embed_rms(const int* __restrict__ idT, const int* __restrict__ idM,
                          const float* __restrict__ E, const float* __restrict__ W,
                          float* __restrict__ H, float* __restrict__ X,
                          __nv_bfloat16* __restrict__ Xh, __nv_bfloat16* __restrict__ Xl)
{
    __shared__ float red[256];
    int t  = blockIdx.x;
    int bb = t >> 9;
    int s  = t & 511;
    int id = (bb < 4) ? idT[bb * SEQ + s] : idM[(bb - 4) * SEQ + s];
    const float* src = E + (size_t)id * DMODEL;
    int tid = threadIdx.x;
    float vals[8];
    float ss = 0.f;
    #pragma unroll
    for (int j = 0; j < 8; j++) {
        float v = src[tid + 256 * j];
        vals[j] = v;
        ss += v * v;
    }
    red[tid] = ss; __syncthreads();
    for (int o = 128; o > 0; o >>= 1) {
        if (tid < o) red[tid] += red[tid + o];
        __syncthreads();
    }
    float scale = rsqrtf(red[0] / (float)DMODEL + 1e-6f);
    size_t base = (size_t)t * DMODEL;
    #pragma unroll
    for (int j = 0; j < 8; j++) {
        int idx = tid + 256 * j;
        float v = vals[j];
        H[base + idx] = v;
        float xv = v * scale * W[idx];
        X[base + idx] = xv;
        __nv_bfloat16 hh, ll;
        split_bf16(xv, hh, ll);
        Xh[base + idx] = hh; Xl[base + idx] = ll;
    }
}

// ---------------- rmsnorm ----------------
__global__ void rmsnorm_kernel(const float* __restrict__ H, const float* __restrict__ W,
                               float* __restrict__ X,
                               __nv_bfloat16* __restrict__ Xh, __nv_bfloat16* __restrict__ Xl)
{
    __shared__ float red[256];
    int row = blockIdx.x;
    const float* h = H + (size_t)row * DMODEL;
    int tid = threadIdx.x;
    float vals[8];
    float s = 0.f;
    #pragma unroll
    for (int j = 0; j < 8; j++) {
        float v = h[tid + 256 * j];
        vals[j] = v;
        s += v * v;
    }
    red[tid] = s; __syncthreads();
    for (int o = 128; o > 0; o >>= 1) {
        if (tid < o) red[tid] += red[tid + o];
        __syncthreads();
    }
    float scale = rsqrtf(red[0] / (float)DMODEL + 1e-6f);
    size_t base = (size_t)row * DMODEL;
    #pragma unroll
    for (int j = 0; j < 8; j++) {
        int idx = tid + 256 * j;
        float v = vals[j] * scale * W[idx];
        X[base + idx] = v;
        __nv_bfloat16 hh, ll;
        split_bf16(v, hh, ll);
        Xh[base + idx] = hh; Xl[base + idx] = ll;
    }
}

// ---------------- RoPE ----------------
__global__ void rope_kernel(const float* __restrict__ Q, const float* __restrict__ Kt,
                            __nv_bfloat16* __restrict__ Qh, __nv_bfloat16* __restrict__ Ql,
                            __nv_bfloat16* __restrict__ Kh, __nv_bfloat16* __restrict__ Kl)
{
    int i = blockIdx.x * blockDim.x + threadIdx.x;
    if (i >= MTOK * NHEAD * 64) return;
    int d = i & 63;
    int h = (i >> 6) & 15;
    int t = i >> 10;
    int s = t & 511;
    float freq = expf(-(float)d * (logf(10000.f) / 64.f));
    float ang = (float)s * freq;
    float sn, cs;
    sincosf(ang, &sn, &cs);
    size_t b0 = (size_t)t * DMODEL + h * HDIM + d;
    __nv_bfloat16 hh, ll;
    float x1 = Q[b0], x2 = Q[b0 + 64];
    float r1 = x1 * cs - x2 * sn;
    float r2 = x1 * sn + x2 * cs;
    split_bf16(r1, hh, ll); Qh[b0] = hh;      Ql[b0] = ll;
    split_bf16(r2, hh, ll); Qh[b0 + 64] = hh; Ql[b0 + 64] = ll;
    x1 = Kt[b0]; x2 = Kt[b0 + 64];
    r1 = x1 * cs - x2 * sn;
    r2 = x1 * sn + x2 * cs;
    split_bf16(r1, hh, ll); Kh[b0] = hh;      Kl[b0] = ll;
    split_bf16(r2, hh, ll); Kh[b0 + 64] = hh; Kl[b0 + 64] = ll;
}

// ---------------- causal-aware row softmax ----------------
__global__ void softmax_kernel(const float* __restrict__ S_,
                               __nv_bfloat16* __restrict__ Ph, __nv_bfloat16* __restrict__ Pl)
{
    __shared__ float red[256];
    const float* p = S_ + (size_t)blockIdx.x * SEQ;
    int sq = blockIdx.x & (SEQ - 1);
    int t = threadIdx.x;
    bool ok0 = (t <= sq);
    bool ok1 = (t + 256 <= sq);
    float v0 = ok0 ? p[t] : -1e30f;
    float v1 = ok1 ? p[t + 256] : -1e30f;
    float m = fmaxf(v0, v1);
    red[t] = m; __syncthreads();
    for (int o = 128; o > 0; o >>= 1) {
        if (t < o) red[t] = fmaxf(red[t], red[t + o]);
        __syncthreads();
    }
    m = red[0]; __syncthreads();
    float e0 = ok0 ? expf(v0 - m) : 0.f;
    float e1 = ok1 ? expf(v1 - m) : 0.f;
    red[t] = e0 + e1; __syncthreads();
    for (int o = 128; o > 0; o >>= 1) {
        if (t < o) red[t] += red[t + o];
        __syncthreads();
    }
    float inv = 1.f / red[0];
    size_t base = (size_t)blockIdx.x * SEQ;
    __nv_bfloat16 hh, ll;
    split_bf16(e0 * inv, hh, ll); Ph[base + t] = hh;       Pl[base + t] = ll;
    split_bf16(e1 * inv, hh, ll); Ph[base + t + 256] = hh; Pl[base + t + 256] = ll;
}

// ---------------- swiglu ----------------
__global__ void swiglu_kernel(float* __restrict__ G, const float* __restrict__ U,
                              __nv_bfloat16* __restrict__ Gh, __nv_bfloat16* __restrict__ Gl)
{
    size_t i = (size_t)blockIdx.x * blockDim.x + threadIdx.x;
    if (i >= (size_t)MTOK * FFDIM) return;
    float g = G[i];
    float sig = 1.f / (1.f + expf(-g));
    float v = g * sig * U[i];
    G[i] = v;
    __nv_bfloat16 hh, ll;
    split_bf16(v, hh, ll);
    Gh[i] = hh; Gl[i] = ll;
}

// ---------------- reps extraction + L2 normalize ----------------
__global__ void reps_kernel(const float* __restrict__ X, const int* __restrict__ mT,
                            const int* __restrict__ mM, float* __restrict__ R_)
{
    __shared__ int ired[256];
    __shared__ float fred[256];
    __shared__ int sidx;
    int bb = blockIdx.x;
    const int* mask = (bb < 4) ? mT : mM;
    int b = bb & 3;
    int t = threadIdx.x;
    int s = 0;
    for (int j = t; j < SEQ; j += 256) s += mask[b * SEQ + j];
    ired[t] = s; __syncthreads();
    for (int o = 128; o > 0; o >>= 1) {
        if (t < o) ired[t] += ired[t + o];
        __syncthreads();
    }
    if (t == 0) {
        int last = mask[0 * SEQ + 511] + mask[1 * SEQ + 511] +
                   mask[2 * SEQ + 511] + mask[3 * SEQ + 511];
        sidx = (last == BATCH) ? (SEQ - 1) : (ired[0] - 1);
    }
    __syncthreads();
    const float* row = X + (size_t)(bb * SEQ + sidx) * DMODEL;
    float ss = 0.f;
    for (int j = t; j < DMODEL; j += 256) { float v = row[j]; ss += v * v; }
    fred[t] = ss; __syncthreads();
    for (int o = 128; o > 0; o >>= 1) {
        if (t < o) fred[t] += fred[t + o];
        __syncthreads();
    }
    float inv = 1.f / sqrtf(fred[0]);
    for (int j = t; j < DMODEL; j += 256) R_[bb * DMODEL + j] = row[j] * inv;
}

// ---------------- contrastive loss ----------------
__global__ void loss_kernel(const float* __restrict__ R_, float* __restrict__ out)
{
    __shared__ float sims[16];
    int tid = threadIdx.x;
    int warp = tid >> 5, lane = tid & 31;
    for (int p = warp; p < 16; p += 8) {
        int i = p >> 2, j = p & 3;
        const float* a = R_ + i * DMODEL;
        const float* bR = R_ + (4 + j) * DMODEL;
        float d = 0.f;
        for (int k2 = lane; k2 < DMODEL; k2 += 32) d += a[k2] * bR[k2];
        #pragma unroll
        for (int o = 16; o > 0; o >>= 1) d += __shfl_xor_sync(0xffffffff, d, o);
        if (lane == 0) sims[p] = d * 20.f;
    }
    __syncthreads();
    if (tid == 0) {
        float loss = 0.f;
        for (int i = 0; i < 4; i++) {
            float m = -1e30f;
            for (int j = 0; j < 4; j++) m = fmaxf(m, sims[i * 4 + j]);
            float sum = 0.f;
            for (int j = 0; j < 4; j++) sum += expf(sims[i * 4 + j] - m);
            loss += (logf(sum) + m) - sims[i * 4 + i];
        }
        out[0] = loss * 0.25f;
    }
}

// ---------------- host driver ----------------
static void* symaddr_raw(const void* sym)
{
    void* p = nullptr;
    cudaGetSymbolAddress(&p, sym);
    return p;
}

extern "C" void kernel_launch(void* const* d_in, const int* in_sizes, int n_in,
                              void* d_out, int out_size)
{
    const int*   idT = (const int*)d_in[0];
    const int*   mT  = (const int*)d_in[1];
    const int*   idM = (const int*)d_in[2];
    const int*   mM  = (const int*)d_in[3];
    const float* emb = (const float*)d_in[4];
    const float* ln1 = (const float*)d_in[5];
    const float* ln2 = (const float*)d_in[6];
    const float* lnf = (const float*)d_in[7];
    const float* Wq = (const float*)d_in[8],  *Aq = (const float*)d_in[9],  *Bq = (const float*)d_in[10];
    const float* Wk = (const float*)d_in[11], *Ak = (const float*)d_in[12], *Bk = (const float*)d_in[13];
    const float* Wv = (const float*)d_in[14], *Av = (const float*)d_in[15], *Bv = (const float*)d_in[16];
    const float* Wo = (const float*)d_in[17], *Ao = (const float*)d_in[18], *Bo = (const float*)d_in[19];
    const float* Wg = (const float*)d_in[20], *Ag = (const float*)d_in[21], *Bg = (const float*)d_in[22];
    const float* Wu = (const float*)d_in[23], *Au = (const float*)d_in[24], *Bu = (const float*)d_in[25];
    const float* Wd = (const float*)d_in[26], *Ad = (const float*)d_in[27], *Bd = (const float*)d_in[28];

    float* h  = (float*)symaddr_raw(g_h);
    float* x  = (float*)symaddr_raw(g_x);
    float* q  = (float*)symaddr_raw(g_q);
    float* k  = (float*)symaddr_raw(g_k);
    float* v  = (float*)symaddr_raw(g_v);
    float* o  = (float*)symaddr_raw(g_o);
    float* sc = (float*)symaddr_raw(g_sc);
    float* gg = (float*)symaddr_raw(g_gate);
    float* uu = (float*)symaddr_raw(g_up);
    float* t0 = (float*)symaddr_raw(g_t);
    float* t1 = t0 + MTOK * RLORA;
    float* t2 = t0 + 2 * MTOK * RLORA;
    float* rp = (float*)symaddr_raw(g_reps);
    __nv_bfloat16* ah  = (__nv_bfloat16*)symaddr_raw(g_ah);
    __nv_bfloat16* al  = (__nv_bfloat16*)symaddr_raw(g_al);
    __nv_bfloat16* wh  = (__nv_bfloat16*)symaddr_raw(g_wh);
    __nv_bfloat16* wl  = (__nv_bfloat16*)symaddr_raw(g_wl);
    __nv_bfloat16* qh  = (__nv_bfloat16*)symaddr_raw(g_qh);
    __nv_bfloat16* ql  = (__nv_bfloat16*)symaddr_raw(g_ql);
    __nv_bfloat16* kh  = (__nv_bfloat16*)symaddr_raw(g_kh);
    __nv_bfloat16* kl  = (__nv_bfloat16*)symaddr_raw(g_kl);
    __nv_bfloat16* ph  = (__nv_bfloat16*)symaddr_raw(g_ph);
    __nv_bfloat16* pl  = (__nv_bfloat16*)symaddr_raw(g_pl);
    __nv_bfloat16* vth = (__nv_bfloat16*)symaddr_raw(g_vth);
    __nv_bfloat16* vtl = (__nv_bfloat16*)symaddr_raw(g_vtl);

    cudaFuncSetAttribute(gemm_tc,    cudaFuncAttributeMaxDynamicSharedMemorySize, GSMEM);
    cudaFuncSetAttribute(scores_mma, cudaFuncAttributeMaxDynamicSharedMemorySize, SCSM);
    cudaFuncSetAttribute(attnv_mma,  cudaFuncAttributeMaxDynamicSharedMemorySize, AVSM);

    const size_t DD = (size_t)DMODEL * DMODEL;
    const size_t DF = (size_t)DMODEL * FFDIM;
    const size_t LSTR = 4 * DD + 3 * DF;
    const dim3 tD(DMODEL / 32, DMODEL / 32), tB(32, 8);
    const dim3 tF(FFDIM / 32, DMODEL / 32);
    const dim3 tFd(DMODEL / 32, FFDIM / 32);
    const dim3 gD(DMODEL / 128, MTOK / 128);
    const dim3 gF(FFDIM / 128, MTOK / 128);

    // ---- prologue ----
    transpose_split<<<tD, tB>>>(Wq, wh, wl, DMODEL, DMODEL);
    embed_rms<<<MTOK, 256>>>(idT, idM, emb, ln1, h, x, ah, al);
    lora_fast<3><<<MTOK / 8, 256>>>(x, DMODEL, Aq, Ak, Av, t0, t1, t2);
    gemm_tc<<<gD, 256, GSMEM>>>(ah, al, wh, wl, q, MTOK, DMODEL, DMODEL, t0, Bq, 0);
    transpose_split<<<tD, tB>>>(Wk, wh + DD, wl + DD, DMODEL, DMODEL);
    gemm_tc<<<gD, 256, GSMEM>>>(ah, al, wh + DD, wl + DD, k, MTOK, DMODEL, DMODEL, t1, Bk, 0);
    transpose_split<<<tD, tB>>>(Wv, wh + 2 * DD, wl + 2 * DD, DMODEL, DMODEL);
    gemm_tc<<<gD, 256, GSMEM>>>(ah, al, wh + 2 * DD, wl + 2 * DD, v, MTOK, DMODEL, DMODEL, t2, Bv, 0);

    // remaining transposes
    transpose_split<<<tD, tB>>>(Wo, wh + 3 * DD, wl + 3 * DD, DMODEL, DMODEL);
    transpose_split<<<tF, tB>>>(Wg, wh + 4 * DD, wl + 4 * DD, DMODEL, FFDIM);
    transpose_split<<<tF, tB>>>(Wu, wh + 4 * DD + DF, wl + 4 * DD + DF, DMODEL, FFDIM);
    transpose_split<<<tFd, tB>>>(Wd, wh + 4 * DD + 2 * DF, wl + 4 * DD + 2 * DF, FFDIM, DMODEL);
    for (int l = 1; l < LAYERS; l++) {
        size_t off = (size_t)l * LSTR;
        transpose_split<<<tD, tB>>>(Wq + l * DD, wh + off,          wl + off,          DMODEL, DMODEL);
        transpose_split<<<tD, tB>>>(Wk + l * DD, wh + off + DD,     wl + off + DD,     DMODEL, DMODEL);
        transpose_split<<<tD, tB>>>(Wv + l * DD, wh + off + 2 * DD, wl + off + 2 * DD, DMODEL, DMODEL);
        transpose_split<<<tD, tB>>>(Wo + l * DD, wh + off + 3 * DD, wl + off + 3 * DD, DMODEL, DMODEL);
        transpose_split<<<tF, tB>>>(Wg + l * DF, wh + off + 4 * DD, wl + off + 4 * DD, DMODEL, FFDIM);
        transpose_split<<<tF, tB>>>(Wu + l * DF, wh + off + 4 * DD + DF, wl + off + 4 * DD + DF, DMODEL, FFDIM);
        transpose_split<<<tFd, tB>>>(Wd + l * DF, wh + off + 4 * DD + 2 * DF, wl + off + 4 * DD + 2 * DF, FFDIM, DMODEL);
    }

    for (int l = 0; l < LAYERS; l++) {
        size_t off = (size_t)l * LSTR;
        const __nv_bfloat16 *Wq_h = wh + off,               *Wq_l = wl + off;
        const __nv_bfloat16 *Wk_h = wh + off + DD,          *Wk_l = wl + off + DD;
        const __nv_bfloat16 *Wv_h = wh + off + 2 * DD,      *Wv_l = wl + off + 2 * DD;
        const __nv_bfloat16 *Wo_h = wh + off + 3 * DD,      *Wo_l = wl + off + 3 * DD;
        const __nv_bfloat16 *Wg_h = wh + off + 4 * DD,      *Wg_l = wl + off + 4 * DD;
        const __nv_bfloat16 *Wu_h = wh + off + 4 * DD + DF, *Wu_l = wl + off + 4 * DD + DF;
        const __nv_bfloat16 *Wd_h = wh + off + 4 * DD + 2 * DF, *Wd_l = wl + off + 4 * DD + 2 * DF;
        const float* Bq_l = Bq + (size_t)l * RLORA * DMODEL;
        const float* Bk_l = Bk + (size_t)l * RLORA * DMODEL;
        const float* Bv_l = Bv + (size_t)l * RLORA * DMODEL;
        const float* Bo_l = Bo + (size_t)l * RLORA * DMODEL;
        const float* Bg_l = Bg + (size_t)l * RLORA * FFDIM;
        const float* Bu_l = Bu + (size_t)l * RLORA * FFDIM;
        const float* Bd_l = Bd + (size_t)l * RLORA * DMODEL;

        if (l > 0) {
            rmsnorm_kernel<<<MTOK, 256>>>(h, ln1 + l * DMODEL, x, ah, al);
            lora_fast<3><<<MTOK / 8, 256>>>(x, DMODEL, Aq + l * DMODEL * RLORA,
                                            Ak + l * DMODEL * RLORA, Av + l * DMODEL * RLORA,
                                            t0, t1, t2);
            gemm_tc<<<gD, 256, GSMEM>>>(ah, al, Wq_h, Wq_l, q, MTOK, DMODEL, DMODEL, t0, Bq_l, 0);
            gemm_tc<<<gD, 256, GSMEM>>>(ah, al, Wk_h, Wk_l, k, MTOK, DMODEL, DMODEL, t1, Bk_l, 0);
            gemm_tc<<<gD, 256, GSMEM>>>(ah, al, Wv_h, Wv_l, v, MTOK, DMODEL, DMODEL, t2, Bv_l, 0);
        }

        rope_kernel<<<(MTOK * NHEAD * 64 + 255) / 256, 256>>>(q, k, qh, ql, kh, kl);
        vsplit_t<<<dim3(MTOK / 32, DMODEL / 32), tB>>>(v, vth, vtl);

        scores_mma<<<dim3(4, 4, BB * NHEAD), 256, SCSM>>>(qh, ql, kh, kl, mT, mM, sc);
        softmax_kernel<<<BB * NHEAD * SEQ, 256>>>(sc, ph, pl);
        attnv_mma<<<dim3(1, 4, BB * NHEAD), 256, AVSM>>>(ph, pl, vth, vtl, o, ah, al);

        lora_fast<1><<<MTOK / 8, 256>>>(o, DMODEL, Ao + (size_t)l * DMODEL * RLORA,
                                        nullptr, nullptr, t0, nullptr, nullptr);
        gemm_tc<<<gD, 256, GSMEM>>>(ah, al, Wo_h, Wo_l, h, MTOK, DMODEL, DMODEL, t0, Bo_l, 1);

        rmsnorm_kernel<<<MTOK, 256>>>(h, ln2 + l * DMODEL, x, ah, al);
        lora_fast<2><<<MTOK / 8, 256>>>(x, DMODEL, Ag + (size_t)l * DMODEL * RLORA,
                                        Au + (size_t)l * DMODEL * RLORA, nullptr,
                                        t0, t1, nullptr);
        gemm_tc<<<gF, 256, GSMEM>>>(ah, al, Wg_h, Wg_l, gg, MTOK, FFDIM, DMODEL, t0, Bg_l, 0);
        gemm_tc<<<gF, 256, GSMEM>>>(ah, al, Wu_h, Wu_l, uu, MTOK, FFDIM, DMODEL, t1, Bu_l, 0);

        swiglu_kernel<<<(int)(((size_t)MTOK * FFDIM + 255) / 256), 256>>>(gg, uu, ah, al);

        lora_fast<1><<<MTOK / 8, 256>>>(gg, FFDIM, Ad + (size_t)l * FFDIM * RLORA,
                                        nullptr, nullptr, t0, nullptr, nullptr);
        gemm_tc<<<gD, 256, GSMEM>>>(ah, al, Wd_h, Wd_l, h, MTOK, DMODEL, FFDIM, t0, Bd_l, 1);
    }

    rmsnorm_kernel<<<MTOK, 256>>>(h, lnf, x, ah, al);
    reps_kernel<<<BB, 256>>>(x, mT, mM, rp);
    loss_kernel<<<1, 256>>>(rp, (float*)d_out);
}

// round 15
// speedup vs baseline: 2.7203x; 1.0488x over previous
#include <cuda_runtime.h>
#include <cuda_bf16.h>
#include <math.h>
#include <stdint.h>

// Problem constants
#define LAYERS 2
#define DMODEL 2048
#define NHEAD  16
#define HDIM   128
#define FFDIM  5632
#define RLORA  16
#define BATCH  4
#define SEQ    512
#define BB     8
#define MTOK   (BB*SEQ)
#define LORA_SCALE 1.4f
#define SCALE_QK 0.08838834764831845f

// ---------------- scratch ----------------
__device__ float g_h   [MTOK * DMODEL];
__device__ float g_x   [MTOK * DMODEL];
__device__ float g_q   [MTOK * DMODEL];
__device__ float g_k   [MTOK * DMODEL];
__device__ float g_v   [MTOK * DMODEL];
__device__ float g_o   [MTOK * DMODEL];
__device__ float g_sc  [BB * NHEAD * SEQ * SEQ];
__device__ float g_gate[MTOK * FFDIM];
__device__ float g_up  [MTOK * FFDIM];
__device__ float g_t   [3 * MTOK * RLORA];
__device__ float g_reps[BB * DMODEL];
__device__ __nv_bfloat16 g_ah[MTOK * FFDIM];
__device__ __nv_bfloat16 g_al[MTOK * FFDIM];
__device__ __nv_bfloat16 g_wh[2 * (4 * DMODEL * DMODEL + 3 * DMODEL * FFDIM)];
__device__ __nv_bfloat16 g_wl[2 * (4 * DMODEL * DMODEL + 3 * DMODEL * FFDIM)];
__device__ __nv_bfloat16 g_qh[MTOK * DMODEL];
__device__ __nv_bfloat16 g_ql[MTOK * DMODEL];
__device__ __nv_bfloat16 g_kh[MTOK * DMODEL];
__device__ __nv_bfloat16 g_kl[MTOK * DMODEL];
__device__ __nv_bfloat16 g_ph[BB * NHEAD * SEQ * SEQ];
__device__ __nv_bfloat16 g_pl[BB * NHEAD * SEQ * SEQ];
__device__ __nv_bfloat16 g_vth[MTOK * DMODEL];
__device__ __nv_bfloat16 g_vtl[MTOK * DMODEL];

// =================== helpers ===================
__device__ __forceinline__ uint32_t smem_u32(const void* p) {
    uint32_t a;
    asm("{ .reg .u64 t; cvta.to.shared.u64 t, %1; cvt.u32.u64 %0, t; }" : "=r"(a) : "l"(p));
    return a;
}
__device__ __forceinline__ void cp_async16(uint32_t saddr, const void* gptr) {
    asm volatile("cp.async.cg.shared.global [%0], [%1], 16;" :: "r"(saddr), "l"(gptr));
}
__device__ __forceinline__ void cp_commit() { asm volatile("cp.async.commit_group;"); }
template <int NWAIT>
__device__ __forceinline__ void cp_wait() {
    asm volatile("cp.async.wait_group %0;" :: "n"(NWAIT));
}
__device__ __forceinline__ void mma16(float* d, const uint32_t* a, uint32_t b0, uint32_t b1) {
    asm volatile(
        "mma.sync.aligned.m16n8k16.row.col.f32.bf16.bf16.f32 "
        "{%0,%1,%2,%3}, {%4,%5,%6,%7}, {%8,%9}, {%0,%1,%2,%3};"
        : "+f"(d[0]), "+f"(d[1]), "+f"(d[2]), "+f"(d[3])
        : "r"(a[0]), "r"(a[1]), "r"(a[2]), "r"(a[3]), "r"(b0), "r"(b1));
}
__device__ __forceinline__ void ldm_x4(uint32_t* r, uint32_t addr) {
    asm volatile("ldmatrix.sync.aligned.m8n8.x4.shared.b16 {%0,%1,%2,%3}, [%4];"
                 : "=r"(r[0]), "=r"(r[1]), "=r"(r[2]), "=r"(r[3]) : "r"(addr));
}
__device__ __forceinline__ void split_bf16(float v, __nv_bfloat16& h, __nv_bfloat16& l) {
    h = __float2bfloat16(v);
    l = __float2bfloat16(v - __bfloat162float(h));
}
__device__ __forceinline__ uint32_t pack_bf2(__nv_bfloat16 a, __nv_bfloat16 b) {
    uint16_t ua = *reinterpret_cast<uint16_t*>(&a);
    uint16_t ub = *reinterpret_cast<uint16_t*>(&b);
    return (uint32_t)ua | ((uint32_t)ub << 16);
}

// 4-stage pipeline, BK=16. Per-stage arrays: 128 rows x 16 bf16, 48B row stride.
#define SMSB16  48
#define ARRB16  6144
#define STGB16  24576
#define NSTAGE  4
#define LA_OFF  98304
#define LB_OFF  104448
#define GSMEM   110592
#define SCSM    98816
#define AVSM    98304

// ---- compute one 128x16 stage (bf16x3), accumulator-interleaved ----
#define COMPUTE16(stbase)                                                         \
    {                                                                             \
        uint32_t ahf[2][4], alf[2][4];                                            \
        int grp = lane >> 3, r8 = lane & 7;                                       \
        int mm = (grp & 1) * 8 + r8;                                              \
        int koff = (grp >> 1) * 8;                                                \
        _Pragma("unroll")                                                         \
        for (int mt = 0; mt < 2; mt++) {                                          \
            uint32_t ad = (stbase) + (wm * 32 + mt * 16 + mm) * SMSB16 + koff * 2;\
            ldm_x4(ahf[mt], ad);                                                  \
            ldm_x4(alf[mt], ad + ARRB16);                                         \
        }                                                                         \
        _Pragma("unroll")                                                         \
        for (int np = 0; np < 4; np++) {                                          \
            int nn = (grp >> 1) * 8 + r8;                                         \
            int koffb = (grp & 1) * 8;                                            \
            uint32_t bd = (stbase) + 2 * ARRB16 + (wn * 64 + np * 16 + nn) * SMSB16 + koffb * 2; \
            uint32_t bh[4], bl[4];                                                \
            ldm_x4(bh, bd);                                                       \
            ldm_x4(bl, bd + ARRB16);                                              \
            mma16(d[0][np * 2],     ahf[0], bh[0], bh[1]);                        \
            mma16(d[0][np * 2 + 1], ahf[0], bh[2], bh[3]);                        \
            mma16(d[1][np * 2],     ahf[1], bh[0], bh[1]);                        \
            mma16(d[1][np * 2 + 1], ahf[1], bh[2], bh[3]);                        \
            mma16(d[0][np * 2],     ahf[0], bl[0], bl[1]);                        \
            mma16(d[0][np * 2 + 1], ahf[0], bl[2], bl[3]);                        \
            mma16(d[1][np * 2],     ahf[1], bl[0], bl[1]);                        \
            mma16(d[1][np * 2 + 1], ahf[1], bl[2], bl[3]);                        \
            mma16(d[0][np * 2],     alf[0], bh[0], bh[1]);                        \
            mma16(d[0][np * 2 + 1], alf[0], bh[2], bh[3]);                        \
            mma16(d[1][np * 2],     alf[1], bh[0], bh[1]);                        \
            mma16(d[1][np * 2 + 1], alf[1], bh[2], bh[3]);                        \
        }                                                                         \
    }

#define ISSUE16(kt, aH, aL, bH, bL, LDA, LDB)                                     \
    {                                                                             \
        const int k0_ = (kt) << 4;                                                \
        const int buf_ = (kt) & (NSTAGE - 1);                                     \
        _Pragma("unroll")                                                         \
        for (int j = 0; j < 4; j++) {                                             \
            int e = tid + j * 256;                                                \
            int arr = e >> 8;                                                     \
            int i = e & 255;                                                      \
            int row = i >> 1;                                                     \
            int cg = (i & 1) << 3;                                                \
            const __nv_bfloat16* gp;                                              \
            if (arr == 0)      gp = (aH) + (size_t)row * (LDA) + k0_ + cg;        \
            else if (arr == 1) gp = (aL) + (size_t)row * (LDA) + k0_ + cg;        \
            else if (arr == 2) gp = (bH) + (size_t)row * (LDB) + k0_ + cg;        \
            else               gp = (bL) + (size_t)row * (LDB) + k0_ + cg;        \
            cp_async16(sb + buf_ * STGB16 + arr * ARRB16 + row * SMSB16 + cg * 2, gp); \
        }                                                                         \
        cp_commit();                                                              \
    }

#define MAINLOOP(nk, aH, aL, bH, bL, LDA, LDB)                                    \
    {                                                                             \
        ISSUE16(0, aH, aL, bH, bL, LDA, LDB);                                     \
        ISSUE16(1, aH, aL, bH, bL, LDA, LDB);                                     \
        ISSUE16(2, aH, aL, bH, bL, LDA, LDB);                                     \
        for (int kt = 0; kt < (nk); kt++) {                                       \
            cp_wait<2>();                                                         \
            __syncthreads();                                                      \
            const uint32_t st_ = sb + (kt & (NSTAGE - 1)) * STGB16;               \
            COMPUTE16(st_)                                                        \
            if (kt + 3 < (nk)) { ISSUE16(kt + 3, aH, aL, bH, bL, LDA, LDB); }     \
            else               { cp_commit(); }                                   \
        }                                                                         \
        cp_wait<0>();                                                             \
        __syncthreads();                                                          \
    }

// =================== batched GEMM with fused LoRA + residual ===================
// blockIdx.z selects the problem: W = Wh/Wl + z*wstride, C = Cz, lT = lT + z*MTOK*R,
// lB = lBz. All problems share A (ah/al) and shapes M,N,K.
__global__ __launch_bounds__(256, 2)
void gemm_tc(const __nv_bfloat16* __restrict__ Agh, const __nv_bfloat16* __restrict__ Agl,
             const __nv_bfloat16* __restrict__ Whb, const __nv_bfloat16* __restrict__ Wlb,
             size_t wstride,
             float* __restrict__ C0, float* __restrict__ C1, float* __restrict__ C2,
             int M, int N, int K,
             const float* __restrict__ lTb,
             const float* __restrict__ lB0, const float* __restrict__ lB1,
             const float* __restrict__ lB2, int accum)
{
    extern __shared__ char smc[];
    const int tid  = threadIdx.x;
    const int wid  = tid >> 5;
    const int lane = tid & 31;
    const int t4   = lane & 3;
    const int g    = lane >> 2;
    const int wm   = wid >> 1;
    const int wn   = wid & 1;
    const int bm   = blockIdx.y * 128;
    const int bn   = blockIdx.x * 128;
    const int z    = blockIdx.z;
    const uint32_t sb = smem_u32(smc);

    const __nv_bfloat16* Wgh = Whb + (size_t)z * wstride;
    const __nv_bfloat16* Wgl = Wlb + (size_t)z * wstride;
    float* C = (z == 0) ? C0 : ((z == 1) ? C1 : C2);
    const float* lT = lTb + (size_t)z * MTOK * RLORA;
    const float* lB = (z == 0) ? lB0 : ((z == 1) ? lB1 : lB2);

    __nv_bfloat16* la = (__nv_bfloat16*)(smc + LA_OFF);
    __nv_bfloat16* lb = (__nv_bfloat16*)(smc + LB_OFF);
    for (int i = tid; i < 2048; i += 256) {
        int row = i >> 4, r = i & 15;
        la[row * 24 + r] = __float2bfloat16(LORA_SCALE * lT[(size_t)(bm + row) * RLORA + r]);
        lb[row * 24 + r] = __float2bfloat16(lB[(size_t)r * N + bn + row]);
    }

    float d[2][8][4];
    #pragma unroll
    for (int mt = 0; mt < 2; mt++)
        #pragma unroll
        for (int nt = 0; nt < 8; nt++)
            #pragma unroll
            for (int j = 0; j < 4; j++) d[mt][nt][j] = 0.f;

    const __nv_bfloat16* aH = Agh + (size_t)bm * K;
    const __nv_bfloat16* aL = Agl + (size_t)bm * K;
    const __nv_bfloat16* bH = Wgh + (size_t)bn * K;
    const __nv_bfloat16* bL = Wgl + (size_t)bn * K;

    const int nk = K >> 4;
    MAINLOOP(nk, aH, aL, bH, bL, K, K)

    // LoRA tail (hi-only, K=16)
    {
        uint32_t a[2][4];
        #pragma unroll
        for (int mt = 0; mt < 2; mt++) {
            const char* pa = (const char*)la + (wm * 32 + mt * 16 + g) * 48 + t4 * 4;
            a[mt][0] = *(const uint32_t*)(pa);
            a[mt][1] = *(const uint32_t*)(pa + 8 * 48);
            a[mt][2] = *(const uint32_t*)(pa + 16);
            a[mt][3] = *(const uint32_t*)(pa + 8 * 48 + 16);
        }
        #pragma unroll
        for (int nt = 0; nt < 8; nt++) {
            const char* pb = (const char*)lb + (wn * 64 + nt * 8 + g) * 48 + t4 * 4;
            uint32_t b0 = *(const uint32_t*)(pb);
            uint32_t b1 = *(const uint32_t*)(pb + 16);
            #pragma unroll
            for (int mt = 0; mt < 2; mt++) mma16(d[mt][nt], a[mt], b0, b1);
        }
    }

    #pragma unroll
    for (int mt = 0; mt < 2; mt++) {
        const int r0 = bm + wm * 32 + mt * 16 + g;
        #pragma unroll
        for (int nt = 0; nt < 8; nt++) {
            const int c0 = bn + wn * 64 + nt * 8 + 2 * t4;
            float2 v0 = make_float2(d[mt][nt][0], d[mt][nt][1]);
            float2 v1 = make_float2(d[mt][nt][2], d[mt][nt][3]);
            float* p0 = C + (size_t)r0 * N + c0;
            float* p1 = C + (size_t)(r0 + 8) * N + c0;
            if (accum) {
                float2 o0 = *(const float2*)p0;
                float2 o1 = *(const float2*)p1;
                v0.x += o0.x; v0.y += o0.y;
                v1.x += o1.x; v1.y += o1.y;
            }
            *(float2*)p0 = v0;
            *(float2*)p1 = v1;
        }
    }
}

// =================== scores (skip masked tiles entirely) ===================
__global__ __launch_bounds__(256, 2)
void scores_mma(const __nv_bfloat16* __restrict__ Qh, const __nv_bfloat16* __restrict__ Ql,
                const __nv_bfloat16* __restrict__ Kh, const __nv_bfloat16* __restrict__ Kl,
                const int* __restrict__ mT, const int* __restrict__ mM,
                float* __restrict__ S_)
{
    extern __shared__ char smc[];
    const int tid  = threadIdx.x;
    const int wid  = tid >> 5;
    const int lane = tid & 31;
    const int t4   = lane & 3;
    const int g    = lane >> 2;
    const int wm   = wid >> 1;
    const int wn   = wid & 1;
    const int z    = blockIdx.z;
    const int bb   = z >> 4;
    const int hh   = z & 15;
    const int bm   = blockIdx.y * 128;
    const int bn   = blockIdx.x * 128;
    if (bn > bm) return;

    const uint32_t sb = smem_u32(smc);
    int* msk = (int*)(smc + NSTAGE * STGB16);

    const int* mask = (bb < 4) ? (mT + bb * SEQ) : (mM + (bb - 4) * SEQ);
    if (tid < 128) msk[tid] = mask[bn + tid];

    float* Sbase = S_ + (size_t)z * SEQ * SEQ;

    float d[2][8][4];
    #pragma unroll
    for (int mt = 0; mt < 2; mt++)
        #pragma unroll
        for (int nt = 0; nt < 8; nt++)
            #pragma unroll
            for (int j = 0; j < 4; j++) d[mt][nt][j] = 0.f;

    const __nv_bfloat16* aH = Qh + (size_t)(bb * SEQ + bm) * DMODEL + hh * HDIM;
    const __nv_bfloat16* aL = Ql + (size_t)(bb * SEQ + bm) * DMODEL + hh * HDIM;
    const __nv_bfloat16* bH = Kh + (size_t)(bb * SEQ + bn) * DMODEL + hh * HDIM;
    const __nv_bfloat16* bL = Kl + (size_t)(bb * SEQ + bn) * DMODEL + hh * HDIM;

    const int nk = HDIM >> 4;
    MAINLOOP(nk, aH, aL, bH, bL, DMODEL, DMODEL)

    #pragma unroll
    for (int mt = 0; mt < 2; mt++) {
        const int r0 = wm * 32 + mt * 16 + g;
        #pragma unroll
        for (int nt = 0; nt < 8; nt++) {
            const int c0 = wn * 64 + nt * 8 + 2 * t4;
            #pragma unroll
            for (int half = 0; half < 2; half++) {
                int r = r0 + half * 8;
                int sq = bm + r, sk0 = bn + c0;
                float va = d[mt][nt][half * 2], vb = d[mt][nt][half * 2 + 1];
                bool ok0 = (sk0 <= sq) && (msk[c0] > 0);
                bool ok1 = (sk0 + 1 <= sq) && (msk[c0 + 1] > 0);
                float2 out;
                out.x = va * SCALE_QK + (ok0 ? 0.f : -1e9f);
                out.y = vb * SCALE_QK + (ok1 ? 0.f : -1e9f);
                *(float2*)(Sbase + (size_t)sq * SEQ + sk0) = out;
            }
        }
    }
}

// =================== attnv (causal-truncated, packed bf16 stores) ===================
__global__ __launch_bounds__(256, 2)
void attnv_mma(const __nv_bfloat16* __restrict__ Ph, const __nv_bfloat16* __restrict__ Pl,
               const __nv_bfloat16* __restrict__ Vth, const __nv_bfloat16* __restrict__ Vtl,
               float* __restrict__ O,
               __nv_bfloat16* __restrict__ Oh, __nv_bfloat16* __restrict__ Ol)
{
    extern __shared__ char smc[];
    const int tid  = threadIdx.x;
    const int wid  = tid >> 5;
    const int lane = tid & 31;
    const int t4   = lane & 3;
    const int g    = lane >> 2;
    const int wm   = wid >> 1;
    const int wn   = wid & 1;
    const int z    = blockIdx.z;
    const int bb   = z >> 4;
    const int hh   = z & 15;
    const int bm   = blockIdx.y * 128;
    const uint32_t sb = smem_u32(smc);

    float d[2][8][4];
    #pragma unroll
    for (int mt = 0; mt < 2; mt++)
        #pragma unroll
        for (int nt = 0; nt < 8; nt++)
            #pragma unroll
            for (int j = 0; j < 4; j++) d[mt][nt][j] = 0.f;

    const __nv_bfloat16* aH = Ph + ((size_t)z * SEQ + bm) * SEQ;
    const __nv_bfloat16* aL = Pl + ((size_t)z * SEQ + bm) * SEQ;
    const __nv_bfloat16* bH = Vth + (size_t)z * HDIM * SEQ;
    const __nv_bfloat16* bL = Vtl + (size_t)z * HDIM * SEQ;

    const int nk = (bm >> 4) + 8;
    MAINLOOP(nk, aH, aL, bH, bL, SEQ, SEQ)

    #pragma unroll
    for (int mt = 0; mt < 2; mt++) {
        const int r0 = bm + wm * 32 + mt * 16 + g;
        #pragma unroll
        for (int nt = 0; nt < 8; nt++) {
            const int c0 = wn * 64 + nt * 8 + 2 * t4;
            #pragma unroll
            for (int half = 0; half < 2; half++) {
                int r = r0 + half * 8;
                size_t oidx = (size_t)(bb * SEQ + r) * DMODEL + hh * HDIM + c0;
                float va = d[mt][nt][half * 2], vb = d[mt][nt][half * 2 + 1];
                *(float2*)(O + oidx) = make_float2(va, vb);
                __nv_bfloat16 h0, l0, h1, l1;
                split_bf16(va, h0, l0);
                split_bf16(vb, h1, l1);
                *(uint32_t*)(Oh + oidx) = pack_bf2(h0, h1);
                *(uint32_t*)(Ol + oidx) = pack_bf2(l0, l1);
            }
        }
    }
}

// =================== fast LoRA-T ===================
#define LCH 512
template <int NM>
__global__ __launch_bounds__(256)
void lora_fast(const float* __restrict__ X, int K,
               const float* __restrict__ A0, const float* __restrict__ A1,
               const float* __restrict__ A2,
               float* __restrict__ T0, float* __restrict__ T1, float* __restrict__ T2)
{
    __shared__ float At[16 * 513];
    const int tid  = threadIdx.x;
    const int lane = tid & 31;
    const int warp = tid >> 5;
    const int row  = blockIdx.x * 8 + warp;

    const float* As[3] = {A0, A1, A2};
    float acc[NM][16];
    #pragma unroll
    for (int m = 0; m < NM; m++)
        #pragma unroll
        for (int r = 0; r < 16; r++) acc[m][r] = 0.f;

    for (int k0 = 0; k0 < K; k0 += LCH) {
        float xs[16];
        #pragma unroll
        for (int j = 0; j < 16; j++)
            xs[j] = X[(size_t)row * K + k0 + lane + 32 * j];
        #pragma unroll
        for (int m = 0; m < NM; m++) {
            __syncthreads();
            const float* Am = As[m];
            for (int i = tid; i < 16 * LCH; i += 256) {
                int k = i >> 4, r = i & 15;
                At[r * 513 + k] = Am[(size_t)(k0 + k) * RLORA + r];
            }
            __syncthreads();
            #pragma unroll
            for (int j = 0; j < 16; j++) {
                int k = lane + 32 * j;
                float xv = xs[j];
                #pragma unroll
                for (int r = 0; r < 16; r++)
                    acc[m][r] += xv * At[r * 513 + k];
            }
        }
    }

    float* Ts[3] = {T0, T1, T2};
    #pragma unroll
    for (int m = 0; m < NM; m++) {
        #pragma unroll
        for (int r = 0; r < 16; r++) {
            float v = acc[m][r];
            #pragma unroll
            for (int o = 16; o > 0; o >>= 1) v += __shfl_xor_sync(0xffffffffu, v, o);
            if (lane == 0) Ts[m][row * RLORA + r] = v;
        }
    }
}

// ---------------- weight transpose + split ----------------
__global__ void transpose_split(const float* __restrict__ W,
                                __nv_bfloat16* __restrict__ Wh, __nv_bfloat16* __restrict__ Wl,
                                int Kd, int Nd)
{
    __shared__ float tile[32][33];
    int n0 = blockIdx.x * 32, k0 = blockIdx.y * 32;
    int x = threadIdx.x, y = threadIdx.y;
    #pragma unroll
    for (int dy = 0; dy < 32; dy += 8)
        tile[y + dy][x] = W[(size_t)(k0 + y + dy) * Nd + n0 + x];
    __syncthreads();
    #pragma unroll
    for (int dy = 0; dy < 32; dy += 8) {
        float v = tile[x][y + dy];
        size_t o = (size_t)(n0 + y + dy) * Kd + k0 + x;
        __nv_bfloat16 h, l;
        split_bf16(v, h, l);
        Wh[o] = h; Wl[o] = l;
    }
}

// ---------------- V transpose + split per head ----------------
__global__ void vsplit_t(const float* __restrict__ V,
                         __nv_bfloat16* __restrict__ Vth, __nv_bfloat16* __restrict__ Vtl)
{
    __shared__ float tile[32][33];
    int tok0 = blockIdx.x * 32, d0 = blockIdx.y * 32;
    int x = threadIdx.x, y = threadIdx.y;
    #pragma unroll
    for (int dy = 0; dy < 32; dy += 8)
        tile[y + dy][x] = V[(size_t)(tok0 + y + dy) * DMODEL + d0 + x];
    __syncthreads();
    int bb = tok0 >> 9, s0 = tok0 & 511;
    int hh = d0 >> 7, dd0 = d0 & 127;
    size_t zb = ((size_t)(bb * NHEAD + hh)) * HDIM * SEQ;
    #pragma unroll
    for (int dy = 0; dy < 32; dy += 8) {
        float v = tile[x][y + dy];
        size_t oidx = zb + (size_t)(dd0 + y + dy) * SEQ + s0 + x;
        __nv_bfloat16 h, l;
        split_bf16(v, h, l);
        Vth[oidx] = h; Vtl[oidx] = l;
    }
}

// ---------------- fused embed + rmsnorm(ln1 layer0) ----------------
__global__ void embed_rms(const int* __restrict__ idT, const int* __restrict__ idM,
                          const float* __restrict__ E, const float* __restrict__ W,
                          float* __restrict__ H, float* __restrict__ X,
                          __nv_bfloat16* __restrict__ Xh, __nv_bfloat16* __restrict__ Xl)
{
    __shared__ float red[256];
    int t  = blockIdx.x;
    int bb = t >> 9;
    int s  = t & 511;
    int id = (bb < 4) ? idT[bb * SEQ + s] : idM[(bb - 4) * SEQ + s];
    const float* src = E + (size_t)id * DMODEL;
    int tid = threadIdx.x;
    float vals[8];
    float ss = 0.f;
    #pragma unroll
    for (int j = 0; j < 8; j++) {
        float v = src[tid + 256 * j];
        vals[j] = v;
        ss += v * v;
    }
    red[tid] = ss; __syncthreads();
    for (int o = 128; o > 0; o >>= 1) {
        if (tid < o) red[tid] += red[tid + o];
        __syncthreads();
    }
    float scale = rsqrtf(red[0] / (float)DMODEL + 1e-6f);
    size_t base = (size_t)t * DMODEL;
    #pragma unroll
    for (int j = 0; j < 8; j++) {
        int idx = tid + 256 * j;
        float v = vals[j];
        H[base + idx] = v;
        float xv = v * scale * W[idx];
        X[base + idx] = xv;
        __nv_bfloat16 hh, ll;
        split_bf16(xv, hh, ll);
        Xh[base + idx] = hh; Xl[base + idx] = ll;
    }
}

// ---------------- rmsnorm ----------------
__global__ void rmsnorm_kernel(const float* __restrict__ H, const float* __restrict__ W,
                               float* __restrict__ X,
                               __nv_bfloat16* __restrict__ Xh, __nv_bfloat16* __restrict__ Xl)
{
    __shared__ float red[256];
    int row = blockIdx.x;
    const float* h = H + (size_t)row * DMODEL;
    int tid = threadIdx.x;
    float vals[8];
    float s = 0.f;
    #pragma unroll
    for (int j = 0; j < 8; j++) {
        float v = h[tid + 256 * j];
        vals[j] = v;
        s += v * v;
    }
    red[tid] = s; __syncthreads();
    for (int o = 128; o > 0; o >>= 1) {
        if (tid < o) red[tid] += red[tid + o];
        __syncthreads();
    }
    float scale = rsqrtf(red[0] / (float)DMODEL + 1e-6f);
    size_t base = (size_t)row * DMODEL;
    #pragma unroll
    for (int j = 0; j < 8; j++) {
        int idx = tid + 256 * j;
        float v = vals[j] * scale * W[idx];
        X[base + idx] = v;
        __nv_bfloat16 hh, ll;
        split_bf16(v, hh, ll);
        Xh[base + idx] = hh; Xl[base + idx] = ll;
    }
}

// ---------------- RoPE ----------------
__global__ void rope_kernel(const float* __restrict__ Q, const float* __restrict__ Kt,
                            __nv_bfloat16* __restrict__ Qh, __nv_bfloat16* __restrict__ Ql,
                            __nv_bfloat16* __restrict__ Kh, __nv_bfloat16* __restrict__ Kl)
{
    int i = blockIdx.x * blockDim.x + threadIdx.x;
    if (i >= MTOK * NHEAD * 64) return;
    int d = i & 63;
    int h = (i >> 6) & 15;
    int t = i >> 10;
    int s = t & 511;
    float freq = expf(-(float)d * (logf(10000.f) / 64.f));
    float ang = (float)s * freq;
    float sn, cs;
    sincosf(ang, &sn, &cs);
    size_t b0 = (size_t)t * DMODEL + h * HDIM + d;
    __nv_bfloat16 hh, ll;
    float x1 = Q[b0], x2 = Q[b0 + 64];
    float r1 = x1 * cs - x2 * sn;
    float r2 = x1 * sn + x2 * cs;
    split_bf16(r1, hh, ll); Qh[b0] = hh;      Ql[b0] = ll;
    split_bf16(r2, hh, ll); Qh[b0 + 64] = hh; Ql[b0 + 64] = ll;
    x1 = Kt[b0]; x2 = Kt[b0 + 64];
    r1 = x1 * cs - x2 * sn;
    r2 = x1 * sn + x2 * cs;
    split_bf16(r1, hh, ll); Kh[b0] = hh;      Kl[b0] = ll;
    split_bf16(r2, hh, ll); Kh[b0 + 64] = hh; Kl[b0 + 64] = ll;
}

// ---------------- causal-aware row softmax ----------------
__global__ void softmax_kernel(const float* __restrict__ S_,
                               __nv_bfloat16* __restrict__ Ph, __nv_bfloat16* __restrict__ Pl)
{
    __shared__ float red[256];
    const float* p = S_ + (size_t)blockIdx.x * SEQ;
    int sq = blockIdx.x & (SEQ - 1);
    int t = threadIdx.x;
    bool ok0 = (t <= sq);
    bool ok1 = (t + 256 <= sq);
    float v0 = ok0 ? p[t] : -1e30f;
    float v1 = ok1 ? p[t + 256] : -1e30f;
    float m = fmaxf(v0, v1);
    red[t] = m; __syncthreads();
    for (int o = 128; o > 0; o >>= 1) {
        if (t < o) red[t] = fmaxf(red[t], red[t + o]);
        __syncthreads();
    }
    m = red[0]; __syncthreads();
    float e0 = ok0 ? expf(v0 - m) : 0.f;
    float e1 = ok1 ? expf(v1 - m) : 0.f;
    red[t] = e0 + e1; __syncthreads();
    for (int o = 128; o > 0; o >>= 1) {
        if (t < o) red[t] += red[t + o];
        __syncthreads();
    }
    float inv = 1.f / red[0];
    size_t base = (size_t)blockIdx.x * SEQ;
    __nv_bfloat16 hh, ll;
    split_bf16(e0 * inv, hh, ll); Ph[base + t] = hh;       Pl[base + t] = ll;
    split_bf16(e1 * inv, hh, ll); Ph[base + t + 256] = hh; Pl[base + t + 256] = ll;
}

// ---------------- swiglu ----------------
__global__ void swiglu_kernel(float* __restrict__ G, const float* __restrict__ U,
                              __nv_bfloat16* __restrict__ Gh, __nv_bfloat16* __restrict__ Gl)
{
    size_t i = (size_t)blockIdx.x * blockDim.x + threadIdx.x;
    if (i >= (size_t)MTOK * FFDIM) return;
    float g = G[i];
    float sig = 1.f / (1.f + expf(-g));
    float v = g * sig * U[i];
    G[i] = v;
    __nv_bfloat16 hh, ll;
    split_bf16(v, hh, ll);
    Gh[i] = hh; Gl[i] = ll;
}

// ---------------- reps extraction + L2 normalize ----------------
__global__ void reps_kernel(const float* __restrict__ X, const int* __restrict__ mT,
                            const int* __restrict__ mM, float* __restrict__ R_)
{
    __shared__ int ired[256];
    __shared__ float fred[256];
    __shared__ int sidx;
    int bb = blockIdx.x;
    const int* mask = (bb < 4) ? mT : mM;
    int b = bb & 3;
    int t = threadIdx.x;
    int s = 0;
    for (int j = t; j < SEQ; j += 256) s += mask[b * SEQ + j];
    ired[t] = s; __syncthreads();
    for (int o = 128; o > 0; o >>= 1) {
        if (t < o) ired[t] += ired[t + o];
        __syncthreads();
    }
    if (t == 0) {
        int last = mask[0 * SEQ + 511] + mask[1 * SEQ + 511] +
                   mask[2 * SEQ + 511] + mask[3 * SEQ + 511];
        sidx = (last == BATCH) ? (SEQ - 1) : (ired[0] - 1);
    }
    __syncthreads();
    const float* row = X + (size_t)(bb * SEQ + sidx) * DMODEL;
    float ss = 0.f;
    for (int j = t; j < DMODEL; j += 256) { float v = row[j]; ss += v * v; }
    fred[t] = ss; __syncthreads();
    for (int o = 128; o > 0; o >>= 1) {
        if (t < o) fred[t] += fred[t + o];
        __syncthreads();
    }
    float inv = 1.f / sqrtf(fred[0]);
    for (int j = t; j < DMODEL; j += 256) R_[bb * DMODEL + j] = row[j] * inv;
}

// ---------------- contrastive loss ----------------
__global__ void loss_kernel(const float* __restrict__ R_, float* __restrict__ out)
{
    __shared__ float sims[16];
    int tid = threadIdx.x;
    int warp = tid >> 5, lane = tid & 31;
    for (int p = warp; p < 16; p += 8) {
        int i = p >> 2, j = p & 3;
        const float* a = R_ + i * DMODEL;
        const float* bR = R_ + (4 + j) * DMODEL;
        float d = 0.f;
        for (int k2 = lane; k2 < DMODEL; k2 += 32) d += a[k2] * bR[k2];
        #pragma unroll
        for (int o = 16; o > 0; o >>= 1) d += __shfl_xor_sync(0xffffffff, d, o);
        if (lane == 0) sims[p] = d * 20.f;
    }
    __syncthreads();
    if (tid == 0) {
        float loss = 0.f;
        for (int i = 0; i < 4; i++) {
            float m = -1e30f;
            for (int j = 0; j < 4; j++) m = fmaxf(m, sims[i * 4 + j]);
            float sum = 0.f;
            for (int j = 0; j < 4; j++) sum += expf(sims[i * 4 + j] - m);
            loss += (logf(sum) + m) - sims[i * 4 + i];
        }
        out[0] = loss * 0.25f;
    }
}

// ---------------- host driver ----------------
static void* symaddr_raw(const void* sym)
{
    void* p = nullptr;
    cudaGetSymbolAddress(&p, sym);
    return p;
}

extern "C" void kernel_launch(void* const* d_in, const int* in_sizes, int n_in,
                              void* d_out, int out_size)
{
    const int*   idT = (const int*)d_in[0];
    const int*   mT  = (const int*)d_in[1];
    const int*   idM = (const int*)d_in[2];
    const int*   mM  = (const int*)d_in[3];
    const float* emb = (const float*)d_in[4];
    const float* ln1 = (const float*)d_in[5];
    const float* ln2 = (const float*)d_in[6];
    const float* lnf = (const float*)d_in[7];
    const float* Wq = (const float*)d_in[8],  *Aq = (const float*)d_in[9],  *Bq = (const float*)d_in[10];
    const float* Wk = (const float*)d_in[11], *Ak = (const float*)d_in[12], *Bk = (const float*)d_in[13];
    const float* Wv = (const float*)d_in[14], *Av = (const float*)d_in[15], *Bv = (const float*)d_in[16];
    const float* Wo = (const float*)d_in[17], *Ao = (const float*)d_in[18], *Bo = (const float*)d_in[19];
    const float* Wg = (const float*)d_in[20], *Ag = (const float*)d_in[21], *Bg = (const float*)d_in[22];
    const float* Wu = (const float*)d_in[23], *Au = (const float*)d_in[24], *Bu = (const float*)d_in[25];
    const float* Wd = (const float*)d_in[26], *Ad = (const float*)d_in[27], *Bd = (const float*)d_in[28];

    float* h  = (float*)symaddr_raw(g_h);
    float* x  = (float*)symaddr_raw(g_x);
    float* q  = (float*)symaddr_raw(g_q);
    float* k  = (float*)symaddr_raw(g_k);
    float* v  = (float*)symaddr_raw(g_v);
    float* o  = (float*)symaddr_raw(g_o);
    float* sc = (float*)symaddr_raw(g_sc);
    float* gg = (float*)symaddr_raw(g_gate);
    float* uu = (float*)symaddr_raw(g_up);
    float* t0 = (float*)symaddr_raw(g_t);
    float* t1 = t0 + MTOK * RLORA;
    float* t2 = t0 + 2 * MTOK * RLORA;
    float* rp = (float*)symaddr_raw(g_reps);
    __nv_bfloat16* ah  = (__nv_bfloat16*)symaddr_raw(g_ah);
    __nv_bfloat16* al  = (__nv_bfloat16*)symaddr_raw(g_al);
    __nv_bfloat16* wh  = (__nv_bfloat16*)symaddr_raw(g_wh);
    __nv_bfloat16* wl  = (__nv_bfloat16*)symaddr_raw(g_wl);
    __nv_bfloat16* qh  = (__nv_bfloat16*)symaddr_raw(g_qh);
    __nv_bfloat16* ql  = (__nv_bfloat16*)symaddr_raw(g_ql);
    __nv_bfloat16* kh  = (__nv_bfloat16*)symaddr_raw(g_kh);
    __nv_bfloat16* kl  = (__nv_bfloat16*)symaddr_raw(g_kl);
    __nv_bfloat16* ph  = (__nv_bfloat16*)symaddr_raw(g_ph);
    __nv_bfloat16* pl  = (__nv_bfloat16*)symaddr_raw(g_pl);
    __nv_bfloat16* vth = (__nv_bfloat16*)symaddr_raw(g_vth);
    __nv_bfloat16* vtl = (__nv_bfloat16*)symaddr_raw(g_vtl);

    cudaFuncSetAttribute(gemm_tc,    cudaFuncAttributeMaxDynamicSharedMemorySize, GSMEM);
    cudaFuncSetAttribute(scores_mma, cudaFuncAttributeMaxDynamicSharedMemorySize, SCSM);
    cudaFuncSetAttribute(attnv_mma,  cudaFuncAttributeMaxDynamicSharedMemorySize, AVSM);

    const size_t DD = (size_t)DMODEL * DMODEL;
    const size_t DF = (size_t)DMODEL * FFDIM;
    const size_t LSTR = 4 * DD + 3 * DF;
    const dim3 tD(DMODEL / 32, DMODEL / 32), tB(32, 8);
    const dim3 tF(FFDIM / 32, DMODEL / 32);
    const dim3 tFd(DMODEL / 32, FFDIM / 32);
    const dim3 gD1(DMODEL / 128, MTOK / 128, 1);
    const dim3 gD3(DMODEL / 128, MTOK / 128, 3);
    const dim3 gF2(FFDIM / 128, MTOK / 128, 2);

    // ---- prologue: weight transposes for layer 0 first, then start compute ----
    transpose_split<<<tD, tB>>>(Wq, wh, wl, DMODEL, DMODEL);
    transpose_split<<<tD, tB>>>(Wk, wh + DD, wl + DD, DMODEL, DMODEL);
    transpose_split<<<tD, tB>>>(Wv, wh + 2 * DD, wl + 2 * DD, DMODEL, DMODEL);
    embed_rms<<<MTOK, 256>>>(idT, idM, emb, ln1, h, x, ah, al);
    lora_fast<3><<<MTOK / 8, 256>>>(x, DMODEL, Aq, Ak, Av, t0, t1, t2);
    // batched q/k/v GEMM
    gemm_tc<<<gD3, 256, GSMEM>>>(ah, al, wh, wl, DD, q, k, v,
                                 MTOK, DMODEL, DMODEL, t0, Bq, Bk, Bv, 0);

    // remaining transposes
    transpose_split<<<tD, tB>>>(Wo, wh + 3 * DD, wl + 3 * DD, DMODEL, DMODEL);
    transpose_split<<<tF, tB>>>(Wg, wh + 4 * DD, wl + 4 * DD, DMODEL, FFDIM);
    transpose_split<<<tF, tB>>>(Wu, wh + 4 * DD + DF, wl + 4 * DD + DF, DMODEL, FFDIM);
    transpose_split<<<tFd, tB>>>(Wd, wh + 4 * DD + 2 * DF, wl + 4 * DD + 2 * DF, FFDIM, DMODEL);
    for (int l = 1; l < LAYERS; l++) {
        size_t off = (size_t)l * LSTR;
        transpose_split<<<tD, tB>>>(Wq + l * DD, wh + off,          wl + off,          DMODEL, DMODEL);
        transpose_split<<<tD, tB>>>(Wk + l * DD, wh + off + DD,     wl + off + DD,     DMODEL, DMODEL);
        transpose_split<<<tD, tB>>>(Wv + l * DD, wh + off + 2 * DD, wl + off + 2 * DD, DMODEL, DMODEL);
        transpose_split<<<tD, tB>>>(Wo + l * DD, wh + off + 3 * DD, wl + off + 3 * DD, DMODEL, DMODEL);
        transpose_split<<<tF, tB>>>(Wg + l * DF, wh + off + 4 * DD, wl + off + 4 * DD, DMODEL, FFDIM);
        transpose_split<<<tF, tB>>>(Wu + l * DF, wh + off + 4 * DD + DF, wl + off + 4 * DD + DF, DMODEL, FFDIM);
        transpose_split<<<tFd, tB>>>(Wd + l * DF, wh + off + 4 * DD + 2 * DF, wl + off + 4 * DD + 2 * DF, FFDIM, DMODEL);
    }

    for (int l = 0; l < LAYERS; l++) {
        size_t off = (size_t)l * LSTR;
        const __nv_bfloat16 *Wl_h = wh + off, *Wl_l = wl + off;
        const float* Bq_l = Bq + (size_t)l * RLORA * DMODEL;
        const float* Bk_l = Bk + (size_t)l * RLORA * DMODEL;
        const float* Bv_l = Bv + (size_t)l * RLORA * DMODEL;
        const float* Bo_l = Bo + (size_t)l * RLORA * DMODEL;
        const float* Bg_l = Bg + (size_t)l * RLORA * FFDIM;
        const float* Bu_l = Bu + (size_t)l * RLORA * FFDIM;
        const float* Bd_l = Bd + (size_t)l * RLORA * DMODEL;

        if (l > 0) {
            rmsnorm_kernel<<<MTOK, 256>>>(h, ln1 + l * DMODEL, x, ah, al);
            lora_fast<3><<<MTOK / 8, 256>>>(x, DMODEL, Aq + l * DMODEL * RLORA,
                                            Ak + l * DMODEL * RLORA, Av + l * DMODEL * RLORA,
                                            t0, t1, t2);
            gemm_tc<<<gD3, 256, GSMEM>>>(ah, al, Wl_h, Wl_l, DD, q, k, v,
                                         MTOK, DMODEL, DMODEL, t0, Bq_l, Bk_l, Bv_l, 0);
        }

        rope_kernel<<<(MTOK * NHEAD * 64 + 255) / 256, 256>>>(q, k, qh, ql, kh, kl);
        vsplit_t<<<dim3(MTOK / 32, DMODEL / 32), tB>>>(v, vth, vtl);

        scores_mma<<<dim3(4, 4, BB * NHEAD), 256, SCSM>>>(qh, ql, kh, kl, mT, mM, sc);
        softmax_kernel<<<BB * NHEAD * SEQ, 256>>>(sc, ph, pl);
        attnv_mma<<<dim3(1, 4, BB * NHEAD), 256, AVSM>>>(ph, pl, vth, vtl, o, ah, al);

        lora_fast<1><<<MTOK / 8, 256>>>(o, DMODEL, Ao + (size_t)l * DMODEL * RLORA,
                                        nullptr, nullptr, t0, nullptr, nullptr);
        gemm_tc<<<gD1, 256, GSMEM>>>(ah, al, Wl_h + 3 * DD, Wl_l + 3 * DD, 0, h, nullptr, nullptr,
                                     MTOK, DMODEL, DMODEL, t0, Bo_l, nullptr, nullptr, 1);

        rmsnorm_kernel<<<MTOK, 256>>>(h, ln2 + l * DMODEL, x, ah, al);
        lora_fast<2><<<MTOK / 8, 256>>>(x, DMODEL, Ag + (size_t)l * DMODEL * RLORA,
                                        Au + (size_t)l * DMODEL * RLORA, nullptr,
                                        t0, t1, nullptr);
        // batched g/u GEMM (weights contiguous: Wg at 4DD, Wu at 4DD+DF -> stride DF)
        gemm_tc<<<gF2, 256, GSMEM>>>(ah, al, Wl_h + 4 * DD, Wl_l + 4 * DD, DF, gg, uu, nullptr,
                                     MTOK, FFDIM, DMODEL, t0, Bg_l, Bu_l, nullptr, 0);

        swiglu_kernel<<<(int)(((size_t)MTOK * FFDIM + 255) / 256), 256>>>(gg, uu, ah, al);

        lora_fast<1><<<MTOK / 8, 256>>>(gg, FFDIM, Ad + (size_t)l * FFDIM * RLORA,
                                        nullptr, nullptr, t0, nullptr, nullptr);
        gemm_tc<<<gD1, 256, GSMEM>>>(ah, al, Wl_h + 4 * DD + 2 * DF, Wl_l + 4 * DD + 2 * DF, 0,
                                     h, nullptr, nullptr,
                                     MTOK, DMODEL, FFDIM, t0, Bd_l, nullptr, nullptr, 1);
    }

    rmsnorm_kernel<<<MTOK, 256>>>(h, lnf, x, ah, al);
    reps_kernel<<<BB, 256>>>(x, mT, mM, rp);
    loss_kernel<<<1, 256>>>(rp, (float*)d_out);
}

// round 16
// speedup vs baseline: 2.7868x; 1.0244x over previous
#include <cuda_runtime.h>
#include <cuda_bf16.h>
#include <math.h>
#include <stdint.h>

// Problem constants
#define LAYERS 2
#define DMODEL 2048
#define NHEAD  16
#define HDIM   128
#define FFDIM  5632
#define RLORA  16
#define BATCH  4
#define SEQ    512
#define BB     8
#define MTOK   (BB*SEQ)
#define LORA_SCALE 1.4f
#define SCALE_QK 0.08838834764831845f

// ---------------- scratch ----------------
__device__ float g_h   [MTOK * DMODEL];
__device__ float g_x   [MTOK * DMODEL];
__device__ float g_q   [MTOK * DMODEL];
__device__ float g_k   [MTOK * DMODEL];
__device__ float g_v   [MTOK * DMODEL];
__device__ float g_o   [MTOK * DMODEL];
__device__ float g_sc  [BB * NHEAD * SEQ * SEQ];
__device__ float g_gate[MTOK * FFDIM];
__device__ float g_up  [MTOK * FFDIM];
__device__ float g_t   [3 * MTOK * RLORA];
__device__ float g_reps[BB * DMODEL];
__device__ __nv_bfloat16 g_ah[MTOK * FFDIM];
__device__ __nv_bfloat16 g_al[MTOK * FFDIM];
__device__ __nv_bfloat16 g_wh[2 * (4 * DMODEL * DMODEL + 3 * DMODEL * FFDIM)];
__device__ __nv_bfloat16 g_wl[2 * (4 * DMODEL * DMODEL + 3 * DMODEL * FFDIM)];
__device__ __nv_bfloat16 g_qh[MTOK * DMODEL];
__device__ __nv_bfloat16 g_ql[MTOK * DMODEL];
__device__ __nv_bfloat16 g_kh[MTOK * DMODEL];
__device__ __nv_bfloat16 g_kl[MTOK * DMODEL];
__device__ __nv_bfloat16 g_ph[BB * NHEAD * SEQ * SEQ];
__device__ __nv_bfloat16 g_pl[BB * NHEAD * SEQ * SEQ];
__device__ __nv_bfloat16 g_vth[MTOK * DMODEL];
__device__ __nv_bfloat16 g_vtl[MTOK * DMODEL];

// =================== helpers ===================
__device__ __forceinline__ uint32_t smem_u32(const void* p) {
    uint32_t a;
    asm("{ .reg .u64 t; cvta.to.shared.u64 t, %1; cvt.u32.u64 %0, t; }" : "=r"(a) : "l"(p));
    return a;
}
__device__ __forceinline__ void cp_async16(uint32_t saddr, const void* gptr) {
    asm volatile("cp.async.cg.shared.global [%0], [%1], 16;" :: "r"(saddr), "l"(gptr));
}
__device__ __forceinline__ void cp_commit() { asm volatile("cp.async.commit_group;"); }
template <int NWAIT>
__device__ __forceinline__ void cp_wait() {
    asm volatile("cp.async.wait_group %0;" :: "n"(NWAIT));
}
__device__ __forceinline__ void mma16(float* d, const uint32_t* a, uint32_t b0, uint32_t b1) {
    asm volatile(
        "mma.sync.aligned.m16n8k16.row.col.f32.bf16.bf16.f32 "
        "{%0,%1,%2,%3}, {%4,%5,%6,%7}, {%8,%9}, {%0,%1,%2,%3};"
        : "+f"(d[0]), "+f"(d[1]), "+f"(d[2]), "+f"(d[3])
        : "r"(a[0]), "r"(a[1]), "r"(a[2]), "r"(a[3]), "r"(b0), "r"(b1));
}
__device__ __forceinline__ void ldm_x4(uint32_t* r, uint32_t addr) {
    asm volatile("ldmatrix.sync.aligned.m8n8.x4.shared.b16 {%0,%1,%2,%3}, [%4];"
                 : "=r"(r[0]), "=r"(r[1]), "=r"(r[2]), "=r"(r[3]) : "r"(addr));
}
__device__ __forceinline__ void split_bf16(float v, __nv_bfloat16& h, __nv_bfloat16& l) {
    h = __float2bfloat16(v);
    l = __float2bfloat16(v - __bfloat162float(h));
}
__device__ __forceinline__ uint32_t pack_bf2(__nv_bfloat16 a, __nv_bfloat16 b) {
    uint16_t ua = *reinterpret_cast<uint16_t*>(&a);
    uint16_t ub = *reinterpret_cast<uint16_t*>(&b);
    return (uint32_t)ua | ((uint32_t)ub << 16);
}

// 4-stage pipeline, BK=16. Per-stage arrays: 128 rows x 16 bf16, 48B row stride.
#define SMSB16  48
#define ARRB16  6144
#define STGB16  24576
#define NSTAGE  4
#define LA_OFF  98304
#define LB_OFF  104448
#define GSMEM   110592
#define SCSM    98816
#define AVSM    98304

// ---- compute one 128x16 stage (bf16x3), accumulator-interleaved ----
#define COMPUTE16(stbase)                                                         \
    {                                                                             \
        uint32_t ahf[2][4], alf[2][4];                                            \
        int grp = lane >> 3, r8 = lane & 7;                                       \
        int mm = (grp & 1) * 8 + r8;                                              \
        int koff = (grp >> 1) * 8;                                                \
        _Pragma("unroll")                                                         \
        for (int mt = 0; mt < 2; mt++) {                                          \
            uint32_t ad = (stbase) + (wm * 32 + mt * 16 + mm) * SMSB16 + koff * 2;\
            ldm_x4(ahf[mt], ad);                                                  \
            ldm_x4(alf[mt], ad + ARRB16);                                         \
        }                                                                         \
        _Pragma("unroll")                                                         \
        for (int np = 0; np < 4; np++) {                                          \
            int nn = (grp >> 1) * 8 + r8;                                         \
            int koffb = (grp & 1) * 8;                                            \
            uint32_t bd = (stbase) + 2 * ARRB16 + (wn * 64 + np * 16 + nn) * SMSB16 + koffb * 2; \
            uint32_t bh[4], bl[4];                                                \
            ldm_x4(bh, bd);                                                       \
            ldm_x4(bl, bd + ARRB16);                                              \
            mma16(d[0][np * 2],     ahf[0], bh[0], bh[1]);                        \
            mma16(d[0][np * 2 + 1], ahf[0], bh[2], bh[3]);                        \
            mma16(d[1][np * 2],     ahf[1], bh[0], bh[1]);                        \
            mma16(d[1][np * 2 + 1], ahf[1], bh[2], bh[3]);                        \
            mma16(d[0][np * 2],     ahf[0], bl[0], bl[1]);                        \
            mma16(d[0][np * 2 + 1], ahf[0], bl[2], bl[3]);                        \
            mma16(d[1][np * 2],     ahf[1], bl[0], bl[1]);                        \
            mma16(d[1][np * 2 + 1], ahf[1], bl[2], bl[3]);                        \
            mma16(d[0][np * 2],     alf[0], bh[0], bh[1]);                        \
            mma16(d[0][np * 2 + 1], alf[0], bh[2], bh[3]);                        \
            mma16(d[1][np * 2],     alf[1], bh[0], bh[1]);                        \
            mma16(d[1][np * 2 + 1], alf[1], bh[2], bh[3]);                        \
        }                                                                         \
    }

#define ISSUE16(kt, aH, aL, bH, bL, LDA, LDB)                                     \
    {                                                                             \
        const int k0_ = (kt) << 4;                                                \
        const int buf_ = (kt) & (NSTAGE - 1);                                     \
        _Pragma("unroll")                                                         \
        for (int j = 0; j < 4; j++) {                                             \
            int e = tid + j * 256;                                                \
            int arr = e >> 8;                                                     \
            int i = e & 255;                                                      \
            int row = i >> 1;                                                     \
            int cg = (i & 1) << 3;                                                \
            const __nv_bfloat16* gp;                                              \
            if (arr == 0)      gp = (aH) + (size_t)row * (LDA) + k0_ + cg;        \
            else if (arr == 1) gp = (aL) + (size_t)row * (LDA) + k0_ + cg;        \
            else if (arr == 2) gp = (bH) + (size_t)row * (LDB) + k0_ + cg;        \
            else               gp = (bL) + (size_t)row * (LDB) + k0_ + cg;        \
            cp_async16(sb + buf_ * STGB16 + arr * ARRB16 + row * SMSB16 + cg * 2, gp); \
        }                                                                         \
        cp_commit();                                                              \
    }

#define MAINLOOP(nk, aH, aL, bH, bL, LDA, LDB)                                    \
    {                                                                             \
        ISSUE16(0, aH, aL, bH, bL, LDA, LDB);                                     \
        ISSUE16(1, aH, aL, bH, bL, LDA, LDB);                                     \
        ISSUE16(2, aH, aL, bH, bL, LDA, LDB);                                     \
        for (int kt = 0; kt < (nk); kt++) {                                       \
            cp_wait<2>();                                                         \
            __syncthreads();                                                      \
            const uint32_t st_ = sb + (kt & (NSTAGE - 1)) * STGB16;               \
            COMPUTE16(st_)                                                        \
            if (kt + 3 < (nk)) { ISSUE16(kt + 3, aH, aL, bH, bL, LDA, LDB); }     \
            else               { cp_commit(); }                                   \
        }                                                                         \
        cp_wait<0>();                                                             \
        __syncthreads();                                                          \
    }

// =================== batched GEMM with fused LoRA + residual ===================
__global__ __launch_bounds__(256, 2)
void gemm_tc(const __nv_bfloat16* __restrict__ Agh, const __nv_bfloat16* __restrict__ Agl,
             const __nv_bfloat16* __restrict__ Whb, const __nv_bfloat16* __restrict__ Wlb,
             size_t wstride,
             float* __restrict__ C0, float* __restrict__ C1, float* __restrict__ C2,
             int M, int N, int K,
             const float* __restrict__ lTb,
             const float* __restrict__ lB0, const float* __restrict__ lB1,
             const float* __restrict__ lB2, int accum)
{
    extern __shared__ char smc[];
    const int tid  = threadIdx.x;
    const int wid  = tid >> 5;
    const int lane = tid & 31;
    const int t4   = lane & 3;
    const int g    = lane >> 2;
    const int wm   = wid >> 1;
    const int wn   = wid & 1;
    const int bm   = blockIdx.y * 128;
    const int bn   = blockIdx.x * 128;
    const int z    = blockIdx.z;
    const uint32_t sb = smem_u32(smc);

    const __nv_bfloat16* Wgh = Whb + (size_t)z * wstride;
    const __nv_bfloat16* Wgl = Wlb + (size_t)z * wstride;
    float* C = (z == 0) ? C0 : ((z == 1) ? C1 : C2);
    const float* lT = lTb + (size_t)z * MTOK * RLORA;
    const float* lB = (z == 0) ? lB0 : ((z == 1) ? lB1 : lB2);

    __nv_bfloat16* la = (__nv_bfloat16*)(smc + LA_OFF);
    __nv_bfloat16* lb = (__nv_bfloat16*)(smc + LB_OFF);
    for (int i = tid; i < 2048; i += 256) {
        int row = i >> 4, r = i & 15;
        la[row * 24 + r] = __float2bfloat16(LORA_SCALE * lT[(size_t)(bm + row) * RLORA + r]);
        lb[row * 24 + r] = __float2bfloat16(lB[(size_t)r * N + bn + row]);
    }

    float d[2][8][4];
    #pragma unroll
    for (int mt = 0; mt < 2; mt++)
        #pragma unroll
        for (int nt = 0; nt < 8; nt++)
            #pragma unroll
            for (int j = 0; j < 4; j++) d[mt][nt][j] = 0.f;

    const __nv_bfloat16* aH = Agh + (size_t)bm * K;
    const __nv_bfloat16* aL = Agl + (size_t)bm * K;
    const __nv_bfloat16* bH = Wgh + (size_t)bn * K;
    const __nv_bfloat16* bL = Wgl + (size_t)bn * K;

    const int nk = K >> 4;
    MAINLOOP(nk, aH, aL, bH, bL, K, K)

    // LoRA tail (hi-only, K=16)
    {
        uint32_t a[2][4];
        #pragma unroll
        for (int mt = 0; mt < 2; mt++) {
            const char* pa = (const char*)la + (wm * 32 + mt * 16 + g) * 48 + t4 * 4;
            a[mt][0] = *(const uint32_t*)(pa);
            a[mt][1] = *(const uint32_t*)(pa + 8 * 48);
            a[mt][2] = *(const uint32_t*)(pa + 16);
            a[mt][3] = *(const uint32_t*)(pa + 8 * 48 + 16);
        }
        #pragma unroll
        for (int nt = 0; nt < 8; nt++) {
            const char* pb = (const char*)lb + (wn * 64 + nt * 8 + g) * 48 + t4 * 4;
            uint32_t b0 = *(const uint32_t*)(pb);
            uint32_t b1 = *(const uint32_t*)(pb + 16);
            #pragma unroll
            for (int mt = 0; mt < 2; mt++) mma16(d[mt][nt], a[mt], b0, b1);
        }
    }

    #pragma unroll
    for (int mt = 0; mt < 2; mt++) {
        const int r0 = bm + wm * 32 + mt * 16 + g;
        #pragma unroll
        for (int nt = 0; nt < 8; nt++) {
            const int c0 = bn + wn * 64 + nt * 8 + 2 * t4;
            float2 v0 = make_float2(d[mt][nt][0], d[mt][nt][1]);
            float2 v1 = make_float2(d[mt][nt][2], d[mt][nt][3]);
            float* p0 = C + (size_t)r0 * N + c0;
            float* p1 = C + (size_t)(r0 + 8) * N + c0;
            if (accum) {
                float2 o0 = *(const float2*)p0;
                float2 o1 = *(const float2*)p1;
                v0.x += o0.x; v0.y += o0.y;
                v1.x += o1.x; v1.y += o1.y;
            }
            *(float2*)p0 = v0;
            *(float2*)p1 = v1;
        }
    }
}

// =================== scores (skip masked tiles entirely) ===================
__global__ __launch_bounds__(256, 2)
void scores_mma(const __nv_bfloat16* __restrict__ Qh, const __nv_bfloat16* __restrict__ Ql,
                const __nv_bfloat16* __restrict__ Kh, const __nv_bfloat16* __restrict__ Kl,
                const int* __restrict__ mT, const int* __restrict__ mM,
                float* __restrict__ S_)
{
    extern __shared__ char smc[];
    const int tid  = threadIdx.x;
    const int wid  = tid >> 5;
    const int lane = tid & 31;
    const int t4   = lane & 3;
    const int g    = lane >> 2;
    const int wm   = wid >> 1;
    const int wn   = wid & 1;
    const int z    = blockIdx.z;
    const int bb   = z >> 4;
    const int hh   = z & 15;
    const int bm   = blockIdx.y * 128;
    const int bn   = blockIdx.x * 128;
    if (bn > bm) return;

    const uint32_t sb = smem_u32(smc);
    int* msk = (int*)(smc + NSTAGE * STGB16);

    const int* mask = (bb < 4) ? (mT + bb * SEQ) : (mM + (bb - 4) * SEQ);
    if (tid < 128) msk[tid] = mask[bn + tid];

    float* Sbase = S_ + (size_t)z * SEQ * SEQ;

    float d[2][8][4];
    #pragma unroll
    for (int mt = 0; mt < 2; mt++)
        #pragma unroll
        for (int nt = 0; nt < 8; nt++)
            #pragma unroll
            for (int j = 0; j < 4; j++) d[mt][nt][j] = 0.f;

    const __nv_bfloat16* aH = Qh + (size_t)(bb * SEQ + bm) * DMODEL + hh * HDIM;
    const __nv_bfloat16* aL = Ql + (size_t)(bb * SEQ + bm) * DMODEL + hh * HDIM;
    const __nv_bfloat16* bH = Kh + (size_t)(bb * SEQ + bn) * DMODEL + hh * HDIM;
    const __nv_bfloat16* bL = Kl + (size_t)(bb * SEQ + bn) * DMODEL + hh * HDIM;

    const int nk = HDIM >> 4;
    MAINLOOP(nk, aH, aL, bH, bL, DMODEL, DMODEL)

    #pragma unroll
    for (int mt = 0; mt < 2; mt++) {
        const int r0 = wm * 32 + mt * 16 + g;
        #pragma unroll
        for (int nt = 0; nt < 8; nt++) {
            const int c0 = wn * 64 + nt * 8 + 2 * t4;
            #pragma unroll
            for (int half = 0; half < 2; half++) {
                int r = r0 + half * 8;
                int sq = bm + r, sk0 = bn + c0;
                float va = d[mt][nt][half * 2], vb = d[mt][nt][half * 2 + 1];
                bool ok0 = (sk0 <= sq) && (msk[c0] > 0);
                bool ok1 = (sk0 + 1 <= sq) && (msk[c0 + 1] > 0);
                float2 out;
                out.x = va * SCALE_QK + (ok0 ? 0.f : -1e9f);
                out.y = vb * SCALE_QK + (ok1 ? 0.f : -1e9f);
                *(float2*)(Sbase + (size_t)sq * SEQ + sk0) = out;
            }
        }
    }
}

// =================== attnv (causal-truncated, longest tiles first) ===================
__global__ __launch_bounds__(256, 2)
void attnv_mma(const __nv_bfloat16* __restrict__ Ph, const __nv_bfloat16* __restrict__ Pl,
               const __nv_bfloat16* __restrict__ Vth, const __nv_bfloat16* __restrict__ Vtl,
               float* __restrict__ O,
               __nv_bfloat16* __restrict__ Oh, __nv_bfloat16* __restrict__ Ol)
{
    extern __shared__ char smc[];
    const int tid  = threadIdx.x;
    const int wid  = tid >> 5;
    const int lane = tid & 31;
    const int t4   = lane & 3;
    const int g    = lane >> 2;
    const int wm   = wid >> 1;
    const int wn   = wid & 1;
    const int z    = blockIdx.z;
    const int bb   = z >> 4;
    const int hh   = z & 15;
    const int bm   = (3 - blockIdx.y) * 128;   // longest-first scheduling
    const uint32_t sb = smem_u32(smc);

    float d[2][8][4];
    #pragma unroll
    for (int mt = 0; mt < 2; mt++)
        #pragma unroll
        for (int nt = 0; nt < 8; nt++)
            #pragma unroll
            for (int j = 0; j < 4; j++) d[mt][nt][j] = 0.f;

    const __nv_bfloat16* aH = Ph + ((size_t)z * SEQ + bm) * SEQ;
    const __nv_bfloat16* aL = Pl + ((size_t)z * SEQ + bm) * SEQ;
    const __nv_bfloat16* bH = Vth + (size_t)z * HDIM * SEQ;
    const __nv_bfloat16* bL = Vtl + (size_t)z * HDIM * SEQ;

    const int nk = (bm >> 4) + 8;
    MAINLOOP(nk, aH, aL, bH, bL, SEQ, SEQ)

    #pragma unroll
    for (int mt = 0; mt < 2; mt++) {
        const int r0 = bm + wm * 32 + mt * 16 + g;
        #pragma unroll
        for (int nt = 0; nt < 8; nt++) {
            const int c0 = wn * 64 + nt * 8 + 2 * t4;
            #pragma unroll
            for (int half = 0; half < 2; half++) {
                int r = r0 + half * 8;
                size_t oidx = (size_t)(bb * SEQ + r) * DMODEL + hh * HDIM + c0;
                float va = d[mt][nt][half * 2], vb = d[mt][nt][half * 2 + 1];
                *(float2*)(O + oidx) = make_float2(va, vb);
                __nv_bfloat16 h0, l0, h1, l1;
                split_bf16(va, h0, l0);
                split_bf16(vb, h1, l1);
                *(uint32_t*)(Oh + oidx) = pack_bf2(h0, h1);
                *(uint32_t*)(Ol + oidx) = pack_bf2(l0, l1);
            }
        }
    }
}

// =================== fast LoRA-T ===================
#define LCH 512
template <int NM>
__global__ __launch_bounds__(256)
void lora_fast(const float* __restrict__ X, int K,
               const float* __restrict__ A0, const float* __restrict__ A1,
               const float* __restrict__ A2,
               float* __restrict__ T0, float* __restrict__ T1, float* __restrict__ T2)
{
    __shared__ float At[16 * 513];
    const int tid  = threadIdx.x;
    const int lane = tid & 31;
    const int warp = tid >> 5;
    const int row  = blockIdx.x * 8 + warp;

    const float* As[3] = {A0, A1, A2};
    float acc[NM][16];
    #pragma unroll
    for (int m = 0; m < NM; m++)
        #pragma unroll
        for (int r = 0; r < 16; r++) acc[m][r] = 0.f;

    for (int k0 = 0; k0 < K; k0 += LCH) {
        float xs[16];
        #pragma unroll
        for (int j = 0; j < 16; j++)
            xs[j] = X[(size_t)row * K + k0 + lane + 32 * j];
        #pragma unroll
        for (int m = 0; m < NM; m++) {
            __syncthreads();
            const float* Am = As[m];
            for (int i = tid; i < 16 * LCH; i += 256) {
                int k = i >> 4, r = i & 15;
                At[r * 513 + k] = Am[(size_t)(k0 + k) * RLORA + r];
            }
            __syncthreads();
            #pragma unroll
            for (int j = 0; j < 16; j++) {
                int k = lane + 32 * j;
                float xv = xs[j];
                #pragma unroll
                for (int r = 0; r < 16; r++)
                    acc[m][r] += xv * At[r * 513 + k];
            }
        }
    }

    float* Ts[3] = {T0, T1, T2};
    #pragma unroll
    for (int m = 0; m < NM; m++) {
        #pragma unroll
        for (int r = 0; r < 16; r++) {
            float v = acc[m][r];
            #pragma unroll
            for (int o = 16; o > 0; o >>= 1) v += __shfl_xor_sync(0xffffffffu, v, o);
            if (lane == 0) Ts[m][row * RLORA + r] = v;
        }
    }
}

// ---------------- batched weight transpose + split (z over {layer, matrix}) ----------------
__global__ void transpose_splitz(const float* __restrict__ W0, const float* __restrict__ W1,
                                 const float* __restrict__ W2, const float* __restrict__ W3,
                                 int nm, size_t src_lstride,
                                 __nv_bfloat16* __restrict__ Whb, __nv_bfloat16* __restrict__ Wlb,
                                 size_t dst_base, size_t dst_mstride, size_t dst_lstride,
                                 int Kd, int Nd)
{
    __shared__ float tile[32][33];
    const int zz = blockIdx.z;
    const int l = zz / nm, m = zz % nm;
    const float* W = ((m == 0) ? W0 : (m == 1) ? W1 : (m == 2) ? W2 : W3) + (size_t)l * src_lstride;
    __nv_bfloat16* Wh = Whb + dst_base + (size_t)l * dst_lstride + (size_t)m * dst_mstride;
    __nv_bfloat16* Wl = Wlb + dst_base + (size_t)l * dst_lstride + (size_t)m * dst_mstride;

    int n0 = blockIdx.x * 32, k0 = blockIdx.y * 32;
    int x = threadIdx.x, y = threadIdx.y;
    #pragma unroll
    for (int dy = 0; dy < 32; dy += 8)
        tile[y + dy][x] = W[(size_t)(k0 + y + dy) * Nd + n0 + x];
    __syncthreads();
    #pragma unroll
    for (int dy = 0; dy < 32; dy += 8) {
        float v = tile[x][y + dy];
        size_t o = (size_t)(n0 + y + dy) * Kd + k0 + x;
        __nv_bfloat16 h, l2;
        split_bf16(v, h, l2);
        Wh[o] = h; Wl[o] = l2;
    }
}

// ---------------- V transpose + split per head ----------------
__global__ void vsplit_t(const float* __restrict__ V,
                         __nv_bfloat16* __restrict__ Vth, __nv_bfloat16* __restrict__ Vtl)
{
    __shared__ float tile[32][33];
    int tok0 = blockIdx.x * 32, d0 = blockIdx.y * 32;
    int x = threadIdx.x, y = threadIdx.y;
    #pragma unroll
    for (int dy = 0; dy < 32; dy += 8)
        tile[y + dy][x] = V[(size_t)(tok0 + y + dy) * DMODEL + d0 + x];
    __syncthreads();
    int bb = tok0 >> 9, s0 = tok0 & 511;
    int hh = d0 >> 7, dd0 = d0 & 127;
    size_t zb = ((size_t)(bb * NHEAD + hh)) * HDIM * SEQ;
    #pragma unroll
    for (int dy = 0; dy < 32; dy += 8) {
        float v = tile[x][y + dy];
        size_t oidx = zb + (size_t)(dd0 + y + dy) * SEQ + s0 + x;
        __nv_bfloat16 h, l;
        split_bf16(v, h, l);
        Vth[oidx] = h; Vtl[oidx] = l;
    }
}

// ---------------- fused embed + rmsnorm(ln1 layer0) ----------------
__global__ void embed_rms(const int* __restrict__ idT, const int* __restrict__ idM,
                          const float* __restrict__ E, const float* __restrict__ W,
                          float* __restrict__ H, float* __restrict__ X,
                          __nv_bfloat16* __restrict__ Xh, __nv_bfloat16* __restrict__ Xl)
{
    __shared__ float red[256];
    int t  = blockIdx.x;
    int bb = t >> 9;
    int s  = t & 511;
    int id = (bb < 4) ? idT[bb * SEQ + s] : idM[(bb - 4) * SEQ + s];
    const float* src = E + (size_t)id * DMODEL;
    int tid = threadIdx.x;
    float vals[8];
    float ss = 0.f;
    #pragma unroll
    for (int j = 0; j < 8; j++) {
        float v = src[tid + 256 * j];
        vals[j] = v;
        ss += v * v;
    }
    red[tid] = ss; __syncthreads();
    for (int o = 128; o > 0; o >>= 1) {
        if (tid < o) red[tid] += red[tid + o];
        __syncthreads();
    }
    float scale = rsqrtf(red[0] / (float)DMODEL + 1e-6f);
    size_t base = (size_t)t * DMODEL;
    #pragma unroll
    for (int j = 0; j < 8; j++) {
        int idx = tid + 256 * j;
        float v = vals[j];
        H[base + idx] = v;
        float xv = v * scale * W[idx];
        X[base + idx] = xv;
        __nv_bfloat16 hh, ll;
        split_bf16(xv, hh, ll);
        Xh[base + idx] = hh; Xl[base + idx] = ll;
    }
}

// ---------------- rmsnorm ----------------
__global__ void rmsnorm_kernel(const float* __restrict__ H, const float* __restrict__ W,
                               float* __restrict__ X,
                               __nv_bfloat16* __restrict__ Xh, __nv_bfloat16* __restrict__ Xl)
{
    __shared__ float red[256];
    int row = blockIdx.x;
    const float* h = H + (size_t)row * DMODEL;
    int tid = threadIdx.x;
    float vals[8];
    float s = 0.f;
    #pragma unroll
    for (int j = 0; j < 8; j++) {
        float v = h[tid + 256 * j];
        vals[j] = v;
        s += v * v;
    }
    red[tid] = s; __syncthreads();
    for (int o = 128; o > 0; o >>= 1) {
        if (tid < o) red[tid] += red[tid + o];
        __syncthreads();
    }
    float scale = rsqrtf(red[0] / (float)DMODEL + 1e-6f);
    size_t base = (size_t)row * DMODEL;
    #pragma unroll
    for (int j = 0; j < 8; j++) {
        int idx = tid + 256 * j;
        float v = vals[j] * scale * W[idx];
        X[base + idx] = v;
        __nv_bfloat16 hh, ll;
        split_bf16(v, hh, ll);
        Xh[base + idx] = hh; Xl[base + idx] = ll;
    }
}

// ---------------- RoPE ----------------
__global__ void rope_kernel(const float* __restrict__ Q, const float* __restrict__ Kt,
                            __nv_bfloat16* __restrict__ Qh, __nv_bfloat16* __restrict__ Ql,
                            __nv_bfloat16* __restrict__ Kh, __nv_bfloat16* __restrict__ Kl)
{
    int i = blockIdx.x * blockDim.x + threadIdx.x;
    if (i >= MTOK * NHEAD * 64) return;
    int d = i & 63;
    int h = (i >> 6) & 15;
    int t = i >> 10;
    int s = t & 511;
    float freq = expf(-(float)d * (logf(10000.f) / 64.f));
    float ang = (float)s * freq;
    float sn, cs;
    sincosf(ang, &sn, &cs);
    size_t b0 = (size_t)t * DMODEL + h * HDIM + d;
    __nv_bfloat16 hh, ll;
    float x1 = Q[b0], x2 = Q[b0 + 64];
    float r1 = x1 * cs - x2 * sn;
    float r2 = x1 * sn + x2 * cs;
    split_bf16(r1, hh, ll); Qh[b0] = hh;      Ql[b0] = ll;
    split_bf16(r2, hh, ll); Qh[b0 + 64] = hh; Ql[b0 + 64] = ll;
    x1 = Kt[b0]; x2 = Kt[b0 + 64];
    r1 = x1 * cs - x2 * sn;
    r2 = x1 * sn + x2 * cs;
    split_bf16(r1, hh, ll); Kh[b0] = hh;      Kl[b0] = ll;
    split_bf16(r2, hh, ll); Kh[b0 + 64] = hh; Kl[b0 + 64] = ll;
}

// ---------------- causal-aware warp-per-row softmax ----------------
// grid = BB*NHEAD*SEQ/8, block 256 (8 warps, one row each)
__global__ void softmax_kernel(const float* __restrict__ S_,
                               __nv_bfloat16* __restrict__ Ph, __nv_bfloat16* __restrict__ Pl)
{
    int row  = blockIdx.x * 8 + (threadIdx.x >> 5);
    int lane = threadIdx.x & 31;
    int sq   = row & (SEQ - 1);
    const float* p = S_ + (size_t)row * SEQ;

    float vals[16];
    float m = -1e30f;
    #pragma unroll
    for (int j = 0; j < 16; j++) {
        int c = lane + 32 * j;
        float v = (c <= sq) ? p[c] : -1e30f;
        vals[j] = v;
        m = fmaxf(m, v);
    }
    #pragma unroll
    for (int o = 16; o > 0; o >>= 1) m = fmaxf(m, __shfl_xor_sync(0xffffffffu, m, o));

    float s = 0.f;
    #pragma unroll
    for (int j = 0; j < 16; j++) {
        int c = lane + 32 * j;
        float e = (c <= sq) ? expf(vals[j] - m) : 0.f;
        vals[j] = e;
        s += e;
    }
    #pragma unroll
    for (int o = 16; o > 0; o >>= 1) s += __shfl_xor_sync(0xffffffffu, s, o);
    float inv = 1.f / s;

    size_t base = (size_t)row * SEQ;
    #pragma unroll
    for (int j = 0; j < 16; j++) {
        int c = lane + 32 * j;
        __nv_bfloat16 hh, ll;
        split_bf16(vals[j] * inv, hh, ll);
        Ph[base + c] = hh;
        Pl[base + c] = ll;
    }
}

// ---------------- swiglu ----------------
__global__ void swiglu_kernel(float* __restrict__ G, const float* __restrict__ U,
                              __nv_bfloat16* __restrict__ Gh, __nv_bfloat16* __restrict__ Gl)
{
    size_t i = (size_t)blockIdx.x * blockDim.x + threadIdx.x;
    if (i >= (size_t)MTOK * FFDIM) return;
    float g = G[i];
    float sig = 1.f / (1.f + expf(-g));
    float v = g * sig * U[i];
    G[i] = v;
    __nv_bfloat16 hh, ll;
    split_bf16(v, hh, ll);
    Gh[i] = hh; Gl[i] = ll;
}

// ---------------- reps extraction + L2 normalize ----------------
__global__ void reps_kernel(const float* __restrict__ X, const int* __restrict__ mT,
                            const int* __restrict__ mM, float* __restrict__ R_)
{
    __shared__ int ired[256];
    __shared__ float fred[256];
    __shared__ int sidx;
    int bb = blockIdx.x;
    const int* mask = (bb < 4) ? mT : mM;
    int b = bb & 3;
    int t = threadIdx.x;
    int s = 0;
    for (int j = t; j < SEQ; j += 256) s += mask[b * SEQ + j];
    ired[t] = s; __syncthreads();
    for (int o = 128; o > 0; o >>= 1) {
        if (t < o) ired[t] += ired[t + o];
        __syncthreads();
    }
    if (t == 0) {
        int last = mask[0 * SEQ + 511] + mask[1 * SEQ + 511] +
                   mask[2 * SEQ + 511] + mask[3 * SEQ + 511];
        sidx = (last == BATCH) ? (SEQ - 1) : (ired[0] - 1);
    }
    __syncthreads();
    const float* row = X + (size_t)(bb * SEQ + sidx) * DMODEL;
    float ss = 0.f;
    for (int j = t; j < DMODEL; j += 256) { float v = row[j]; ss += v * v; }
    fred[t] = ss; __syncthreads();
    for (int o = 128; o > 0; o >>= 1) {
        if (t < o) fred[t] += fred[t + o];
        __syncthreads();
    }
    float inv = 1.f / sqrtf(fred[0]);
    for (int j = t; j < DMODEL; j += 256) R_[bb * DMODEL + j] = row[j] * inv;
}

// ---------------- contrastive loss ----------------
__global__ void loss_kernel(const float* __restrict__ R_, float* __restrict__ out)
{
    __shared__ float sims[16];
    int tid = threadIdx.x;
    int warp = tid >> 5, lane = tid & 31;
    for (int p = warp; p < 16; p += 8) {
        int i = p >> 2, j = p & 3;
        const float* a = R_ + i * DMODEL;
        const float* bR = R_ + (4 + j) * DMODEL;
        float d = 0.f;
        for (int k2 = lane; k2 < DMODEL; k2 += 32) d += a[k2] * bR[k2];
        #pragma unroll
        for (int o = 16; o > 0; o >>= 1) d += __shfl_xor_sync(0xffffffff, d, o);
        if (lane == 0) sims[p] = d * 20.f;
    }
    __syncthreads();
    if (tid == 0) {
        float loss = 0.f;
        for (int i = 0; i < 4; i++) {
            float m = -1e30f;
            for (int j = 0; j < 4; j++) m = fmaxf(m, sims[i * 4 + j]);
            float sum = 0.f;
            for (int j = 0; j < 4; j++) sum += expf(sims[i * 4 + j] - m);
            loss += (logf(sum) + m) - sims[i * 4 + i];
        }
        out[0] = loss * 0.25f;
    }
}

// ---------------- host driver ----------------
static void* symaddr_raw(const void* sym)
{
    void* p = nullptr;
    cudaGetSymbolAddress(&p, sym);
    return p;
}

extern "C" void kernel_launch(void* const* d_in, const int* in_sizes, int n_in,
                              void* d_out, int out_size)
{
    const int*   idT = (const int*)d_in[0];
    const int*   mT  = (const int*)d_in[1];
    const int*   idM = (const int*)d_in[2];
    const int*   mM  = (const int*)d_in[3];
    const float* emb = (const float*)d_in[4];
    const float* ln1 = (const float*)d_in[5];
    const float* ln2 = (const float*)d_in[6];
    const float* lnf = (const float*)d_in[7];
    const float* Wq = (const float*)d_in[8],  *Aq = (const float*)d_in[9],  *Bq = (const float*)d_in[10];
    const float* Wk = (const float*)d_in[11], *Ak = (const float*)d_in[12], *Bk = (const float*)d_in[13];
    const float* Wv = (const float*)d_in[14], *Av = (const float*)d_in[15], *Bv = (const float*)d_in[16];
    const float* Wo = (const float*)d_in[17], *Ao = (const float*)d_in[18], *Bo = (const float*)d_in[19];
    const float* Wg = (const float*)d_in[20], *Ag = (const float*)d_in[21], *Bg = (const float*)d_in[22];
    const float* Wu = (const float*)d_in[23], *Au = (const float*)d_in[24], *Bu = (const float*)d_in[25];
    const float* Wd = (const float*)d_in[26], *Ad = (const float*)d_in[27], *Bd = (const float*)d_in[28];

    float* h  = (float*)symaddr_raw(g_h);
    float* x  = (float*)symaddr_raw(g_x);
    float* q  = (float*)symaddr_raw(g_q);
    float* k  = (float*)symaddr_raw(g_k);
    float* v  = (float*)symaddr_raw(g_v);
    float* o  = (float*)symaddr_raw(g_o);
    float* sc = (float*)symaddr_raw(g_sc);
    float* gg = (float*)symaddr_raw(g_gate);
    float* uu = (float*)symaddr_raw(g_up);
    float* t0 = (float*)symaddr_raw(g_t);
    float* rp = (float*)symaddr_raw(g_reps);
    __nv_bfloat16* ah  = (__nv_bfloat16*)symaddr_raw(g_ah);
    __nv_bfloat16* al  = (__nv_bfloat16*)symaddr_raw(g_al);
    __nv_bfloat16* wh  = (__nv_bfloat16*)symaddr_raw(g_wh);
    __nv_bfloat16* wl  = (__nv_bfloat16*)symaddr_raw(g_wl);
    __nv_bfloat16* qh  = (__nv_bfloat16*)symaddr_raw(g_qh);
    __nv_bfloat16* ql  = (__nv_bfloat16*)symaddr_raw(g_ql);
    __nv_bfloat16* kh  = (__nv_bfloat16*)symaddr_raw(g_kh);
    __nv_bfloat16* kl  = (__nv_bfloat16*)symaddr_raw(g_kl);
    __nv_bfloat16* ph  = (__nv_bfloat16*)symaddr_raw(g_ph);
    __nv_bfloat16* pl  = (__nv_bfloat16*)symaddr_raw(g_pl);
    __nv_bfloat16* vth = (__nv_bfloat16*)symaddr_raw(g_vth);
    __nv_bfloat16* vtl = (__nv_bfloat16*)symaddr_raw(g_vtl);

    cudaFuncSetAttribute(gemm_tc,    cudaFuncAttributeMaxDynamicSharedMemorySize, GSMEM);
    cudaFuncSetAttribute(scores_mma, cudaFuncAttributeMaxDynamicSharedMemorySize, SCSM);
    cudaFuncSetAttribute(attnv_mma,  cudaFuncAttributeMaxDynamicSharedMemorySize, AVSM);

    const size_t DD = (size_t)DMODEL * DMODEL;
    const size_t DF = (size_t)DMODEL * FFDIM;
    const size_t LSTR = 4 * DD + 3 * DF;
    const dim3 tB(32, 8);
    const dim3 gD1(DMODEL / 128, MTOK / 128, 1);
    const dim3 gD3(DMODEL / 128, MTOK / 128, 3);
    const dim3 gF2(FFDIM / 128, MTOK / 128, 2);

    // ---- all weight transposes in 3 batched launches ----
    transpose_splitz<<<dim3(DMODEL / 32, DMODEL / 32, LAYERS * 4), tB>>>(
        Wq, Wk, Wv, Wo, 4, DD, wh, wl, 0, DD, LSTR, DMODEL, DMODEL);
    transpose_splitz<<<dim3(FFDIM / 32, DMODEL / 32, LAYERS * 2), tB>>>(
        Wg, Wu, nullptr, nullptr, 2, DF, wh, wl, 4 * DD, DF, LSTR, DMODEL, FFDIM);
    transpose_splitz<<<dim3(DMODEL / 32, FFDIM / 32, LAYERS), tB>>>(
        Wd, nullptr, nullptr, nullptr, 1, DF, wh, wl, 4 * DD + 2 * DF, 0, LSTR, FFDIM, DMODEL);

    embed_rms<<<MTOK, 256>>>(idT, idM, emb, ln1, h, x, ah, al);

    for (int l = 0; l < LAYERS; l++) {
        size_t off = (size_t)l * LSTR;
        const __nv_bfloat16 *Wl_h = wh + off, *Wl_l = wl + off;
        const float* Bq_l = Bq + (size_t)l * RLORA * DMODEL;
        const float* Bk_l = Bk + (size_t)l * RLORA * DMODEL;
        const float* Bv_l = Bv + (size_t)l * RLORA * DMODEL;
        const float* Bo_l = Bo + (size_t)l * RLORA * DMODEL;
        const float* Bg_l = Bg + (size_t)l * RLORA * FFDIM;
        const float* Bu_l = Bu + (size_t)l * RLORA * FFDIM;
        const float* Bd_l = Bd + (size_t)l * RLORA * DMODEL;

        if (l > 0)
            rmsnorm_kernel<<<MTOK, 256>>>(h, ln1 + l * DMODEL, x, ah, al);

        lora_fast<3><<<MTOK / 8, 256>>>(x, DMODEL, Aq + (size_t)l * DMODEL * RLORA,
                                        Ak + (size_t)l * DMODEL * RLORA,
                                        Av + (size_t)l * DMODEL * RLORA,
                                        t0, t0 + MTOK * RLORA, t0 + 2 * MTOK * RLORA);
        gemm_tc<<<gD3, 256, GSMEM>>>(ah, al, Wl_h, Wl_l, DD, q, k, v,
                                     MTOK, DMODEL, DMODEL, t0, Bq_l, Bk_l, Bv_l, 0);

        rope_kernel<<<(MTOK * NHEAD * 64 + 255) / 256, 256>>>(q, k, qh, ql, kh, kl);
        vsplit_t<<<dim3(MTOK / 32, DMODEL / 32), tB>>>(v, vth, vtl);

        scores_mma<<<dim3(4, 4, BB * NHEAD), 256, SCSM>>>(qh, ql, kh, kl, mT, mM, sc);
        softmax_kernel<<<BB * NHEAD * SEQ / 8, 256>>>(sc, ph, pl);
        attnv_mma<<<dim3(1, 4, BB * NHEAD), 256, AVSM>>>(ph, pl, vth, vtl, o, ah, al);

        lora_fast<1><<<MTOK / 8, 256>>>(o, DMODEL, Ao + (size_t)l * DMODEL * RLORA,
                                        nullptr, nullptr, t0, nullptr, nullptr);
        gemm_tc<<<gD1, 256, GSMEM>>>(ah, al, Wl_h + 3 * DD, Wl_l + 3 * DD, 0, h, nullptr, nullptr,
                                     MTOK, DMODEL, DMODEL, t0, Bo_l, nullptr, nullptr, 1);

        rmsnorm_kernel<<<MTOK, 256>>>(h, ln2 + l * DMODEL, x, ah, al);
        lora_fast<2><<<MTOK / 8, 256>>>(x, DMODEL, Ag + (size_t)l * DMODEL * RLORA,
                                        Au + (size_t)l * DMODEL * RLORA, nullptr,
                                        t0, t0 + MTOK * RLORA, nullptr);
        gemm_tc<<<gF2, 256, GSMEM>>>(ah, al, Wl_h + 4 * DD, Wl_l + 4 * DD, DF, gg, uu, nullptr,
                                     MTOK, FFDIM, DMODEL, t0, Bg_l, Bu_l, nullptr, 0);

        swiglu_kernel<<<(int)(((size_t)MTOK * FFDIM + 255) / 256), 256>>>(gg, uu, ah, al);

        lora_fast<1><<<MTOK / 8, 256>>>(gg, FFDIM, Ad + (size_t)l * FFDIM * RLORA,
                                        nullptr, nullptr, t0, nullptr, nullptr);
        gemm_tc<<<gD1, 256, GSMEM>>>(ah, al, Wl_h + 4 * DD + 2 * DF, Wl_l + 4 * DD + 2 * DF, 0,
                                     h, nullptr, nullptr,
                                     MTOK, DMODEL, FFDIM, t0, Bd_l, nullptr, nullptr, 1);
    }

    rmsnorm_kernel<<<MTOK, 256>>>(h, lnf, x, ah, al);
    reps_kernel<<<BB, 256>>>(x, mT, mM, rp);
    loss_kernel<<<1, 256>>>(rp, (float*)d_out);
}

// round 17
// speedup vs baseline: 2.8500x; 1.0227x over previous
#include <cuda_runtime.h>
#include <cuda_bf16.h>
#include <math.h>
#include <stdint.h>

// Problem constants
#define LAYERS 2
#define DMODEL 2048
#define NHEAD  16
#define HDIM   128
#define FFDIM  5632
#define RLORA  16
#define BATCH  4
#define SEQ    512
#define BB     8
#define MTOK   (BB*SEQ)
#define LORA_SCALE 1.4f
#define SCALE_QK 0.08838834764831845f

// ---------------- scratch ----------------
__device__ float g_h   [MTOK * DMODEL];
__device__ float g_x   [MTOK * DMODEL];
__device__ float g_v   [MTOK * DMODEL];
__device__ float g_o   [MTOK * DMODEL];
__device__ float g_sc  [BB * NHEAD * SEQ * SEQ];
__device__ float g_gate[MTOK * FFDIM];
__device__ float g_up  [MTOK * FFDIM];
__device__ float g_t   [3 * MTOK * RLORA];
__device__ float g_reps[BB * DMODEL];
__device__ __nv_bfloat16 g_ah[MTOK * FFDIM];
__device__ __nv_bfloat16 g_al[MTOK * FFDIM];
__device__ __nv_bfloat16 g_wh[2 * (4 * DMODEL * DMODEL + 3 * DMODEL * FFDIM)];
__device__ __nv_bfloat16 g_wl[2 * (4 * DMODEL * DMODEL + 3 * DMODEL * FFDIM)];
__device__ __nv_bfloat16 g_qh[MTOK * DMODEL];
__device__ __nv_bfloat16 g_ql[MTOK * DMODEL];
__device__ __nv_bfloat16 g_kh[MTOK * DMODEL];
__device__ __nv_bfloat16 g_kl[MTOK * DMODEL];
__device__ __nv_bfloat16 g_ph[BB * NHEAD * SEQ * SEQ];
__device__ __nv_bfloat16 g_pl[BB * NHEAD * SEQ * SEQ];
__device__ __nv_bfloat16 g_vth[MTOK * DMODEL];
__device__ __nv_bfloat16 g_vtl[MTOK * DMODEL];

// =================== helpers ===================
__device__ __forceinline__ uint32_t smem_u32(const void* p) {
    uint32_t a;
    asm("{ .reg .u64 t; cvta.to.shared.u64 t, %1; cvt.u32.u64 %0, t; }" : "=r"(a) : "l"(p));
    return a;
}
__device__ __forceinline__ void cp_async16(uint32_t saddr, const void* gptr) {
    asm volatile("cp.async.cg.shared.global [%0], [%1], 16;" :: "r"(saddr), "l"(gptr));
}
__device__ __forceinline__ void cp_commit() { asm volatile("cp.async.commit_group;"); }
template <int NWAIT>
__device__ __forceinline__ void cp_wait() {
    asm volatile("cp.async.wait_group %0;" :: "n"(NWAIT));
}
__device__ __forceinline__ void mma16(float* d, const uint32_t* a, uint32_t b0, uint32_t b1) {
    asm volatile(
        "mma.sync.aligned.m16n8k16.row.col.f32.bf16.bf16.f32 "
        "{%0,%1,%2,%3}, {%4,%5,%6,%7}, {%8,%9}, {%0,%1,%2,%3};"
        : "+f"(d[0]), "+f"(d[1]), "+f"(d[2]), "+f"(d[3])
        : "r"(a[0]), "r"(a[1]), "r"(a[2]), "r"(a[3]), "r"(b0), "r"(b1));
}
__device__ __forceinline__ void ldm_x4(uint32_t* r, uint32_t addr) {
    asm volatile("ldmatrix.sync.aligned.m8n8.x4.shared.b16 {%0,%1,%2,%3}, [%4];"
                 : "=r"(r[0]), "=r"(r[1]), "=r"(r[2]), "=r"(r[3]) : "r"(addr));
}
__device__ __forceinline__ void split_bf16(float v, __nv_bfloat16& h, __nv_bfloat16& l) {
    h = __float2bfloat16(v);
    l = __float2bfloat16(v - __bfloat162float(h));
}
__device__ __forceinline__ uint32_t pack_bf2(__nv_bfloat16 a, __nv_bfloat16 b) {
    uint16_t ua = *reinterpret_cast<uint16_t*>(&a);
    uint16_t ub = *reinterpret_cast<uint16_t*>(&b);
    return (uint32_t)ua | ((uint32_t)ub << 16);
}

// 4-stage pipeline, BK=16. Per-stage arrays: 128 rows x 16 bf16, 48B row stride.
#define SMSB16  48
#define ARRB16  6144
#define STGB16  24576
#define NSTAGE  4
#define LA_OFF  98304
#define LB_OFF  104448
#define GSMEM   110592
#define SCSM    98816
#define AVSM    98304

// ---- compute one 128x16 stage (bf16x3), accumulator-interleaved ----
#define COMPUTE16(stbase)                                                         \
    {                                                                             \
        uint32_t ahf[2][4], alf[2][4];                                            \
        int grp = lane >> 3, r8 = lane & 7;                                       \
        int mm = (grp & 1) * 8 + r8;                                              \
        int koff = (grp >> 1) * 8;                                                \
        _Pragma("unroll")                                                         \
        for (int mt = 0; mt < 2; mt++) {                                          \
            uint32_t ad = (stbase) + (wm * 32 + mt * 16 + mm) * SMSB16 + koff * 2;\
            ldm_x4(ahf[mt], ad);                                                  \
            ldm_x4(alf[mt], ad + ARRB16);                                         \
        }                                                                         \
        _Pragma("unroll")                                                         \
        for (int np = 0; np < 4; np++) {                                          \
            int nn = (grp >> 1) * 8 + r8;                                         \
            int koffb = (grp & 1) * 8;                                            \
            uint32_t bd = (stbase) + 2 * ARRB16 + (wn * 64 + np * 16 + nn) * SMSB16 + koffb * 2; \
            uint32_t bh[4], bl[4];                                                \
            ldm_x4(bh, bd);                                                       \
            ldm_x4(bl, bd + ARRB16);                                              \
            mma16(d[0][np * 2],     ahf[0], bh[0], bh[1]);                        \
            mma16(d[0][np * 2 + 1], ahf[0], bh[2], bh[3]);                        \
            mma16(d[1][np * 2],     ahf[1], bh[0], bh[1]);                        \
            mma16(d[1][np * 2 + 1], ahf[1], bh[2], bh[3]);                        \
            mma16(d[0][np * 2],     ahf[0], bl[0], bl[1]);                        \
            mma16(d[0][np * 2 + 1], ahf[0], bl[2], bl[3]);                        \
            mma16(d[1][np * 2],     ahf[1], bl[0], bl[1]);                        \
            mma16(d[1][np * 2 + 1], ahf[1], bl[2], bl[3]);                        \
            mma16(d[0][np * 2],     alf[0], bh[0], bh[1]);                        \
            mma16(d[0][np * 2 + 1], alf[0], bh[2], bh[3]);                        \
            mma16(d[1][np * 2],     alf[1], bh[0], bh[1]);                        \
            mma16(d[1][np * 2 + 1], alf[1], bh[2], bh[3]);                        \
        }                                                                         \
    }

#define ISSUE16(kt, aH, aL, bH, bL, LDA, LDB)                                     \
    {                                                                             \
        const int k0_ = (kt) << 4;                                                \
        const int buf_ = (kt) & (NSTAGE - 1);                                     \
        _Pragma("unroll")                                                         \
        for (int j = 0; j < 4; j++) {                                             \
            int e = tid + j * 256;                                                \
            int arr = e >> 8;                                                     \
            int i = e & 255;                                                      \
            int row = i >> 1;                                                     \
            int cg = (i & 1) << 3;                                                \
            const __nv_bfloat16* gp;                                              \
            if (arr == 0)      gp = (aH) + (size_t)row * (LDA) + k0_ + cg;        \
            else if (arr == 1) gp = (aL) + (size_t)row * (LDA) + k0_ + cg;        \
            else if (arr == 2) gp = (bH) + (size_t)row * (LDB) + k0_ + cg;        \
            else               gp = (bL) + (size_t)row * (LDB) + k0_ + cg;        \
            cp_async16(sb + buf_ * STGB16 + arr * ARRB16 + row * SMSB16 + cg * 2, gp); \
        }                                                                         \
        cp_commit();                                                              \
    }

#define MAINLOOP(nk, aH, aL, bH, bL, LDA, LDB)                                    \
    {                                                                             \
        ISSUE16(0, aH, aL, bH, bL, LDA, LDB);                                     \
        ISSUE16(1, aH, aL, bH, bL, LDA, LDB);                                     \
        ISSUE16(2, aH, aL, bH, bL, LDA, LDB);                                     \
        for (int kt = 0; kt < (nk); kt++) {                                       \
            cp_wait<2>();                                                         \
            __syncthreads();                                                      \
            const uint32_t st_ = sb + (kt & (NSTAGE - 1)) * STGB16;               \
            COMPUTE16(st_)                                                        \
            if (kt + 3 < (nk)) { ISSUE16(kt + 3, aH, aL, bH, bL, LDA, LDB); }     \
            else               { cp_commit(); }                                   \
        }                                                                         \
        cp_wait<0>();                                                             \
        __syncthreads();                                                          \
    }

// =================== batched GEMM with fused LoRA + residual / RoPE ===================
// mode 0: C = result.  mode 1: C += result.
// mode 3 (qkv): z=0 -> rope -> Qh/Ql; z=1 -> rope -> Kh/Kl; z=2 -> fp32 C2 (v).
__global__ __launch_bounds__(256, 2)
void gemm_tc(const __nv_bfloat16* __restrict__ Agh, const __nv_bfloat16* __restrict__ Agl,
             const __nv_bfloat16* __restrict__ Whb, const __nv_bfloat16* __restrict__ Wlb,
             size_t wstride,
             float* __restrict__ C0, float* __restrict__ C1, float* __restrict__ C2,
             int M, int N, int K,
             const float* __restrict__ lTb,
             const float* __restrict__ lB0, const float* __restrict__ lB1,
             const float* __restrict__ lB2, int mode,
             __nv_bfloat16* __restrict__ Qh, __nv_bfloat16* __restrict__ Ql,
             __nv_bfloat16* __restrict__ Kh, __nv_bfloat16* __restrict__ Kl)
{
    extern __shared__ char smc[];
    const int tid  = threadIdx.x;
    const int wid  = tid >> 5;
    const int lane = tid & 31;
    const int t4   = lane & 3;
    const int g    = lane >> 2;
    const int wm   = wid >> 1;
    const int wn   = wid & 1;
    const int bm   = blockIdx.y * 128;
    const int bn   = blockIdx.x * 128;
    const int z    = blockIdx.z;
    const uint32_t sb = smem_u32(smc);

    const __nv_bfloat16* Wgh = Whb + (size_t)z * wstride;
    const __nv_bfloat16* Wgl = Wlb + (size_t)z * wstride;
    float* C = (z == 0) ? C0 : ((z == 1) ? C1 : C2);
    const float* lT = lTb + (size_t)z * MTOK * RLORA;
    const float* lB = (z == 0) ? lB0 : ((z == 1) ? lB1 : lB2);

    __nv_bfloat16* la = (__nv_bfloat16*)(smc + LA_OFF);
    __nv_bfloat16* lb = (__nv_bfloat16*)(smc + LB_OFF);
    for (int i = tid; i < 2048; i += 256) {
        int row = i >> 4, r = i & 15;
        la[row * 24 + r] = __float2bfloat16(LORA_SCALE * lT[(size_t)(bm + row) * RLORA + r]);
        lb[row * 24 + r] = __float2bfloat16(lB[(size_t)r * N + bn + row]);
    }

    float d[2][8][4];
    #pragma unroll
    for (int mt = 0; mt < 2; mt++)
        #pragma unroll
        for (int nt = 0; nt < 8; nt++)
            #pragma unroll
            for (int j = 0; j < 4; j++) d[mt][nt][j] = 0.f;

    const __nv_bfloat16* aH = Agh + (size_t)bm * K;
    const __nv_bfloat16* aL = Agl + (size_t)bm * K;
    const __nv_bfloat16* bH = Wgh + (size_t)bn * K;
    const __nv_bfloat16* bL = Wgl + (size_t)bn * K;

    const int nk = K >> 4;
    MAINLOOP(nk, aH, aL, bH, bL, K, K)

    // LoRA tail (hi-only, K=16)
    {
        uint32_t a[2][4];
        #pragma unroll
        for (int mt = 0; mt < 2; mt++) {
            const char* pa = (const char*)la + (wm * 32 + mt * 16 + g) * 48 + t4 * 4;
            a[mt][0] = *(const uint32_t*)(pa);
            a[mt][1] = *(const uint32_t*)(pa + 8 * 48);
            a[mt][2] = *(const uint32_t*)(pa + 16);
            a[mt][3] = *(const uint32_t*)(pa + 8 * 48 + 16);
        }
        #pragma unroll
        for (int nt = 0; nt < 8; nt++) {
            const char* pb = (const char*)lb + (wn * 64 + nt * 8 + g) * 48 + t4 * 4;
            uint32_t b0 = *(const uint32_t*)(pb);
            uint32_t b1 = *(const uint32_t*)(pb + 16);
            #pragma unroll
            for (int mt = 0; mt < 2; mt++) mma16(d[mt][nt], a[mt], b0, b1);
        }
    }

    if (mode == 3 && z < 2) {
        // ---- fused RoPE epilogue: stage tile, rotate pairs, emit bf16 splits ----
        float* tile = (float*)smc;   // 128 x 132 floats (stage area is free now)
        #pragma unroll
        for (int mt = 0; mt < 2; mt++) {
            #pragma unroll
            for (int half = 0; half < 2; half++) {
                const int rl = wm * 32 + mt * 16 + half * 8 + g;
                #pragma unroll
                for (int nt = 0; nt < 8; nt++) {
                    const int cl = wn * 64 + nt * 8 + 2 * t4;
                    tile[rl * 132 + cl]     = d[mt][nt][half * 2];
                    tile[rl * 132 + cl + 1] = d[mt][nt][half * 2 + 1];
                }
            }
        }
        __syncthreads();
        __nv_bfloat16* OH = (z == 0) ? Qh : Kh;
        __nv_bfloat16* OL = (z == 0) ? Ql : Kl;
        const float lgc = logf(10000.f) / 64.f;
        #pragma unroll
        for (int mt = 0; mt < 2; mt++) {
            #pragma unroll
            for (int half = 0; half < 2; half++) {
                const int rl = wm * 32 + mt * 16 + half * 8 + g;
                const int sq = (bm + rl) & (SEQ - 1);
                #pragma unroll
                for (int nt = 0; nt < 8; nt++) {
                    const int cl = wn * 64 + nt * 8 + 2 * t4;
                    __nv_bfloat16 hv[2], lv[2];
                    #pragma unroll
                    for (int cc = 0; cc < 2; cc++) {
                        int col = cl + cc;
                        int dd2 = col & 63;
                        float x1 = tile[rl * 132 + dd2];
                        float x2 = tile[rl * 132 + dd2 + 64];
                        float freq = expf(-(float)dd2 * lgc);
                        float sn, cs;
                        sincosf((float)sq * freq, &sn, &cs);
                        float val = (col >= 64) ? (x1 * sn + x2 * cs) : (x1 * cs - x2 * sn);
                        split_bf16(val, hv[cc], lv[cc]);
                    }
                    size_t oidx = (size_t)(bm + rl) * DMODEL + bn + cl;
                    *(uint32_t*)(OH + oidx) = pack_bf2(hv[0], hv[1]);
                    *(uint32_t*)(OL + oidx) = pack_bf2(lv[0], lv[1]);
                }
            }
        }
        return;
    }

    #pragma unroll
    for (int mt = 0; mt < 2; mt++) {
        const int r0 = bm + wm * 32 + mt * 16 + g;
        #pragma unroll
        for (int nt = 0; nt < 8; nt++) {
            const int c0 = bn + wn * 64 + nt * 8 + 2 * t4;
            float2 v0 = make_float2(d[mt][nt][0], d[mt][nt][1]);
            float2 v1 = make_float2(d[mt][nt][2], d[mt][nt][3]);
            float* p0 = C + (size_t)r0 * N + c0;
            float* p1 = C + (size_t)(r0 + 8) * N + c0;
            if (mode == 1) {
                float2 o0 = *(const float2*)p0;
                float2 o1 = *(const float2*)p1;
                v0.x += o0.x; v0.y += o0.y;
                v1.x += o1.x; v1.y += o1.y;
            }
            *(float2*)p0 = v0;
            *(float2*)p1 = v1;
        }
    }
}

// =================== scores (skip masked tiles entirely) ===================
__global__ __launch_bounds__(256, 2)
void scores_mma(const __nv_bfloat16* __restrict__ Qh, const __nv_bfloat16* __restrict__ Ql,
                const __nv_bfloat16* __restrict__ Kh, const __nv_bfloat16* __restrict__ Kl,
                const int* __restrict__ mT, const int* __restrict__ mM,
                float* __restrict__ S_)
{
    extern __shared__ char smc[];
    const int tid  = threadIdx.x;
    const int wid  = tid >> 5;
    const int lane = tid & 31;
    const int t4   = lane & 3;
    const int g    = lane >> 2;
    const int wm   = wid >> 1;
    const int wn   = wid & 1;
    const int z    = blockIdx.z;
    const int bb   = z >> 4;
    const int hh   = z & 15;
    const int bm   = blockIdx.y * 128;
    const int bn   = blockIdx.x * 128;
    if (bn > bm) return;

    const uint32_t sb = smem_u32(smc);
    int* msk = (int*)(smc + NSTAGE * STGB16);

    const int* mask = (bb < 4) ? (mT + bb * SEQ) : (mM + (bb - 4) * SEQ);
    if (tid < 128) msk[tid] = mask[bn + tid];

    float* Sbase = S_ + (size_t)z * SEQ * SEQ;

    float d[2][8][4];
    #pragma unroll
    for (int mt = 0; mt < 2; mt++)
        #pragma unroll
        for (int nt = 0; nt < 8; nt++)
            #pragma unroll
            for (int j = 0; j < 4; j++) d[mt][nt][j] = 0.f;

    const __nv_bfloat16* aH = Qh + (size_t)(bb * SEQ + bm) * DMODEL + hh * HDIM;
    const __nv_bfloat16* aL = Ql + (size_t)(bb * SEQ + bm) * DMODEL + hh * HDIM;
    const __nv_bfloat16* bH = Kh + (size_t)(bb * SEQ + bn) * DMODEL + hh * HDIM;
    const __nv_bfloat16* bL = Kl + (size_t)(bb * SEQ + bn) * DMODEL + hh * HDIM;

    const int nk = HDIM >> 4;
    MAINLOOP(nk, aH, aL, bH, bL, DMODEL, DMODEL)

    #pragma unroll
    for (int mt = 0; mt < 2; mt++) {
        const int r0 = wm * 32 + mt * 16 + g;
        #pragma unroll
        for (int nt = 0; nt < 8; nt++) {
            const int c0 = wn * 64 + nt * 8 + 2 * t4;
            #pragma unroll
            for (int half = 0; half < 2; half++) {
                int r = r0 + half * 8;
                int sq = bm + r, sk0 = bn + c0;
                float va = d[mt][nt][half * 2], vb = d[mt][nt][half * 2 + 1];
                bool ok0 = (sk0 <= sq) && (msk[c0] > 0);
                bool ok1 = (sk0 + 1 <= sq) && (msk[c0 + 1] > 0);
                float2 out;
                out.x = va * SCALE_QK + (ok0 ? 0.f : -1e9f);
                out.y = vb * SCALE_QK + (ok1 ? 0.f : -1e9f);
                *(float2*)(Sbase + (size_t)sq * SEQ + sk0) = out;
            }
        }
    }
}

// =================== attnv (causal-truncated, longest tiles first) ===================
__global__ __launch_bounds__(256, 2)
void attnv_mma(const __nv_bfloat16* __restrict__ Ph, const __nv_bfloat16* __restrict__ Pl,
               const __nv_bfloat16* __restrict__ Vth, const __nv_bfloat16* __restrict__ Vtl,
               float* __restrict__ O,
               __nv_bfloat16* __restrict__ Oh, __nv_bfloat16* __restrict__ Ol)
{
    extern __shared__ char smc[];
    const int tid  = threadIdx.x;
    const int wid  = tid >> 5;
    const int lane = tid & 31;
    const int t4   = lane & 3;
    const int g    = lane >> 2;
    const int wm   = wid >> 1;
    const int wn   = wid & 1;
    const int z    = blockIdx.z;
    const int bb   = z >> 4;
    const int hh   = z & 15;
    const int bm   = (3 - blockIdx.y) * 128;   // longest-first scheduling
    const uint32_t sb = smem_u32(smc);

    float d[2][8][4];
    #pragma unroll
    for (int mt = 0; mt < 2; mt++)
        #pragma unroll
        for (int nt = 0; nt < 8; nt++)
            #pragma unroll
            for (int j = 0; j < 4; j++) d[mt][nt][j] = 0.f;

    const __nv_bfloat16* aH = Ph + ((size_t)z * SEQ + bm) * SEQ;
    const __nv_bfloat16* aL = Pl + ((size_t)z * SEQ + bm) * SEQ;
    const __nv_bfloat16* bH = Vth + (size_t)z * HDIM * SEQ;
    const __nv_bfloat16* bL = Vtl + (size_t)z * HDIM * SEQ;

    const int nk = (bm >> 4) + 8;
    MAINLOOP(nk, aH, aL, bH, bL, SEQ, SEQ)

    #pragma unroll
    for (int mt = 0; mt < 2; mt++) {
        const int r0 = bm + wm * 32 + mt * 16 + g;
        #pragma unroll
        for (int nt = 0; nt < 8; nt++) {
            const int c0 = wn * 64 + nt * 8 + 2 * t4;
            #pragma unroll
            for (int half = 0; half < 2; half++) {
                int r = r0 + half * 8;
                size_t oidx = (size_t)(bb * SEQ + r) * DMODEL + hh * HDIM + c0;
                float va = d[mt][nt][half * 2], vb = d[mt][nt][half * 2 + 1];
                *(float2*)(O + oidx) = make_float2(va, vb);
                __nv_bfloat16 h0, l0, h1, l1;
                split_bf16(va, h0, l0);
                split_bf16(vb, h1, l1);
                *(uint32_t*)(Oh + oidx) = pack_bf2(h0, h1);
                *(uint32_t*)(Ol + oidx) = pack_bf2(l0, l1);
            }
        }
    }
}

// =================== fast LoRA-T ===================
#define LCH 512
template <int NM>
__global__ __launch_bounds__(256)
void lora_fast(const float* __restrict__ X, int K,
               const float* __restrict__ A0, const float* __restrict__ A1,
               const float* __restrict__ A2,
               float* __restrict__ T0, float* __restrict__ T1, float* __restrict__ T2)
{
    __shared__ float At[16 * 513];
    const int tid  = threadIdx.x;
    const int lane = tid & 31;
    const int warp = tid >> 5;
    const int row  = blockIdx.x * 8 + warp;

    const float* As[3] = {A0, A1, A2};
    float acc[NM][16];
    #pragma unroll
    for (int m = 0; m < NM; m++)
        #pragma unroll
        for (int r = 0; r < 16; r++) acc[m][r] = 0.f;

    for (int k0 = 0; k0 < K; k0 += LCH) {
        float xs[16];
        #pragma unroll
        for (int j = 0; j < 16; j++)
            xs[j] = X[(size_t)row * K + k0 + lane + 32 * j];
        #pragma unroll
        for (int m = 0; m < NM; m++) {
            __syncthreads();
            const float* Am = As[m];
            for (int i = tid; i < 16 * LCH; i += 256) {
                int k = i >> 4, r = i & 15;
                At[r * 513 + k] = Am[(size_t)(k0 + k) * RLORA + r];
            }
            __syncthreads();
            #pragma unroll
            for (int j = 0; j < 16; j++) {
                int k = lane + 32 * j;
                float xv = xs[j];
                #pragma unroll
                for (int r = 0; r < 16; r++)
                    acc[m][r] += xv * At[r * 513 + k];
            }
        }
    }

    float* Ts[3] = {T0, T1, T2};
    #pragma unroll
    for (int m = 0; m < NM; m++) {
        #pragma unroll
        for (int r = 0; r < 16; r++) {
            float v = acc[m][r];
            #pragma unroll
            for (int o = 16; o > 0; o >>= 1) v += __shfl_xor_sync(0xffffffffu, v, o);
            if (lane == 0) Ts[m][row * RLORA + r] = v;
        }
    }
}

// ---------------- batched weight transpose + split ----------------
__global__ void transpose_splitz(const float* __restrict__ W0, const float* __restrict__ W1,
                                 const float* __restrict__ W2, const float* __restrict__ W3,
                                 int nm, size_t src_lstride,
                                 __nv_bfloat16* __restrict__ Whb, __nv_bfloat16* __restrict__ Wlb,
                                 size_t dst_base, size_t dst_mstride, size_t dst_lstride,
                                 int Kd, int Nd)
{
    __shared__ float tile[32][33];
    const int zz = blockIdx.z;
    const int l = zz / nm, m = zz % nm;
    const float* W = ((m == 0) ? W0 : (m == 1) ? W1 : (m == 2) ? W2 : W3) + (size_t)l * src_lstride;
    __nv_bfloat16* Wh = Whb + dst_base + (size_t)l * dst_lstride + (size_t)m * dst_mstride;
    __nv_bfloat16* Wl = Wlb + dst_base + (size_t)l * dst_lstride + (size_t)m * dst_mstride;

    int n0 = blockIdx.x * 32, k0 = blockIdx.y * 32;
    int x = threadIdx.x, y = threadIdx.y;
    #pragma unroll
    for (int dy = 0; dy < 32; dy += 8)
        tile[y + dy][x] = W[(size_t)(k0 + y + dy) * Nd + n0 + x];
    __syncthreads();
    #pragma unroll
    for (int dy = 0; dy < 32; dy += 8) {
        float v = tile[x][y + dy];
        size_t o = (size_t)(n0 + y + dy) * Kd + k0 + x;
        __nv_bfloat16 h, l2;
        split_bf16(v, h, l2);
        Wh[o] = h; Wl[o] = l2;
    }
}

// ---------------- V transpose + split per head ----------------
__global__ void vsplit_t(const float* __restrict__ V,
                         __nv_bfloat16* __restrict__ Vth, __nv_bfloat16* __restrict__ Vtl)
{
    __shared__ float tile[32][33];
    int tok0 = blockIdx.x * 32, d0 = blockIdx.y * 32;
    int x = threadIdx.x, y = threadIdx.y;
    #pragma unroll
    for (int dy = 0; dy < 32; dy += 8)
        tile[y + dy][x] = V[(size_t)(tok0 + y + dy) * DMODEL + d0 + x];
    __syncthreads();
    int bb = tok0 >> 9, s0 = tok0 & 511;
    int hh = d0 >> 7, dd0 = d0 & 127;
    size_t zb = ((size_t)(bb * NHEAD + hh)) * HDIM * SEQ;
    #pragma unroll
    for (int dy = 0; dy < 32; dy += 8) {
        float v = tile[x][y + dy];
        size_t oidx = zb + (size_t)(dd0 + y + dy) * SEQ + s0 + x;
        __nv_bfloat16 h, l;
        split_bf16(v, h, l);
        Vth[oidx] = h; Vtl[oidx] = l;
    }
}

// ---------------- fused embed + rmsnorm(ln1 layer0) ----------------
__global__ void embed_rms(const int* __restrict__ idT, const int* __restrict__ idM,
                          const float* __restrict__ E, const float* __restrict__ W,
                          float* __restrict__ H, float* __restrict__ X,
                          __nv_bfloat16* __restrict__ Xh, __nv_bfloat16* __restrict__ Xl)
{
    __shared__ float red[256];
    int t  = blockIdx.x;
    int bb = t >> 9;
    int s  = t & 511;
    int id = (bb < 4) ? idT[bb * SEQ + s] : idM[(bb - 4) * SEQ + s];
    const float* src = E + (size_t)id * DMODEL;
    int tid = threadIdx.x;
    float vals[8];
    float ss = 0.f;
    #pragma unroll
    for (int j = 0; j < 8; j++) {
        float v = src[tid + 256 * j];
        vals[j] = v;
        ss += v * v;
    }
    red[tid] = ss; __syncthreads();
    for (int o = 128; o > 0; o >>= 1) {
        if (tid < o) red[tid] += red[tid + o];
        __syncthreads();
    }
    float scale = rsqrtf(red[0] / (float)DMODEL + 1e-6f);
    size_t base = (size_t)t * DMODEL;
    #pragma unroll
    for (int j = 0; j < 8; j++) {
        int idx = tid + 256 * j;
        float v = vals[j];
        H[base + idx] = v;
        float xv = v * scale * W[idx];
        X[base + idx] = xv;
        __nv_bfloat16 hh, ll;
        split_bf16(xv, hh, ll);
        Xh[base + idx] = hh; Xl[base + idx] = ll;
    }
}

// ---------------- rmsnorm ----------------
__global__ void rmsnorm_kernel(const float* __restrict__ H, const float* __restrict__ W,
                               float* __restrict__ X,
                               __nv_bfloat16* __restrict__ Xh, __nv_bfloat16* __restrict__ Xl)
{
    __shared__ float red[256];
    int row = blockIdx.x;
    const float* h = H + (size_t)row * DMODEL;
    int tid = threadIdx.x;
    float vals[8];
    float s = 0.f;
    #pragma unroll
    for (int j = 0; j < 8; j++) {
        float v = h[tid + 256 * j];
        vals[j] = v;
        s += v * v;
    }
    red[tid] = s; __syncthreads();
    for (int o = 128; o > 0; o >>= 1) {
        if (tid < o) red[tid] += red[tid + o];
        __syncthreads();
    }
    float scale = rsqrtf(red[0] / (float)DMODEL + 1e-6f);
    size_t base = (size_t)row * DMODEL;
    #pragma unroll
    for (int j = 0; j < 8; j++) {
        int idx = tid + 256 * j;
        float v = vals[j] * scale * W[idx];
        X[base + idx] = v;
        __nv_bfloat16 hh, ll;
        split_bf16(v, hh, ll);
        Xh[base + idx] = hh; Xl[base + idx] = ll;
    }
}

// ---------------- causal-aware warp-per-row softmax ----------------
__global__ void softmax_kernel(const float* __restrict__ S_,
                               __nv_bfloat16* __restrict__ Ph, __nv_bfloat16* __restrict__ Pl)
{
    int row  = blockIdx.x * 8 + (threadIdx.x >> 5);
    int lane = threadIdx.x & 31;
    int sq   = row & (SEQ - 1);
    const float* p = S_ + (size_t)row * SEQ;

    float vals[16];
    float m = -1e30f;
    #pragma unroll
    for (int j = 0; j < 16; j++) {
        int c = lane + 32 * j;
        float v = (c <= sq) ? p[c] : -1e30f;
        vals[j] = v;
        m = fmaxf(m, v);
    }
    #pragma unroll
    for (int o = 16; o > 0; o >>= 1) m = fmaxf(m, __shfl_xor_sync(0xffffffffu, m, o));

    float s = 0.f;
    #pragma unroll
    for (int j = 0; j < 16; j++) {
        int c = lane + 32 * j;
        float e = (c <= sq) ? expf(vals[j] - m) : 0.f;
        vals[j] = e;
        s += e;
    }
    #pragma unroll
    for (int o = 16; o > 0; o >>= 1) s += __shfl_xor_sync(0xffffffffu, s, o);
    float inv = 1.f / s;

    size_t base = (size_t)row * SEQ;
    #pragma unroll
    for (int j = 0; j < 16; j++) {
        int c = lane + 32 * j;
        __nv_bfloat16 hh, ll;
        split_bf16(vals[j] * inv, hh, ll);
        Ph[base + c] = hh;
        Pl[base + c] = ll;
    }
}

// ---------------- swiglu ----------------
__global__ void swiglu_kernel(float* __restrict__ G, const float* __restrict__ U,
                              __nv_bfloat16* __restrict__ Gh, __nv_bfloat16* __restrict__ Gl)
{
    size_t i = (size_t)blockIdx.x * blockDim.x + threadIdx.x;
    if (i >= (size_t)MTOK * FFDIM) return;
    float g = G[i];
    float sig = 1.f / (1.f + expf(-g));
    float v = g * sig * U[i];
    G[i] = v;
    __nv_bfloat16 hh, ll;
    split_bf16(v, hh, ll);
    Gh[i] = hh; Gl[i] = ll;
}

// ---------------- reps extraction + L2 normalize ----------------
__global__ void reps_kernel(const float* __restrict__ X, const int* __restrict__ mT,
                            const int* __restrict__ mM, float* __restrict__ R_)
{
    __shared__ int ired[256];
    __shared__ float fred[256];
    __shared__ int sidx;
    int bb = blockIdx.x;
    const int* mask = (bb < 4) ? mT : mM;
    int b = bb & 3;
    int t = threadIdx.x;
    int s = 0;
    for (int j = t; j < SEQ; j += 256) s += mask[b * SEQ + j];
    ired[t] = s; __syncthreads();
    for (int o = 128; o > 0; o >>= 1) {
        if (t < o) ired[t] += ired[t + o];
        __syncthreads();
    }
    if (t == 0) {
        int last = mask[0 * SEQ + 511] + mask[1 * SEQ + 511] +
                   mask[2 * SEQ + 511] + mask[3 * SEQ + 511];
        sidx = (last == BATCH) ? (SEQ - 1) : (ired[0] - 1);
    }
    __syncthreads();
    const float* row = X + (size_t)(bb * SEQ + sidx) * DMODEL;
    float ss = 0.f;
    for (int j = t; j < DMODEL; j += 256) { float v = row[j]; ss += v * v; }
    fred[t] = ss; __syncthreads();
    for (int o = 128; o > 0; o >>= 1) {
        if (t < o) fred[t] += fred[t + o];
        __syncthreads();
    }
    float inv = 1.f / sqrtf(fred[0]);
    for (int j = t; j < DMODEL; j += 256) R_[bb * DMODEL + j] = row[j] * inv;
}

// ---------------- contrastive loss ----------------
__global__ void loss_kernel(const float* __restrict__ R_, float* __restrict__ out)
{
    __shared__ float sims[16];
    int tid = threadIdx.x;
    int warp = tid >> 5, lane = tid & 31;
    for (int p = warp; p < 16; p += 8) {
        int i = p >> 2, j = p & 3;
        const float* a = R_ + i * DMODEL;
        const float* bR = R_ + (4 + j) * DMODEL;
        float d = 0.f;
        for (int k2 = lane; k2 < DMODEL; k2 += 32) d += a[k2] * bR[k2];
        #pragma unroll
        for (int o = 16; o > 0; o >>= 1) d += __shfl_xor_sync(0xffffffff, d, o);
        if (lane == 0) sims[p] = d * 20.f;
    }
    __syncthreads();
    if (tid == 0) {
        float loss = 0.f;
        for (int i = 0; i < 4; i++) {
            float m = -1e30f;
            for (int j = 0; j < 4; j++) m = fmaxf(m, sims[i * 4 + j]);
            float sum = 0.f;
            for (int j = 0; j < 4; j++) sum += expf(sims[i * 4 + j] - m);
            loss += (logf(sum) + m) - sims[i * 4 + i];
        }
        out[0] = loss * 0.25f;
    }
}

// ---------------- host driver ----------------
static void* symaddr_raw(const void* sym)
{
    void* p = nullptr;
    cudaGetSymbolAddress(&p, sym);
    return p;
}

extern "C" void kernel_launch(void* const* d_in, const int* in_sizes, int n_in,
                              void* d_out, int out_size)
{
    const int*   idT = (const int*)d_in[0];
    const int*   mT  = (const int*)d_in[1];
    const int*   idM = (const int*)d_in[2];
    const int*   mM  = (const int*)d_in[3];
    const float* emb = (const float*)d_in[4];
    const float* ln1 = (const float*)d_in[5];
    const float* ln2 = (const float*)d_in[6];
    const float* lnf = (const float*)d_in[7];
    const float* Wq = (const float*)d_in[8],  *Aq = (const float*)d_in[9],  *Bq = (const float*)d_in[10];
    const float* Wk = (const float*)d_in[11], *Ak = (const float*)d_in[12], *Bk = (const float*)d_in[13];
    const float* Wv = (const float*)d_in[14], *Av = (const float*)d_in[15], *Bv = (const float*)d_in[16];
    const float* Wo = (const float*)d_in[17], *Ao = (const float*)d_in[18], *Bo = (const float*)d_in[19];
    const float* Wg = (const float*)d_in[20], *Ag = (const float*)d_in[21], *Bg = (const float*)d_in[22];
    const float* Wu = (const float*)d_in[23], *Au = (const float*)d_in[24], *Bu = (const float*)d_in[25];
    const float* Wd = (const float*)d_in[26], *Ad = (const float*)d_in[27], *Bd = (const float*)d_in[28];

    float* h  = (float*)symaddr_raw(g_h);
    float* x  = (float*)symaddr_raw(g_x);
    float* v  = (float*)symaddr_raw(g_v);
    float* o  = (float*)symaddr_raw(g_o);
    float* sc = (float*)symaddr_raw(g_sc);
    float* gg = (float*)symaddr_raw(g_gate);
    float* uu = (float*)symaddr_raw(g_up);
    float* t0 = (float*)symaddr_raw(g_t);
    float* rp = (float*)symaddr_raw(g_reps);
    __nv_bfloat16* ah  = (__nv_bfloat16*)symaddr_raw(g_ah);
    __nv_bfloat16* al  = (__nv_bfloat16*)symaddr_raw(g_al);
    __nv_bfloat16* wh  = (__nv_bfloat16*)symaddr_raw(g_wh);
    __nv_bfloat16* wl  = (__nv_bfloat16*)symaddr_raw(g_wl);
    __nv_bfloat16* qh  = (__nv_bfloat16*)symaddr_raw(g_qh);
    __nv_bfloat16* ql  = (__nv_bfloat16*)symaddr_raw(g_ql);
    __nv_bfloat16* kh  = (__nv_bfloat16*)symaddr_raw(g_kh);
    __nv_bfloat16* kl  = (__nv_bfloat16*)symaddr_raw(g_kl);
    __nv_bfloat16* ph  = (__nv_bfloat16*)symaddr_raw(g_ph);
    __nv_bfloat16* pl  = (__nv_bfloat16*)symaddr_raw(g_pl);
    __nv_bfloat16* vth = (__nv_bfloat16*)symaddr_raw(g_vth);
    __nv_bfloat16* vtl = (__nv_bfloat16*)symaddr_raw(g_vtl);

    cudaFuncSetAttribute(gemm_tc,    cudaFuncAttributeMaxDynamicSharedMemorySize, GSMEM);
    cudaFuncSetAttribute(scores_mma, cudaFuncAttributeMaxDynamicSharedMemorySize, SCSM);
    cudaFuncSetAttribute(attnv_mma,  cudaFuncAttributeMaxDynamicSharedMemorySize, AVSM);

    const size_t DD = (size_t)DMODEL * DMODEL;
    const size_t DF = (size_t)DMODEL * FFDIM;
    const size_t LSTR = 4 * DD + 3 * DF;
    const dim3 tB(32, 8);
    const dim3 gD1(DMODEL / 128, MTOK / 128, 1);
    const dim3 gD3(DMODEL / 128, MTOK / 128, 3);
    const dim3 gF2(FFDIM / 128, MTOK / 128, 2);

    // ---- all weight transposes in 3 batched launches ----
    transpose_splitz<<<dim3(DMODEL / 32, DMODEL / 32, LAYERS * 4), tB>>>(
        Wq, Wk, Wv, Wo, 4, DD, wh, wl, 0, DD, LSTR, DMODEL, DMODEL);
    transpose_splitz<<<dim3(FFDIM / 32, DMODEL / 32, LAYERS * 2), tB>>>(
        Wg, Wu, nullptr, nullptr, 2, DF, wh, wl, 4 * DD, DF, LSTR, DMODEL, FFDIM);
    transpose_splitz<<<dim3(DMODEL / 32, FFDIM / 32, LAYERS), tB>>>(
        Wd, nullptr, nullptr, nullptr, 1, DF, wh, wl, 4 * DD + 2 * DF, 0, LSTR, FFDIM, DMODEL);

    embed_rms<<<MTOK, 256>>>(idT, idM, emb, ln1, h, x, ah, al);

    for (int l = 0; l < LAYERS; l++) {
        size_t off = (size_t)l * LSTR;
        const __nv_bfloat16 *Wl_h = wh + off, *Wl_l = wl + off;
        const float* Bq_l = Bq + (size_t)l * RLORA * DMODEL;
        const float* Bk_l = Bk + (size_t)l * RLORA * DMODEL;
        const float* Bv_l = Bv + (size_t)l * RLORA * DMODEL;
        const float* Bo_l = Bo + (size_t)l * RLORA * DMODEL;
        const float* Bg_l = Bg + (size_t)l * RLORA * FFDIM;
        const float* Bu_l = Bu + (size_t)l * RLORA * FFDIM;
        const float* Bd_l = Bd + (size_t)l * RLORA * DMODEL;

        if (l > 0)
            rmsnorm_kernel<<<MTOK, 256>>>(h, ln1 + l * DMODEL, x, ah, al);

        lora_fast<3><<<MTOK / 8, 256>>>(x, DMODEL, Aq + (size_t)l * DMODEL * RLORA,
                                        Ak + (size_t)l * DMODEL * RLORA,
                                        Av + (size_t)l * DMODEL * RLORA,
                                        t0, t0 + MTOK * RLORA, t0 + 2 * MTOK * RLORA);
        // qkv with fused RoPE (z=0,1 write qh/ql/kh/kl; z=2 writes fp32 v)
        gemm_tc<<<gD3, 256, GSMEM>>>(ah, al, Wl_h, Wl_l, DD, nullptr, nullptr, v,
                                     MTOK, DMODEL, DMODEL, t0, Bq_l, Bk_l, Bv_l, 3,
                                     qh, ql, kh, kl);

        vsplit_t<<<dim3(MTOK / 32, DMODEL / 32), tB>>>(v, vth, vtl);

        scores_mma<<<dim3(4, 4, BB * NHEAD), 256, SCSM>>>(qh, ql, kh, kl, mT, mM, sc);
        softmax_kernel<<<BB * NHEAD * SEQ / 8, 256>>>(sc, ph, pl);
        attnv_mma<<<dim3(1, 4, BB * NHEAD), 256, AVSM>>>(ph, pl, vth, vtl, o, ah, al);

        lora_fast<1><<<MTOK / 8, 256>>>(o, DMODEL, Ao + (size_t)l * DMODEL * RLORA,
                                        nullptr, nullptr, t0, nullptr, nullptr);
        gemm_tc<<<gD1, 256, GSMEM>>>(ah, al, Wl_h + 3 * DD, Wl_l + 3 * DD, 0, h, nullptr, nullptr,
                                     MTOK, DMODEL, DMODEL, t0, Bo_l, nullptr, nullptr, 1,
                                     nullptr, nullptr, nullptr, nullptr);

        rmsnorm_kernel<<<MTOK, 256>>>(h, ln2 + l * DMODEL, x, ah, al);
        lora_fast<2><<<MTOK / 8, 256>>>(x, DMODEL, Ag + (size_t)l * DMODEL * RLORA,
                                        Au + (size_t)l * DMODEL * RLORA, nullptr,
                                        t0, t0 + MTOK * RLORA, nullptr);
        gemm_tc<<<gF2, 256, GSMEM>>>(ah, al, Wl_h + 4 * DD, Wl_l + 4 * DD, DF, gg, uu, nullptr,
                                     MTOK, FFDIM, DMODEL, t0, Bg_l, Bu_l, nullptr, 0,
                                     nullptr, nullptr, nullptr, nullptr);

        swiglu_kernel<<<(int)(((size_t)MTOK * FFDIM + 255) / 256), 256>>>(gg, uu, ah, al);

        lora_fast<1><<<MTOK / 8, 256>>>(gg, FFDIM, Ad + (size_t)l * FFDIM * RLORA,
                                        nullptr, nullptr, t0, nullptr, nullptr);
        gemm_tc<<<gD1, 256, GSMEM>>>(ah, al, Wl_h + 4 * DD + 2 * DF, Wl_l + 4 * DD + 2 * DF, 0,
                                     h, nullptr, nullptr,
                                     MTOK, DMODEL, FFDIM, t0, Bd_l, nullptr, nullptr, 1,
                                     nullptr, nullptr, nullptr, nullptr);
    }

    rmsnorm_kernel<<<MTOK, 256>>>(h, lnf, x, ah, al);
    reps_kernel<<<BB, 256>>>(x, mT, mM, rp);
    loss_kernel<<<1, 256>>>(rp, (float*)d_out);
}